// round 10
// baseline (speedup 1.0000x reference)
#include <cuda_runtime.h>
#include <cuda_bf16.h>
#include <cstdint>
#include <math.h>

#define N_TOK 2048
#define DM 256
#define PWY 4096
#define KSEL 4
#define NE 16
#define HMAX 1280
#define NPAIR (N_TOK*KSEL)

typedef unsigned long long u64;
typedef unsigned int uint32;
typedef __nv_bfloat16 bf16;
typedef __nv_bfloat162 bf162;

#define MMA_BF16(d, a0,a1,a2,a3, b0,b1) \
  asm volatile("mma.sync.aligned.m16n8k16.row.col.f32.bf16.bf16.f32 " \
    "{%0,%1,%2,%3}, {%4,%5,%6,%7}, {%8,%9}, {%0,%1,%2,%3};" \
    : "+f"(d[0]),"+f"(d[1]),"+f"(d[2]),"+f"(d[3]) \
    : "r"(a0),"r"(a1),"r"(a2),"r"(a3),"r"(b0),"r"(b1))

#define CP16(dst, src) \
  asm volatile("cp.async.ca.shared.global [%0], [%1], 16;" :: "r"(dst), "l"(src))
#define CP16_Z(dst, src) \
  asm volatile("cp.async.ca.shared.global [%0], [%1], 16, 0;" :: "r"(dst), "l"(src))
#define CP_COMMIT() asm volatile("cp.async.commit_group;" ::: "memory")
#define CP_WAIT1()  asm volatile("cp.async.wait_group 1;" ::: "memory")
#define CP_WAIT0()  asm volatile("cp.async.wait_group 0;" ::: "memory")

__device__ __forceinline__ uint32 smem_u32(const void* p){
    uint32 a;
    asm("{ .reg .u64 t; cvta.to.shared.u64 t, %1; cvt.u32.u64 %0, t; }" : "=r"(a) : "l"(p));
    return a;
}

// ---------------- device scratch (static, no allocation) ----------------
__device__ float g_scores[N_TOK*PWY];
__device__ float g_freq[PWY];
__device__ int   g_topidx[NPAIR];
__device__ float g_topval[NPAIR];
__device__ int   g_cnt[3*NE];
__device__ int   g_list[3*NE*NPAIR];
__device__ float g_pre0[NPAIR*DM];
__device__ float g_post0[NPAIR*DM];
// split bf16 activations
__device__ bf16 g_xh[N_TOK*DM],    g_xl[N_TOK*DM];
__device__ bf16 g_h1h[N_TOK*256],  g_h1l[N_TOK*256];
__device__ bf16 g_h2h[N_TOK*128],  g_h2l[N_TOK*128];
__device__ bf16 g_xpreh[NPAIR*DM], g_xprel[NPAIR*DM];
__device__ bf16 g_xmidh[(size_t)NPAIR*HMAX], g_xmidl[(size_t)NPAIR*HMAX];
__device__ bf16 g_xmlph[NPAIR*DM], g_xmlpl[NPAIR*DM];
// split bf16 transposed weights: WT[n][k]
__device__ bf16 g_rw1h[256*256],  g_rw1l[256*256];
__device__ bf16 g_rw2h[128*256],  g_rw2l[128*256];
__device__ bf16 g_rw3h[PWY*128],  g_rw3l[PWY*128];
__device__ bf16 g_pwh[NE*DM*DM],  g_pwl[NE*DM*DM];
__device__ bf16 g_m1h[NE*HMAX*DM], g_m1l[NE*HMAX*DM];
__device__ bf16 g_m2h[NE*DM*HMAX], g_m2l[NE*DM*HMAX];
__device__ bf16 g_qwh[NE*DM*DM],  g_qwl[NE*DM*DM];

__device__ __forceinline__ float geluf(float v){
    return 0.5f*v*(1.0f+erff(v*0.70710678118654752f));
}

// ---------------- weight convert + transpose ----------------
__global__ __launch_bounds__(256) void convt(
    const float* __restrict__ W, bf16* __restrict__ Th,
    bf16* __restrict__ Tl, int R, int C,
    long long wstride, long long tstride)
{
    int e = blockIdx.z;
    __shared__ float tile[32][33];
    int c0 = blockIdx.x*32, r0 = blockIdx.y*32;
    const float* Win = W + (size_t)e*wstride;
    int tx = threadIdx.x & 31, ty = threadIdx.x >> 5;
    for (int i=0;i<32;i+=8)
        tile[ty+i][tx] = Win[(size_t)(r0+ty+i)*C + c0+tx];
    __syncthreads();
    bf16* oh = Th + (size_t)e*tstride;
    bf16* ol = Tl + (size_t)e*tstride;
    for (int i=0;i<32;i+=8){
        float v = tile[tx][ty+i];
        bf16 h = __float2bfloat16(v);
        oh[(size_t)(c0+ty+i)*R + r0+tx] = h;
        ol[(size_t)(c0+ty+i)*R + r0+tx] = __float2bfloat16(v - __bfloat162float(h));
    }
}

// ---------------- split x ----------------
__global__ __launch_bounds__(256) void split_x(const float* __restrict__ x)
{
    int idx = (blockIdx.x*256 + threadIdx.x)*8;
    float4 v0 = *(const float4*)&x[idx];
    float4 v1 = *(const float4*)&x[idx+4];
    float v[8] = {v0.x,v0.y,v0.z,v0.w,v1.x,v1.y,v1.z,v1.w};
    bf162* dh = (bf162*)&g_xh[idx];
    bf162* dl = (bf162*)&g_xl[idx];
#pragma unroll
    for (int j=0;j<4;j++){
        bf16 h0 = __float2bfloat16(v[2*j]);
        bf16 h1 = __float2bfloat16(v[2*j+1]);
        bf16 l0 = __float2bfloat16(v[2*j]   - __bfloat162float(h0));
        bf16 l1 = __float2bfloat16(v[2*j+1] - __bfloat162float(h1));
        dh[j] = __halves2bfloat162(h0,h1);
        dl[j] = __halves2bfloat162(l0,l1);
    }
}

// ---------------- split-bf16 mma.sync GEMM: 128x128 tile, 4 warps, cp.async 2-buffer --------
// dyn smem element layout (bf16): [AH | AL | BH | BL], each [2][128][40]
#define SEG 10240            // elems per array (2*128*40)
#define AHo 0
#define ALo SEG
#define BHo (2*SEG)
#define BLo (3*SEG)
#define SMEM_GEMM_BYTES (4*SEG*2)

__global__ __launch_bounds__(128,2) void gemm_bf16(
    const bf16* __restrict__ Ahg, const bf16* __restrict__ Alg, int lda,
    const bf16* __restrict__ Wth, const bf16* __restrict__ Wtl,
    int Kw, long long wse,
    const float* __restrict__ bias, int bse,
    float* __restrict__ Cf, bf16* __restrict__ Chp, bf16* __restrict__ Clp,
    int ldc, int Kfix, int kvar, int nvar, int act, int listoff, int ashift, int osplit)
{
    extern __shared__ bf16 S[];
    int e = blockIdx.z;
    int hid = DM*(2 + (e>>2));
    int K = kvar ? hid : Kfix;
    int n0 = blockIdx.x*128;
    if (nvar && n0 >= hid) return;
    int m0 = blockIdx.y*128;
    const int* list = 0; int cnt = 0;
    if (listoff >= 0){
        cnt = g_cnt[listoff+e];
        if (m0 >= cnt) return;
        list = g_list + (size_t)(listoff+e)*NPAIR;
    }
    __shared__ int pairs[128];
    int tid = threadIdx.x;
    pairs[tid] = (listoff>=0) ? ((m0+tid < cnt) ? list[m0+tid] : -1) : (m0+tid);
    __syncthreads();

    int prA = pairs[tid];
    const bf16* Ahp = (prA>=0) ? (Ahg + (size_t)(prA>>ashift)*lda) : Ahg;
    const bf16* Alp = (prA>=0) ? (Alg + (size_t)(prA>>ashift)*lda) : Alg;
    bool avalid = (prA>=0);
    const bf16* Bhp = Wth + (size_t)e*wse + (size_t)(n0+tid)*Kw;
    const bf16* Blp = Wtl + (size_t)e*wse + (size_t)(n0+tid)*Kw;

    // per-thread smem dst base addresses (row = tid, 40-elem pad)
    uint32 dAh = smem_u32(&S[AHo + tid*40]);
    uint32 dAl = smem_u32(&S[ALo + tid*40]);
    uint32 dBh = smem_u32(&S[BHo + tid*40]);
    uint32 dBl = smem_u32(&S[BLo + tid*40]);
    const uint32 bufB = 128*40*2;  // byte offset between buffers

    auto issue = [&](int c){
        uint32 bo = (c&1) ? bufB : 0;
#pragma unroll
        for (int j=0;j<4;j++){
            if (avalid){
                CP16(dAh + bo + j*16, Ahp + c*32 + j*8);
                CP16(dAl + bo + j*16, Alp + c*32 + j*8);
            } else {
                CP16_Z(dAh + bo + j*16, Ahp);
                CP16_Z(dAl + bo + j*16, Alp);
            }
            CP16(dBh + bo + j*16, Bhp + c*32 + j*8);
            CP16(dBl + bo + j*16, Blp + c*32 + j*8);
        }
    };

    int lane = tid & 31, wid = tid >> 5;
    int wm = wid >> 1, wn = wid & 1;
    int qr = lane >> 2, qc = lane & 3;

    float acc[4][8][4];
#pragma unroll
    for (int i=0;i<4;i++)
#pragma unroll
    for (int j=0;j<8;j++)
#pragma unroll
    for (int q=0;q<4;q++) acc[i][j][q]=0.f;

    int nchunks = K/32;
    issue(0); CP_COMMIT();
    for (int c=0;c<nchunks;c++){
        if (c+1 < nchunks){ issue(c+1); CP_COMMIT(); CP_WAIT1(); }
        else { CP_WAIT0(); }
        __syncthreads();
        int bo = (c&1) ? 128*40 : 0;   // element offset of buffer
#pragma unroll
        for (int k16=0;k16<32;k16+=16){
            uint32 bh[8][2], bl[8][2];
#pragma unroll
            for (int nf=0;nf<8;nf++){
                int n = wn*64 + nf*8 + qr;
                int bb = BHo + (bo + n*40) + k16 + qc*2;
                int lb = BLo + (bo + n*40) + k16 + qc*2;
                bh[nf][0] = *(const uint32*)&S[bb];
                bh[nf][1] = *(const uint32*)&S[bb+8];
                bl[nf][0] = *(const uint32*)&S[lb];
                bl[nf][1] = *(const uint32*)&S[lb+8];
            }
#pragma unroll
            for (int mf=0;mf<4;mf++){
                int m = wm*64 + mf*16 + qr;
                int ab = AHo + (bo + m*40) + k16 + qc*2;
                int lb = ALo + (bo + m*40) + k16 + qc*2;
                uint32 ah0 = *(const uint32*)&S[ab];
                uint32 ah1 = *(const uint32*)&S[ab+320];
                uint32 ah2 = *(const uint32*)&S[ab+8];
                uint32 ah3 = *(const uint32*)&S[ab+328];
                uint32 al0 = *(const uint32*)&S[lb];
                uint32 al1 = *(const uint32*)&S[lb+320];
                uint32 al2 = *(const uint32*)&S[lb+8];
                uint32 al3 = *(const uint32*)&S[lb+328];
#pragma unroll
                for (int nf=0;nf<8;nf++){
                    MMA_BF16(acc[mf][nf], ah0,ah1,ah2,ah3, bh[nf][0],bh[nf][1]);
                    MMA_BF16(acc[mf][nf], ah0,ah1,ah2,ah3, bl[nf][0],bl[nf][1]);
                    MMA_BF16(acc[mf][nf], al0,al1,al2,al3, bh[nf][0],bh[nf][1]);
                }
            }
        }
        __syncthreads();
    }

    bool relu_e = (act==3) && (e&1);
#pragma unroll
    for (int mf=0;mf<4;mf++){
        int r0 = wm*64 + mf*16 + qr;
        int r1 = r0 + 8;
        int pr0 = pairs[r0], pr1 = pairs[r1];
#pragma unroll
        for (int nf=0;nf<8;nf++){
            int n = n0 + wn*64 + nf*8 + qc*2;
            float b0 = bias[(size_t)e*bse + n];
            float b1 = bias[(size_t)e*bse + n + 1];
            float v00 = acc[mf][nf][0] + b0, v01 = acc[mf][nf][1] + b1;
            float v10 = acc[mf][nf][2] + b0, v11 = acc[mf][nf][3] + b1;
            if (act==1){
                v00=geluf(v00); v01=geluf(v01); v10=geluf(v10); v11=geluf(v11);
            } else if (act==3){
                if (relu_e){
                    v00=fmaxf(v00,0.f); v01=fmaxf(v01,0.f);
                    v10=fmaxf(v10,0.f); v11=fmaxf(v11,0.f);
                } else {
                    v00=geluf(v00); v01=geluf(v01);
                    v10=geluf(v10); v11=geluf(v11);
                }
            }
            if (osplit){
                if (pr0>=0){
                    bf16 h0=__float2bfloat16(v00), h1=__float2bfloat16(v01);
                    bf16 l0=__float2bfloat16(v00-__bfloat162float(h0));
                    bf16 l1=__float2bfloat16(v01-__bfloat162float(h1));
                    *(bf162*)&Chp[(size_t)pr0*ldc + n] = __halves2bfloat162(h0,h1);
                    *(bf162*)&Clp[(size_t)pr0*ldc + n] = __halves2bfloat162(l0,l1);
                }
                if (pr1>=0){
                    bf16 h0=__float2bfloat16(v10), h1=__float2bfloat16(v11);
                    bf16 l0=__float2bfloat16(v10-__bfloat162float(h0));
                    bf16 l1=__float2bfloat16(v11-__bfloat162float(h1));
                    *(bf162*)&Chp[(size_t)pr1*ldc + n] = __halves2bfloat162(h0,h1);
                    *(bf162*)&Clp[(size_t)pr1*ldc + n] = __halves2bfloat162(l0,l1);
                }
            } else {
                if (pr0>=0) *(float2*)&Cf[(size_t)pr0*ldc + n] = make_float2(v00,v01);
                if (pr1>=0) *(float2*)&Cf[(size_t)pr1*ldc + n] = make_float2(v10,v11);
            }
        }
    }
}

// ---------------- pre epilogue: LN + act, writes split bf16 ----------------
__global__ __launch_bounds__(256) void epil_pre(
    const float* __restrict__ pg, const float* __restrict__ pbb)
{
    int i = blockIdx.x*8 + (threadIdx.x>>5);
    int lane = threadIdx.x & 31;
    int e = g_topidx[i] >> 8;
    const float* row = g_pre0 + (size_t)i*DM;
    float y[8];
    float4 v0 = *(const float4*)&row[lane*8];
    float4 v1 = *(const float4*)&row[lane*8+4];
    y[0]=v0.x;y[1]=v0.y;y[2]=v0.z;y[3]=v0.w;y[4]=v1.x;y[5]=v1.y;y[6]=v1.z;y[7]=v1.w;
    float s = y[0]+y[1]+y[2]+y[3]+y[4]+y[5]+y[6]+y[7];
#pragma unroll
    for (int m=16;m>0;m>>=1) s += __shfl_xor_sync(0xffffffffu, s, m, 32);
    float mu = s * (1.0f/DM);
    float ss = 0.f;
#pragma unroll
    for (int j=0;j<8;j++){ float d=y[j]-mu; ss += d*d; }
#pragma unroll
    for (int m=16;m>0;m>>=1) ss += __shfl_xor_sync(0xffffffffu, ss, m, 32);
    float rstd = rsqrtf(ss*(1.0f/DM) + 1e-5f);
    int actm = e % 3;
    bf162* dh = (bf162*)&g_xpreh[(size_t)i*DM + lane*8];
    bf162* dl = (bf162*)&g_xprel[(size_t)i*DM + lane*8];
#pragma unroll
    for (int j=0;j<4;j++){
        float o[2];
#pragma unroll
        for (int q=0;q<2;q++){
            int c = lane*8 + 2*j + q;
            float v = (y[2*j+q]-mu)*rstd*pg[e*DM+c] + pbb[e*DM+c];
            o[q] = (actm==0) ? geluf(v) : (actm==1) ? fmaxf(v,0.f) : tanhf(v);
        }
        bf16 h0=__float2bfloat16(o[0]), h1=__float2bfloat16(o[1]);
        bf16 l0=__float2bfloat16(o[0]-__bfloat162float(h0));
        bf16 l1=__float2bfloat16(o[1]-__bfloat162float(h1));
        dh[j] = __halves2bfloat162(h0,h1);
        dl[j] = __halves2bfloat162(l0,l1);
    }
}

// ---------------- post epilogue: optional LN + weighted scatter ----------------
__global__ __launch_bounds__(256) void epil_post(
    const float* __restrict__ qg, const float* __restrict__ qbb,
    float* __restrict__ out_y)
{
    int i = blockIdx.x*8 + (threadIdx.x>>5);
    int lane = threadIdx.x & 31;
    int e = g_topidx[i] & 15;
    const float* row = g_post0 + (size_t)i*DM;
    float y[8];
    float4 v0 = *(const float4*)&row[lane*8];
    float4 v1 = *(const float4*)&row[lane*8+4];
    y[0]=v0.x;y[1]=v0.y;y[2]=v0.z;y[3]=v0.w;y[4]=v1.x;y[5]=v1.y;y[6]=v1.z;y[7]=v1.w;
    if ((e & 1) == 0){
        float s = y[0]+y[1]+y[2]+y[3]+y[4]+y[5]+y[6]+y[7];
#pragma unroll
        for (int m=16;m>0;m>>=1) s += __shfl_xor_sync(0xffffffffu, s, m, 32);
        float mu = s * (1.0f/DM);
        float ss = 0.f;
#pragma unroll
        for (int j=0;j<8;j++){ float d=y[j]-mu; ss += d*d; }
#pragma unroll
        for (int m=16;m>0;m>>=1) ss += __shfl_xor_sync(0xffffffffu, ss, m, 32);
        float rstd = rsqrtf(ss*(1.0f/DM) + 1e-5f);
#pragma unroll
        for (int j=0;j<8;j++){
            int c = lane*8 + j;
            y[j] = (y[j]-mu)*rstd*qg[e*DM+c] + qbb[e*DM+c];
        }
    }
    float w = g_topval[i];
    int tok = i >> 2;
#pragma unroll
    for (int j=0;j<8;j++)
        atomicAdd(&out_y[(size_t)tok*DM + lane*8 + j], y[j]*w);
}

// ---------------- softmax + topk (validated) ----------------
__global__ __launch_bounds__(256) void softmax_topk(
    const float* __restrict__ temp, float* __restrict__ pwout)
{
    __shared__ float s[PWY];
    __shared__ float rv[256*4];
    __shared__ int   ri[256*4];
    __shared__ float red1[256];
    __shared__ float red2[256];
    __shared__ float pv[KSEL];
    int n = blockIdx.x, tid = threadIdx.x;
    float* srow = g_scores + (size_t)n*PWY;
    for (int i=0;i<4;i++){
        int idx = i*1024 + tid*4;
        *(float4*)&s[idx] = *(const float4*)&srow[idx];
    }
    __syncthreads();
    float invt = 1.0f/temp[0];

    float tv[4] = {-INFINITY,-INFINITY,-INFINITY,-INFINITY};
    int tix[4] = {PWY,PWY,PWY,PWY};
    float lm = -INFINITY;
#pragma unroll
    for (int i=0;i<16;i++){
        int j = tid + i*256;
        float v = s[j];
        lm = fmaxf(lm, v);
        if (v > tv[3] || (v == tv[3] && j < tix[3])){
            tv[3]=v; tix[3]=j;
#pragma unroll
            for (int q=3;q>0;q--){
                if (tv[q] > tv[q-1] || (tv[q]==tv[q-1] && tix[q] < tix[q-1])){
                    float tmv=tv[q]; tv[q]=tv[q-1]; tv[q-1]=tmv;
                    int tmi=tix[q]; tix[q]=tix[q-1]; tix[q-1]=tmi;
                }
            }
        }
    }
    red1[tid]=lm; __syncthreads();
    for (int off=128;off>0;off>>=1){ if(tid<off) red1[tid]=fmaxf(red1[tid],red1[tid+off]); __syncthreads(); }
    float m0 = red1[0]; __syncthreads();

    float f[16]; float ls0=0.f, lst=0.f;
#pragma unroll
    for (int i=0;i<16;i++){
        int j = tid + i*256;
        float d = s[j]-m0;
        float e0 = __expf(d);
        f[i]=e0; ls0+=e0;
        lst += __expf(d*invt);
    }
    red1[tid]=ls0; red2[tid]=lst; __syncthreads();
    for (int off=128;off>0;off>>=1){
        if(tid<off){ red1[tid]+=red1[tid+off]; red2[tid]+=red2[tid+off]; }
        __syncthreads();
    }
    float inv0 = 1.0f/red1[0];
    float invsumt = 1.0f/red2[0];
    __syncthreads();

#pragma unroll
    for (int i=0;i<16;i++) srow[tid + i*256] = f[i]*inv0;

#pragma unroll
    for (int q=0;q<4;q++){ rv[tid*4+q]=tv[q]; ri[tid*4+q]=tix[q]; }
    __syncthreads();
    for (int off=128;off>0;off>>=1){
        if (tid < off){
            float a0[4], b0[4]; int ai[4], bi[4];
#pragma unroll
            for (int q=0;q<4;q++){
                a0[q]=rv[tid*4+q]; ai[q]=ri[tid*4+q];
                b0[q]=rv[(tid+off)*4+q]; bi[q]=ri[(tid+off)*4+q];
            }
            int ia=0, ib=0;
            float ov[4]; int oi[4];
#pragma unroll
            for (int q=0;q<4;q++){
                bool ta = (a0[ia] > b0[ib]) || (a0[ia]==b0[ib] && ai[ia] < bi[ib]);
                if (ta){ ov[q]=a0[ia]; oi[q]=ai[ia]; ia++; }
                else   { ov[q]=b0[ib]; oi[q]=bi[ib]; ib++; }
            }
#pragma unroll
            for (int q=0;q<4;q++){ rv[tid*4+q]=ov[q]; ri[tid*4+q]=oi[q]; }
        }
        __syncthreads();
    }

    if (tid < KSEL){
        int se = ri[tid];
        float p = __expf((s[se]-m0)*invt)*invsumt;
        pv[tid]=p;
        g_topidx[n*KSEL+tid]=se;
        g_topval[n*KSEL+tid]=p;
    }
    __syncthreads();
    float invps = 1.0f/(pv[0]+pv[1]+pv[2]+pv[3] + 1e-8f);
    int s0=ri[0], s1=ri[1], s2=ri[2], s3=ri[3];
    float w0=pv[0]*invps, w1=pv[1]*invps, w2=pv[2]*invps, w3=pv[3]*invps;
    float* prow = pwout + (size_t)n*PWY;
    for (int i=0;i<16;i++){
        int j = tid + i*256;
        float v = 0.f;
        if (j==s0) v=w0; else if (j==s1) v=w1; else if (j==s2) v=w2; else if (j==s3) v=w3;
        prow[j]=v;
    }
}

// ---------------- freq + loss + lists ----------------
__global__ __launch_bounds__(256) void freq_partial()
{
    int p = blockIdx.x*256 + threadIdx.x;
    int nbeg = blockIdx.y*256;
    float acc = 0.f;
    for (int n=nbeg; n<nbeg+256; n++)
        acc += g_scores[(size_t)n*PWY + p];
    atomicAdd(&g_freq[p], acc);
}

__global__ __launch_bounds__(256) void glbl_loss_kernel(float* __restrict__ out)
{
    __shared__ float red[256];
    int tid = threadIdx.x;
    const float invN = 1.0f/(float)N_TOK;
    float lsum = 0.f;
    for (int i=0;i<PWY/256;i++) lsum += g_freq[tid+i*256]*invN;
    red[tid]=lsum; __syncthreads();
    for (int off=128;off>0;off>>=1){ if(tid<off) red[tid]+=red[tid+off]; __syncthreads(); }
    float mean = red[0]/(float)PWY; __syncthreads();
    float lss = 0.f;
    for (int i=0;i<PWY/256;i++){
        float d = g_freq[tid+i*256]*invN - mean;
        lss += d*d;
    }
    red[tid]=lss; __syncthreads();
    for (int off=128;off>0;off>>=1){ if(tid<off) red[tid]+=red[tid+off]; __syncthreads(); }
    if (tid==0) out[0] = (float)PWY * (red[0]/(float)(PWY-1));
}

__global__ __launch_bounds__(256) void build_lists()
{
    int i = blockIdx.x*256 + threadIdx.x;
    if (i >= NPAIR) return;
    int idx = g_topidx[i];
    int pe = idx >> 8, rem = idx & 255;
    int me = rem >> 4, qe = rem & 15;
    int pos;
    pos = atomicAdd(&g_cnt[pe], 1);         g_list[pe*NPAIR + pos] = i;
    pos = atomicAdd(&g_cnt[NE+me], 1);      g_list[(NE+me)*NPAIR + pos] = i;
    pos = atomicAdd(&g_cnt[2*NE+qe], 1);    g_list[(2*NE+qe)*NPAIR + pos] = i;
}

// ---------------- host launch ----------------
extern "C" void kernel_launch(void* const* d_in, const int* in_sizes, int n_in,
                              void* d_out, int out_size)
{
    const float* x   = (const float*)d_in[0];
    const float* rw1 = (const float*)d_in[1];
    const float* rb1 = (const float*)d_in[2];
    const float* rw2 = (const float*)d_in[3];
    const float* rb2 = (const float*)d_in[4];
    const float* rw3 = (const float*)d_in[5];
    const float* rb3 = (const float*)d_in[6];
    const float* temp= (const float*)d_in[7];
    const float* pw  = (const float*)d_in[8];
    const float* pb  = (const float*)d_in[9];
    const float* pg  = (const float*)d_in[10];
    const float* pbb = (const float*)d_in[11];
    const float* mw1 = (const float*)d_in[12];
    const float* mb1 = (const float*)d_in[13];
    const float* mw2 = (const float*)d_in[14];
    const float* mb2 = (const float*)d_in[15];
    const float* qw  = (const float*)d_in[16];
    const float* qb  = (const float*)d_in[17];
    const float* qg  = (const float*)d_in[18];
    const float* qbb = (const float*)d_in[19];

    float* out      = (float*)d_out;
    float* out_y    = out;
    float* out_loss = out + N_TOK*DM;
    float* out_pw   = out + N_TOK*DM + 1;

    void* p;
    cudaGetSymbolAddress(&p, g_scores); float* scores = (float*)p;
    cudaGetSymbolAddress(&p, g_freq);   float* freqp = (float*)p;
    cudaGetSymbolAddress(&p, g_cnt);    int*   cntp = (int*)p;
    cudaGetSymbolAddress(&p, g_pre0);   float* pre0 = (float*)p;
    cudaGetSymbolAddress(&p, g_post0);  float* post0 = (float*)p;
    cudaGetSymbolAddress(&p, g_xh);     bf16* xh = (bf16*)p;
    cudaGetSymbolAddress(&p, g_xl);     bf16* xl = (bf16*)p;
    cudaGetSymbolAddress(&p, g_h1h);    bf16* h1h = (bf16*)p;
    cudaGetSymbolAddress(&p, g_h1l);    bf16* h1l = (bf16*)p;
    cudaGetSymbolAddress(&p, g_h2h);    bf16* h2h = (bf16*)p;
    cudaGetSymbolAddress(&p, g_h2l);    bf16* h2l = (bf16*)p;
    cudaGetSymbolAddress(&p, g_xpreh);  bf16* xpreh = (bf16*)p;
    cudaGetSymbolAddress(&p, g_xprel);  bf16* xprel = (bf16*)p;
    cudaGetSymbolAddress(&p, g_xmidh);  bf16* xmidh = (bf16*)p;
    cudaGetSymbolAddress(&p, g_xmidl);  bf16* xmidl = (bf16*)p;
    cudaGetSymbolAddress(&p, g_xmlph);  bf16* xmlph = (bf16*)p;
    cudaGetSymbolAddress(&p, g_xmlpl);  bf16* xmlpl = (bf16*)p;
    cudaGetSymbolAddress(&p, g_rw1h);   bf16* rw1h = (bf16*)p;
    cudaGetSymbolAddress(&p, g_rw1l);   bf16* rw1l = (bf16*)p;
    cudaGetSymbolAddress(&p, g_rw2h);   bf16* rw2h = (bf16*)p;
    cudaGetSymbolAddress(&p, g_rw2l);   bf16* rw2l = (bf16*)p;
    cudaGetSymbolAddress(&p, g_rw3h);   bf16* rw3h = (bf16*)p;
    cudaGetSymbolAddress(&p, g_rw3l);   bf16* rw3l = (bf16*)p;
    cudaGetSymbolAddress(&p, g_pwh);    bf16* pwh = (bf16*)p;
    cudaGetSymbolAddress(&p, g_pwl);    bf16* pwl = (bf16*)p;
    cudaGetSymbolAddress(&p, g_m1h);    bf16* m1h = (bf16*)p;
    cudaGetSymbolAddress(&p, g_m1l);    bf16* m1l = (bf16*)p;
    cudaGetSymbolAddress(&p, g_m2h);    bf16* m2h = (bf16*)p;
    cudaGetSymbolAddress(&p, g_m2l);    bf16* m2l = (bf16*)p;
    cudaGetSymbolAddress(&p, g_qwh);    bf16* qwh = (bf16*)p;
    cudaGetSymbolAddress(&p, g_qwl);    bf16* qwl = (bf16*)p;

    cudaFuncSetAttribute(gemm_bf16, cudaFuncAttributeMaxDynamicSharedMemorySize, SMEM_GEMM_BYTES);

    cudaMemsetAsync(out_y, 0, (size_t)N_TOK*DM*sizeof(float), 0);
    cudaMemsetAsync(freqp, 0, PWY*sizeof(float), 0);
    cudaMemsetAsync(cntp,  0, 3*NE*sizeof(int), 0);

    // weight conversion + transpose (bf16 hi/lo)
    convt<<<dim3(256/32, 256/32, 1), 256>>>(rw1, rw1h, rw1l, 256, 256, 0LL, 0LL);
    convt<<<dim3(128/32, 256/32, 1), 256>>>(rw2, rw2h, rw2l, 256, 128, 0LL, 0LL);
    convt<<<dim3(PWY/32, 128/32, 1), 256>>>(rw3, rw3h, rw3l, 128, PWY, 0LL, 0LL);
    convt<<<dim3(DM/32, DM/32, NE), 256>>>(pw, pwh, pwl, DM, DM,
        (long long)DM*DM, (long long)DM*DM);
    convt<<<dim3(HMAX/32, DM/32, NE), 256>>>(mw1, m1h, m1l, DM, HMAX,
        (long long)DM*HMAX, (long long)HMAX*DM);
    convt<<<dim3(DM/32, HMAX/32, NE), 256>>>(mw2, m2h, m2l, HMAX, DM,
        (long long)HMAX*DM, (long long)DM*HMAX);
    convt<<<dim3(DM/32, DM/32, NE), 256>>>(qw, qwh, qwl, DM, DM,
        (long long)DM*DM, (long long)DM*DM);

    // split x once
    split_x<<<N_TOK*DM/(256*8), 256>>>(x);

    // router
    gemm_bf16<<<dim3(2, N_TOK/128, 1), 128, SMEM_GEMM_BYTES>>>(
        xh, xl, DM, rw1h, rw1l, 256, 0LL, rb1, 0,
        0, h1h, h1l, 256, 256, 0, 0, 1, -1, 0, 1);
    gemm_bf16<<<dim3(1, N_TOK/128, 1), 128, SMEM_GEMM_BYTES>>>(
        h1h, h1l, 256, rw2h, rw2l, 256, 0LL, rb2, 0,
        0, h2h, h2l, 128, 256, 0, 0, 1, -1, 0, 1);
    gemm_bf16<<<dim3(PWY/128, N_TOK/128, 1), 128, SMEM_GEMM_BYTES>>>(
        h2h, h2l, 128, rw3h, rw3l, 128, 0LL, rb3, 0,
        scores, 0, 0, PWY, 128, 0, 0, 0, -1, 0, 0);

    // softmax + topk + pathway weights + probs writeback
    softmax_topk<<<N_TOK, 256>>>(temp, out_pw);

    // GLBL loss
    freq_partial<<<dim3(PWY/256, N_TOK/256), 256>>>();
    glbl_loss_kernel<<<1, 256>>>(out_loss);

    // routing
    build_lists<<<NPAIR/256, 256>>>();

    // pre experts: gemm -> LN epilogue
    gemm_bf16<<<dim3(DM/128, NPAIR/128, NE), 128, SMEM_GEMM_BYTES>>>(
        xh, xl, DM, pwh, pwl, DM, (long long)DM*DM, pb, DM,
        pre0, 0, 0, DM, DM, 0, 0, 0, 0, 2, 0);
    epil_pre<<<NPAIR/8, 256>>>(pg, pbb);

    // mlp experts
    gemm_bf16<<<dim3(HMAX/128, NPAIR/128, NE), 128, SMEM_GEMM_BYTES>>>(
        xpreh, xprel, DM, m1h, m1l, DM, (long long)HMAX*DM, mb1, HMAX,
        0, xmidh, xmidl, HMAX, DM, 0, 1, 3, NE, 0, 1);
    gemm_bf16<<<dim3(DM/128, NPAIR/128, NE), 128, SMEM_GEMM_BYTES>>>(
        xmidh, xmidl, HMAX, m2h, m2l, HMAX, (long long)DM*HMAX, mb2, DM,
        0, xmlph, xmlpl, DM, 0, 1, 0, 0, NE, 0, 1);

    // post experts: gemm -> LN + scatter epilogue
    gemm_bf16<<<dim3(DM/128, NPAIR/128, NE), 128, SMEM_GEMM_BYTES>>>(
        xmlph, xmlpl, DM, qwh, qwl, DM, (long long)DM*DM, qb, DM,
        post0, 0, 0, DM, DM, 0, 0, 0, 2*NE, 0, 0);
    epil_post<<<NPAIR/8, 256>>>(qg, qbb, out_y);
}

// round 11
// speedup vs baseline: 1.3079x; 1.3079x over previous
#include <cuda_runtime.h>
#include <cuda_bf16.h>
#include <cstdint>
#include <math.h>

#define N_TOK 2048
#define DM 256
#define PWY 4096
#define KSEL 4
#define NE 16
#define HMAX 1280
#define NPAIR (N_TOK*KSEL)

typedef unsigned long long u64;
typedef unsigned int uint32;
typedef __nv_bfloat16 bf16;
typedef __nv_bfloat162 bf162;

#define MMA_BF16(d, a0,a1,a2,a3, b0,b1) \
  asm volatile("mma.sync.aligned.m16n8k16.row.col.f32.bf16.bf16.f32 " \
    "{%0,%1,%2,%3}, {%4,%5,%6,%7}, {%8,%9}, {%0,%1,%2,%3};" \
    : "+f"(d[0]),"+f"(d[1]),"+f"(d[2]),"+f"(d[3]) \
    : "r"(a0),"r"(a1),"r"(a2),"r"(a3),"r"(b0),"r"(b1))

#define LDSM_X4(r0,r1,r2,r3,addr) \
  asm volatile("ldmatrix.sync.aligned.m8n8.x4.shared.b16 {%0,%1,%2,%3}, [%4];" \
    : "=r"(r0),"=r"(r1),"=r"(r2),"=r"(r3) : "r"(addr))
#define LDSM_X2(r0,r1,addr) \
  asm volatile("ldmatrix.sync.aligned.m8n8.x2.shared.b16 {%0,%1}, [%2];" \
    : "=r"(r0),"=r"(r1) : "r"(addr))

#define CP16(dst, src) \
  asm volatile("cp.async.ca.shared.global [%0], [%1], 16;" :: "r"(dst), "l"(src))
#define CP16_Z(dst, src) \
  asm volatile("cp.async.ca.shared.global [%0], [%1], 16, 0;" :: "r"(dst), "l"(src))
#define CP_COMMIT() asm volatile("cp.async.commit_group;" ::: "memory")
#define CP_WAIT1()  asm volatile("cp.async.wait_group 1;" ::: "memory")
#define CP_WAIT0()  asm volatile("cp.async.wait_group 0;" ::: "memory")

__device__ __forceinline__ uint32 smem_u32(const void* p){
    uint32 a;
    asm("{ .reg .u64 t; cvta.to.shared.u64 t, %1; cvt.u32.u64 %0, t; }" : "=r"(a) : "l"(p));
    return a;
}

// ---------------- device scratch (static, no allocation) ----------------
__device__ float g_scores[N_TOK*PWY];
__device__ float g_freq[PWY];
__device__ int   g_topidx[NPAIR];
__device__ float g_topval[NPAIR];
__device__ int   g_cnt[3*NE];
__device__ int   g_list[3*NE*NPAIR];
__device__ float g_pre0[NPAIR*DM];
__device__ float g_post0[NPAIR*DM];
// split bf16 activations
__device__ bf16 g_xh[N_TOK*DM],    g_xl[N_TOK*DM];
__device__ bf16 g_h1h[N_TOK*256],  g_h1l[N_TOK*256];
__device__ bf16 g_h2h[N_TOK*128],  g_h2l[N_TOK*128];
__device__ bf16 g_xpreh[NPAIR*DM], g_xprel[NPAIR*DM];
__device__ bf16 g_xmidh[(size_t)NPAIR*HMAX], g_xmidl[(size_t)NPAIR*HMAX];
__device__ bf16 g_xmlph[NPAIR*DM], g_xmlpl[NPAIR*DM];
// split bf16 transposed weights: WT[n][k]
__device__ bf16 g_rw1h[256*256],  g_rw1l[256*256];
__device__ bf16 g_rw2h[128*256],  g_rw2l[128*256];
__device__ bf16 g_rw3h[PWY*128],  g_rw3l[PWY*128];
__device__ bf16 g_pwh[NE*DM*DM],  g_pwl[NE*DM*DM];
__device__ bf16 g_m1h[NE*HMAX*DM], g_m1l[NE*HMAX*DM];
__device__ bf16 g_m2h[NE*DM*HMAX], g_m2l[NE*DM*HMAX];
__device__ bf16 g_qwh[NE*DM*DM],  g_qwl[NE*DM*DM];

__device__ __forceinline__ float geluf(float v){
    return 0.5f*v*(1.0f+erff(v*0.70710678118654752f));
}

// ---------------- weight convert + transpose ----------------
__global__ __launch_bounds__(256) void convt(
    const float* __restrict__ W, bf16* __restrict__ Th,
    bf16* __restrict__ Tl, int R, int C,
    long long wstride, long long tstride)
{
    int e = blockIdx.z;
    __shared__ float tile[32][33];
    int c0 = blockIdx.x*32, r0 = blockIdx.y*32;
    const float* Win = W + (size_t)e*wstride;
    int tx = threadIdx.x & 31, ty = threadIdx.x >> 5;
    for (int i=0;i<32;i+=8)
        tile[ty+i][tx] = Win[(size_t)(r0+ty+i)*C + c0+tx];
    __syncthreads();
    bf16* oh = Th + (size_t)e*tstride;
    bf16* ol = Tl + (size_t)e*tstride;
    for (int i=0;i<32;i+=8){
        float v = tile[tx][ty+i];
        bf16 h = __float2bfloat16(v);
        oh[(size_t)(c0+ty+i)*R + r0+tx] = h;
        ol[(size_t)(c0+ty+i)*R + r0+tx] = __float2bfloat16(v - __bfloat162float(h));
    }
}

// ---------------- split x ----------------
__global__ __launch_bounds__(256) void split_x(const float* __restrict__ x)
{
    int idx = (blockIdx.x*256 + threadIdx.x)*8;
    float4 v0 = *(const float4*)&x[idx];
    float4 v1 = *(const float4*)&x[idx+4];
    float v[8] = {v0.x,v0.y,v0.z,v0.w,v1.x,v1.y,v1.z,v1.w};
    bf162* dh = (bf162*)&g_xh[idx];
    bf162* dl = (bf162*)&g_xl[idx];
#pragma unroll
    for (int j=0;j<4;j++){
        bf16 h0 = __float2bfloat16(v[2*j]);
        bf16 h1 = __float2bfloat16(v[2*j+1]);
        bf16 l0 = __float2bfloat16(v[2*j]   - __bfloat162float(h0));
        bf16 l1 = __float2bfloat16(v[2*j+1] - __bfloat162float(h1));
        dh[j] = __halves2bfloat162(h0,h1);
        dl[j] = __halves2bfloat162(l0,l1);
    }
}

// ---------------- split-bf16 mma.sync GEMM: 128x128 tile, 8 warps, cp.async 2-buf, ldmatrix --
// dyn smem (bf16): [AH | AL | BH | BL], each [2][128][40]
#define SEG 10240            // elems per array (2*128*40)
#define AHo 0
#define ALo SEG
#define BHo (2*SEG)
#define BLo (3*SEG)
#define BUF_E 5120           // elems per buffer (128*40)
#define SMEM_GEMM_BYTES (4*SEG*2)

__global__ __launch_bounds__(256,2) void gemm_bf16(
    const bf16* __restrict__ Ahg, const bf16* __restrict__ Alg, int lda,
    const bf16* __restrict__ Wth, const bf16* __restrict__ Wtl,
    int Kw, long long wse,
    const float* __restrict__ bias, int bse,
    float* __restrict__ Cf, bf16* __restrict__ Chp, bf16* __restrict__ Clp,
    int ldc, int Kfix, int kvar, int nvar, int act, int listoff, int ashift, int osplit)
{
    extern __shared__ bf16 S[];
    int e = blockIdx.z;
    int hid = DM*(2 + (e>>2));
    int K = kvar ? hid : Kfix;
    int n0 = blockIdx.x*128;
    if (nvar && n0 >= hid) return;
    int m0 = blockIdx.y*128;
    const int* list = 0; int cnt = 0;
    if (listoff >= 0){
        cnt = g_cnt[listoff+e];
        if (m0 >= cnt) return;
        list = g_list + (size_t)(listoff+e)*NPAIR;
    }
    __shared__ int pairs[128];
    int tid = threadIdx.x;
    if (tid < 128)
        pairs[tid] = (listoff>=0) ? ((m0+tid < cnt) ? list[m0+tid] : -1) : (m0+tid);
    __syncthreads();

    // cp.async producers: thread t -> row t>>1, 16-elem half (t&1)
    int arow = tid >> 1;
    int half = (tid & 1) * 16;
    int prA = pairs[arow];
    bool avalid = (prA>=0);
    const bf16* Ahp = avalid ? (Ahg + (size_t)(prA>>ashift)*lda) : Ahg;
    const bf16* Alp = avalid ? (Alg + (size_t)(prA>>ashift)*lda) : Alg;
    const bf16* Bhp = Wth + (size_t)e*wse + (size_t)(n0+arow)*Kw;
    const bf16* Blp = Wtl + (size_t)e*wse + (size_t)(n0+arow)*Kw;

    uint32 Sb = smem_u32(S);
    uint32 dAh = Sb + 2*(AHo + arow*40 + half);
    uint32 dAl = Sb + 2*(ALo + arow*40 + half);
    uint32 dBh = Sb + 2*(BHo + arow*40 + half);
    uint32 dBl = Sb + 2*(BLo + arow*40 + half);
    const uint32 bufB = BUF_E*2;

    auto issue = [&](int c){
        uint32 bo = (c&1) ? bufB : 0;
#pragma unroll
        for (int j=0;j<2;j++){
            if (avalid){
                CP16(dAh + bo + j*16, Ahp + c*32 + half + j*8);
                CP16(dAl + bo + j*16, Alp + c*32 + half + j*8);
            } else {
                CP16_Z(dAh + bo + j*16, Ahp);
                CP16_Z(dAl + bo + j*16, Alp);
            }
            CP16(dBh + bo + j*16, Bhp + c*32 + half + j*8);
            CP16(dBl + bo + j*16, Blp + c*32 + half + j*8);
        }
    };

    int lane = tid & 31, wid = tid >> 5;
    int wm = wid >> 2, wn = wid & 3;     // 2 x 4 warp grid -> 64x32 warp tile
    int qr = lane >> 2, qc = lane & 3;
    int al_r = lane & 15, al_c = (lane >> 4) * 8;         // A ldmatrix x4 lane addr
    int bl_r = lane & 7,  bl_c = ((lane >> 3) & 1) * 8;   // B ldmatrix x2 lane addr

    float acc[4][4][4];
#pragma unroll
    for (int i=0;i<4;i++)
#pragma unroll
    for (int j=0;j<4;j++)
#pragma unroll
    for (int q=0;q<4;q++) acc[i][j][q]=0.f;

    int nchunks = K/32;
    issue(0); CP_COMMIT();
    for (int c=0;c<nchunks;c++){
        if (c+1 < nchunks){ issue(c+1); CP_COMMIT(); CP_WAIT1(); }
        else { CP_WAIT0(); }
        __syncthreads();
        int boE = (c&1) ? BUF_E : 0;
#pragma unroll
        for (int k16=0;k16<32;k16+=16){
            uint32 bh[4][2], bl4[4][2];
#pragma unroll
            for (int nf=0;nf<4;nf++){
                int brow = wn*32 + nf*8 + bl_r;
                uint32 abh = Sb + 2*(BHo + boE + brow*40 + k16 + bl_c);
                uint32 abl = Sb + 2*(BLo + boE + brow*40 + k16 + bl_c);
                LDSM_X2(bh[nf][0], bh[nf][1], abh);
                LDSM_X2(bl4[nf][0], bl4[nf][1], abl);
            }
#pragma unroll
            for (int mf=0;mf<4;mf++){
                int ar = wm*64 + mf*16 + al_r;
                uint32 aah = Sb + 2*(AHo + boE + ar*40 + k16 + al_c);
                uint32 aal = Sb + 2*(ALo + boE + ar*40 + k16 + al_c);
                uint32 ah0,ah1,ah2,ah3, al0,al1,al2,al3;
                LDSM_X4(ah0,ah1,ah2,ah3, aah);
                LDSM_X4(al0,al1,al2,al3, aal);
#pragma unroll
                for (int nf=0;nf<4;nf++){
                    MMA_BF16(acc[mf][nf], ah0,ah1,ah2,ah3, bh[nf][0],bh[nf][1]);
                    MMA_BF16(acc[mf][nf], ah0,ah1,ah2,ah3, bl4[nf][0],bl4[nf][1]);
                    MMA_BF16(acc[mf][nf], al0,al1,al2,al3, bh[nf][0],bh[nf][1]);
                }
            }
        }
        __syncthreads();
    }

    bool relu_e = (act==3) && (e&1);
#pragma unroll
    for (int mf=0;mf<4;mf++){
        int r0 = wm*64 + mf*16 + qr;
        int r1 = r0 + 8;
        int pr0 = pairs[r0], pr1 = pairs[r1];
#pragma unroll
        for (int nf=0;nf<4;nf++){
            int n = n0 + wn*32 + nf*8 + qc*2;
            float b0 = bias[(size_t)e*bse + n];
            float b1 = bias[(size_t)e*bse + n + 1];
            float v00 = acc[mf][nf][0] + b0, v01 = acc[mf][nf][1] + b1;
            float v10 = acc[mf][nf][2] + b0, v11 = acc[mf][nf][3] + b1;
            if (act==1){
                v00=geluf(v00); v01=geluf(v01); v10=geluf(v10); v11=geluf(v11);
            } else if (act==3){
                if (relu_e){
                    v00=fmaxf(v00,0.f); v01=fmaxf(v01,0.f);
                    v10=fmaxf(v10,0.f); v11=fmaxf(v11,0.f);
                } else {
                    v00=geluf(v00); v01=geluf(v01);
                    v10=geluf(v10); v11=geluf(v11);
                }
            }
            if (osplit){
                if (pr0>=0){
                    bf16 h0=__float2bfloat16(v00), h1=__float2bfloat16(v01);
                    bf16 l0=__float2bfloat16(v00-__bfloat162float(h0));
                    bf16 l1=__float2bfloat16(v01-__bfloat162float(h1));
                    *(bf162*)&Chp[(size_t)pr0*ldc + n] = __halves2bfloat162(h0,h1);
                    *(bf162*)&Clp[(size_t)pr0*ldc + n] = __halves2bfloat162(l0,l1);
                }
                if (pr1>=0){
                    bf16 h0=__float2bfloat16(v10), h1=__float2bfloat16(v11);
                    bf16 l0=__float2bfloat16(v10-__bfloat162float(h0));
                    bf16 l1=__float2bfloat16(v11-__bfloat162float(h1));
                    *(bf162*)&Chp[(size_t)pr1*ldc + n] = __halves2bfloat162(h0,h1);
                    *(bf162*)&Clp[(size_t)pr1*ldc + n] = __halves2bfloat162(l0,l1);
                }
            } else {
                if (pr0>=0) *(float2*)&Cf[(size_t)pr0*ldc + n] = make_float2(v00,v01);
                if (pr1>=0) *(float2*)&Cf[(size_t)pr1*ldc + n] = make_float2(v10,v11);
            }
        }
    }
}

// ---------------- pre epilogue: LN + act, writes split bf16 ----------------
__global__ __launch_bounds__(256) void epil_pre(
    const float* __restrict__ pg, const float* __restrict__ pbb)
{
    int i = blockIdx.x*8 + (threadIdx.x>>5);
    int lane = threadIdx.x & 31;
    int e = g_topidx[i] >> 8;
    const float* row = g_pre0 + (size_t)i*DM;
    float y[8];
    float4 v0 = *(const float4*)&row[lane*8];
    float4 v1 = *(const float4*)&row[lane*8+4];
    y[0]=v0.x;y[1]=v0.y;y[2]=v0.z;y[3]=v0.w;y[4]=v1.x;y[5]=v1.y;y[6]=v1.z;y[7]=v1.w;
    float s = y[0]+y[1]+y[2]+y[3]+y[4]+y[5]+y[6]+y[7];
#pragma unroll
    for (int m=16;m>0;m>>=1) s += __shfl_xor_sync(0xffffffffu, s, m, 32);
    float mu = s * (1.0f/DM);
    float ss = 0.f;
#pragma unroll
    for (int j=0;j<8;j++){ float d=y[j]-mu; ss += d*d; }
#pragma unroll
    for (int m=16;m>0;m>>=1) ss += __shfl_xor_sync(0xffffffffu, ss, m, 32);
    float rstd = rsqrtf(ss*(1.0f/DM) + 1e-5f);
    int actm = e % 3;
    bf162* dh = (bf162*)&g_xpreh[(size_t)i*DM + lane*8];
    bf162* dl = (bf162*)&g_xprel[(size_t)i*DM + lane*8];
#pragma unroll
    for (int j=0;j<4;j++){
        float o[2];
#pragma unroll
        for (int q=0;q<2;q++){
            int c = lane*8 + 2*j + q;
            float v = (y[2*j+q]-mu)*rstd*pg[e*DM+c] + pbb[e*DM+c];
            o[q] = (actm==0) ? geluf(v) : (actm==1) ? fmaxf(v,0.f) : tanhf(v);
        }
        bf16 h0=__float2bfloat16(o[0]), h1=__float2bfloat16(o[1]);
        bf16 l0=__float2bfloat16(o[0]-__bfloat162float(h0));
        bf16 l1=__float2bfloat16(o[1]-__bfloat162float(h1));
        dh[j] = __halves2bfloat162(h0,h1);
        dl[j] = __halves2bfloat162(l0,l1);
    }
}

// ---------------- post epilogue: optional LN + weighted scatter ----------------
__global__ __launch_bounds__(256) void epil_post(
    const float* __restrict__ qg, const float* __restrict__ qbb,
    float* __restrict__ out_y)
{
    int i = blockIdx.x*8 + (threadIdx.x>>5);
    int lane = threadIdx.x & 31;
    int e = g_topidx[i] & 15;
    const float* row = g_post0 + (size_t)i*DM;
    float y[8];
    float4 v0 = *(const float4*)&row[lane*8];
    float4 v1 = *(const float4*)&row[lane*8+4];
    y[0]=v0.x;y[1]=v0.y;y[2]=v0.z;y[3]=v0.w;y[4]=v1.x;y[5]=v1.y;y[6]=v1.z;y[7]=v1.w;
    if ((e & 1) == 0){
        float s = y[0]+y[1]+y[2]+y[3]+y[4]+y[5]+y[6]+y[7];
#pragma unroll
        for (int m=16;m>0;m>>=1) s += __shfl_xor_sync(0xffffffffu, s, m, 32);
        float mu = s * (1.0f/DM);
        float ss = 0.f;
#pragma unroll
        for (int j=0;j<8;j++){ float d=y[j]-mu; ss += d*d; }
#pragma unroll
        for (int m=16;m>0;m>>=1) ss += __shfl_xor_sync(0xffffffffu, ss, m, 32);
        float rstd = rsqrtf(ss*(1.0f/DM) + 1e-5f);
#pragma unroll
        for (int j=0;j<8;j++){
            int c = lane*8 + j;
            y[j] = (y[j]-mu)*rstd*qg[e*DM+c] + qbb[e*DM+c];
        }
    }
    float w = g_topval[i];
    int tok = i >> 2;
#pragma unroll
    for (int j=0;j<8;j++)
        atomicAdd(&out_y[(size_t)tok*DM + lane*8 + j], y[j]*w);
}

// ---------------- softmax + topk (validated) ----------------
__global__ __launch_bounds__(256) void softmax_topk(
    const float* __restrict__ temp, float* __restrict__ pwout)
{
    __shared__ float s[PWY];
    __shared__ float rv[256*4];
    __shared__ int   ri[256*4];
    __shared__ float red1[256];
    __shared__ float red2[256];
    __shared__ float pv[KSEL];
    int n = blockIdx.x, tid = threadIdx.x;
    float* srow = g_scores + (size_t)n*PWY;
    for (int i=0;i<4;i++){
        int idx = i*1024 + tid*4;
        *(float4*)&s[idx] = *(const float4*)&srow[idx];
    }
    __syncthreads();
    float invt = 1.0f/temp[0];

    float tv[4] = {-INFINITY,-INFINITY,-INFINITY,-INFINITY};
    int tix[4] = {PWY,PWY,PWY,PWY};
    float lm = -INFINITY;
#pragma unroll
    for (int i=0;i<16;i++){
        int j = tid + i*256;
        float v = s[j];
        lm = fmaxf(lm, v);
        if (v > tv[3] || (v == tv[3] && j < tix[3])){
            tv[3]=v; tix[3]=j;
#pragma unroll
            for (int q=3;q>0;q--){
                if (tv[q] > tv[q-1] || (tv[q]==tv[q-1] && tix[q] < tix[q-1])){
                    float tmv=tv[q]; tv[q]=tv[q-1]; tv[q-1]=tmv;
                    int tmi=tix[q]; tix[q]=tix[q-1]; tix[q-1]=tmi;
                }
            }
        }
    }
    red1[tid]=lm; __syncthreads();
    for (int off=128;off>0;off>>=1){ if(tid<off) red1[tid]=fmaxf(red1[tid],red1[tid+off]); __syncthreads(); }
    float m0 = red1[0]; __syncthreads();

    float f[16]; float ls0=0.f, lst=0.f;
#pragma unroll
    for (int i=0;i<16;i++){
        int j = tid + i*256;
        float d = s[j]-m0;
        float e0 = __expf(d);
        f[i]=e0; ls0+=e0;
        lst += __expf(d*invt);
    }
    red1[tid]=ls0; red2[tid]=lst; __syncthreads();
    for (int off=128;off>0;off>>=1){
        if(tid<off){ red1[tid]+=red1[tid+off]; red2[tid]+=red2[tid+off]; }
        __syncthreads();
    }
    float inv0 = 1.0f/red1[0];
    float invsumt = 1.0f/red2[0];
    __syncthreads();

#pragma unroll
    for (int i=0;i<16;i++) srow[tid + i*256] = f[i]*inv0;

#pragma unroll
    for (int q=0;q<4;q++){ rv[tid*4+q]=tv[q]; ri[tid*4+q]=tix[q]; }
    __syncthreads();
    for (int off=128;off>0;off>>=1){
        if (tid < off){
            float a0[4], b0[4]; int ai[4], bi[4];
#pragma unroll
            for (int q=0;q<4;q++){
                a0[q]=rv[tid*4+q]; ai[q]=ri[tid*4+q];
                b0[q]=rv[(tid+off)*4+q]; bi[q]=ri[(tid+off)*4+q];
            }
            int ia=0, ib=0;
            float ov[4]; int oi[4];
#pragma unroll
            for (int q=0;q<4;q++){
                bool ta = (a0[ia] > b0[ib]) || (a0[ia]==b0[ib] && ai[ia] < bi[ib]);
                if (ta){ ov[q]=a0[ia]; oi[q]=ai[ia]; ia++; }
                else   { ov[q]=b0[ib]; oi[q]=bi[ib]; ib++; }
            }
#pragma unroll
            for (int q=0;q<4;q++){ rv[tid*4+q]=ov[q]; ri[tid*4+q]=oi[q]; }
        }
        __syncthreads();
    }

    if (tid < KSEL){
        int se = ri[tid];
        float p = __expf((s[se]-m0)*invt)*invsumt;
        pv[tid]=p;
        g_topidx[n*KSEL+tid]=se;
        g_topval[n*KSEL+tid]=p;
    }
    __syncthreads();
    float invps = 1.0f/(pv[0]+pv[1]+pv[2]+pv[3] + 1e-8f);
    int s0=ri[0], s1=ri[1], s2=ri[2], s3=ri[3];
    float w0=pv[0]*invps, w1=pv[1]*invps, w2=pv[2]*invps, w3=pv[3]*invps;
    float* prow = pwout + (size_t)n*PWY;
    for (int i=0;i<16;i++){
        int j = tid + i*256;
        float v = 0.f;
        if (j==s0) v=w0; else if (j==s1) v=w1; else if (j==s2) v=w2; else if (j==s3) v=w3;
        prow[j]=v;
    }
}

// ---------------- freq + loss + lists ----------------
__global__ __launch_bounds__(256) void freq_partial()
{
    int p = blockIdx.x*256 + threadIdx.x;
    int nbeg = blockIdx.y*256;
    float acc = 0.f;
    for (int n=nbeg; n<nbeg+256; n++)
        acc += g_scores[(size_t)n*PWY + p];
    atomicAdd(&g_freq[p], acc);
}

__global__ __launch_bounds__(256) void glbl_loss_kernel(float* __restrict__ out)
{
    __shared__ float red[256];
    int tid = threadIdx.x;
    const float invN = 1.0f/(float)N_TOK;
    float lsum = 0.f;
    for (int i=0;i<PWY/256;i++) lsum += g_freq[tid+i*256]*invN;
    red[tid]=lsum; __syncthreads();
    for (int off=128;off>0;off>>=1){ if(tid<off) red[tid]+=red[tid+off]; __syncthreads(); }
    float mean = red[0]/(float)PWY; __syncthreads();
    float lss = 0.f;
    for (int i=0;i<PWY/256;i++){
        float d = g_freq[tid+i*256]*invN - mean;
        lss += d*d;
    }
    red[tid]=lss; __syncthreads();
    for (int off=128;off>0;off>>=1){ if(tid<off) red[tid]+=red[tid+off]; __syncthreads(); }
    if (tid==0) out[0] = (float)PWY * (red[0]/(float)(PWY-1));
}

__global__ __launch_bounds__(256) void build_lists()
{
    int i = blockIdx.x*256 + threadIdx.x;
    if (i >= NPAIR) return;
    int idx = g_topidx[i];
    int pe = idx >> 8, rem = idx & 255;
    int me = rem >> 4, qe = rem & 15;
    int pos;
    pos = atomicAdd(&g_cnt[pe], 1);         g_list[pe*NPAIR + pos] = i;
    pos = atomicAdd(&g_cnt[NE+me], 1);      g_list[(NE+me)*NPAIR + pos] = i;
    pos = atomicAdd(&g_cnt[2*NE+qe], 1);    g_list[(2*NE+qe)*NPAIR + pos] = i;
}

// ---------------- host launch ----------------
extern "C" void kernel_launch(void* const* d_in, const int* in_sizes, int n_in,
                              void* d_out, int out_size)
{
    const float* x   = (const float*)d_in[0];
    const float* rw1 = (const float*)d_in[1];
    const float* rb1 = (const float*)d_in[2];
    const float* rw2 = (const float*)d_in[3];
    const float* rb2 = (const float*)d_in[4];
    const float* rw3 = (const float*)d_in[5];
    const float* rb3 = (const float*)d_in[6];
    const float* temp= (const float*)d_in[7];
    const float* pw  = (const float*)d_in[8];
    const float* pb  = (const float*)d_in[9];
    const float* pg  = (const float*)d_in[10];
    const float* pbb = (const float*)d_in[11];
    const float* mw1 = (const float*)d_in[12];
    const float* mb1 = (const float*)d_in[13];
    const float* mw2 = (const float*)d_in[14];
    const float* mb2 = (const float*)d_in[15];
    const float* qw  = (const float*)d_in[16];
    const float* qb  = (const float*)d_in[17];
    const float* qg  = (const float*)d_in[18];
    const float* qbb = (const float*)d_in[19];

    float* out      = (float*)d_out;
    float* out_y    = out;
    float* out_loss = out + N_TOK*DM;
    float* out_pw   = out + N_TOK*DM + 1;

    void* p;
    cudaGetSymbolAddress(&p, g_scores); float* scores = (float*)p;
    cudaGetSymbolAddress(&p, g_freq);   float* freqp = (float*)p;
    cudaGetSymbolAddress(&p, g_cnt);    int*   cntp = (int*)p;
    cudaGetSymbolAddress(&p, g_pre0);   float* pre0 = (float*)p;
    cudaGetSymbolAddress(&p, g_post0);  float* post0 = (float*)p;
    cudaGetSymbolAddress(&p, g_xh);     bf16* xh = (bf16*)p;
    cudaGetSymbolAddress(&p, g_xl);     bf16* xl = (bf16*)p;
    cudaGetSymbolAddress(&p, g_h1h);    bf16* h1h = (bf16*)p;
    cudaGetSymbolAddress(&p, g_h1l);    bf16* h1l = (bf16*)p;
    cudaGetSymbolAddress(&p, g_h2h);    bf16* h2h = (bf16*)p;
    cudaGetSymbolAddress(&p, g_h2l);    bf16* h2l = (bf16*)p;
    cudaGetSymbolAddress(&p, g_xpreh);  bf16* xpreh = (bf16*)p;
    cudaGetSymbolAddress(&p, g_xprel);  bf16* xprel = (bf16*)p;
    cudaGetSymbolAddress(&p, g_xmidh);  bf16* xmidh = (bf16*)p;
    cudaGetSymbolAddress(&p, g_xmidl);  bf16* xmidl = (bf16*)p;
    cudaGetSymbolAddress(&p, g_xmlph);  bf16* xmlph = (bf16*)p;
    cudaGetSymbolAddress(&p, g_xmlpl);  bf16* xmlpl = (bf16*)p;
    cudaGetSymbolAddress(&p, g_rw1h);   bf16* rw1h = (bf16*)p;
    cudaGetSymbolAddress(&p, g_rw1l);   bf16* rw1l = (bf16*)p;
    cudaGetSymbolAddress(&p, g_rw2h);   bf16* rw2h = (bf16*)p;
    cudaGetSymbolAddress(&p, g_rw2l);   bf16* rw2l = (bf16*)p;
    cudaGetSymbolAddress(&p, g_rw3h);   bf16* rw3h = (bf16*)p;
    cudaGetSymbolAddress(&p, g_rw3l);   bf16* rw3l = (bf16*)p;
    cudaGetSymbolAddress(&p, g_pwh);    bf16* pwh = (bf16*)p;
    cudaGetSymbolAddress(&p, g_pwl);    bf16* pwl = (bf16*)p;
    cudaGetSymbolAddress(&p, g_m1h);    bf16* m1h = (bf16*)p;
    cudaGetSymbolAddress(&p, g_m1l);    bf16* m1l = (bf16*)p;
    cudaGetSymbolAddress(&p, g_m2h);    bf16* m2h = (bf16*)p;
    cudaGetSymbolAddress(&p, g_m2l);    bf16* m2l = (bf16*)p;
    cudaGetSymbolAddress(&p, g_qwh);    bf16* qwh = (bf16*)p;
    cudaGetSymbolAddress(&p, g_qwl);    bf16* qwl = (bf16*)p;

    cudaFuncSetAttribute(gemm_bf16, cudaFuncAttributeMaxDynamicSharedMemorySize, SMEM_GEMM_BYTES);

    cudaMemsetAsync(out_y, 0, (size_t)N_TOK*DM*sizeof(float), 0);
    cudaMemsetAsync(freqp, 0, PWY*sizeof(float), 0);
    cudaMemsetAsync(cntp,  0, 3*NE*sizeof(int), 0);

    // weight conversion + transpose (bf16 hi/lo)
    convt<<<dim3(256/32, 256/32, 1), 256>>>(rw1, rw1h, rw1l, 256, 256, 0LL, 0LL);
    convt<<<dim3(128/32, 256/32, 1), 256>>>(rw2, rw2h, rw2l, 256, 128, 0LL, 0LL);
    convt<<<dim3(PWY/32, 128/32, 1), 256>>>(rw3, rw3h, rw3l, 128, PWY, 0LL, 0LL);
    convt<<<dim3(DM/32, DM/32, NE), 256>>>(pw, pwh, pwl, DM, DM,
        (long long)DM*DM, (long long)DM*DM);
    convt<<<dim3(HMAX/32, DM/32, NE), 256>>>(mw1, m1h, m1l, DM, HMAX,
        (long long)DM*HMAX, (long long)HMAX*DM);
    convt<<<dim3(DM/32, HMAX/32, NE), 256>>>(mw2, m2h, m2l, HMAX, DM,
        (long long)HMAX*DM, (long long)DM*HMAX);
    convt<<<dim3(DM/32, DM/32, NE), 256>>>(qw, qwh, qwl, DM, DM,
        (long long)DM*DM, (long long)DM*DM);

    // split x once
    split_x<<<N_TOK*DM/(256*8), 256>>>(x);

    // router
    gemm_bf16<<<dim3(2, N_TOK/128, 1), 256, SMEM_GEMM_BYTES>>>(
        xh, xl, DM, rw1h, rw1l, 256, 0LL, rb1, 0,
        0, h1h, h1l, 256, 256, 0, 0, 1, -1, 0, 1);
    gemm_bf16<<<dim3(1, N_TOK/128, 1), 256, SMEM_GEMM_BYTES>>>(
        h1h, h1l, 256, rw2h, rw2l, 256, 0LL, rb2, 0,
        0, h2h, h2l, 128, 256, 0, 0, 1, -1, 0, 1);
    gemm_bf16<<<dim3(PWY/128, N_TOK/128, 1), 256, SMEM_GEMM_BYTES>>>(
        h2h, h2l, 128, rw3h, rw3l, 128, 0LL, rb3, 0,
        scores, 0, 0, PWY, 128, 0, 0, 0, -1, 0, 0);

    // softmax + topk + pathway weights + probs writeback
    softmax_topk<<<N_TOK, 256>>>(temp, out_pw);

    // GLBL loss
    freq_partial<<<dim3(PWY/256, N_TOK/256), 256>>>();
    glbl_loss_kernel<<<1, 256>>>(out_loss);

    // routing
    build_lists<<<NPAIR/256, 256>>>();

    // pre experts: gemm -> LN epilogue
    gemm_bf16<<<dim3(DM/128, NPAIR/128, NE), 256, SMEM_GEMM_BYTES>>>(
        xh, xl, DM, pwh, pwl, DM, (long long)DM*DM, pb, DM,
        pre0, 0, 0, DM, DM, 0, 0, 0, 0, 2, 0);
    epil_pre<<<NPAIR/8, 256>>>(pg, pbb);

    // mlp experts
    gemm_bf16<<<dim3(HMAX/128, NPAIR/128, NE), 256, SMEM_GEMM_BYTES>>>(
        xpreh, xprel, DM, m1h, m1l, DM, (long long)HMAX*DM, mb1, HMAX,
        0, xmidh, xmidl, HMAX, DM, 0, 1, 3, NE, 0, 1);
    gemm_bf16<<<dim3(DM/128, NPAIR/128, NE), 256, SMEM_GEMM_BYTES>>>(
        xmidh, xmidl, HMAX, m2h, m2l, HMAX, (long long)DM*HMAX, mb2, DM,
        0, xmlph, xmlpl, DM, 0, 1, 0, 0, NE, 0, 1);

    // post experts: gemm -> LN + scatter epilogue
    gemm_bf16<<<dim3(DM/128, NPAIR/128, NE), 256, SMEM_GEMM_BYTES>>>(
        xmlph, xmlpl, DM, qwh, qwl, DM, (long long)DM*DM, qb, DM,
        post0, 0, 0, DM, DM, 0, 0, 0, 2*NE, 0, 0);
    epil_post<<<NPAIR/8, 256>>>(qg, qbb, out_y);
}

// round 13
// speedup vs baseline: 1.3109x; 1.0023x over previous
#include <cuda_runtime.h>
#include <cuda_bf16.h>
#include <cstdint>
#include <math.h>

#define N_TOK 2048
#define DM 256
#define PWY 4096
#define KSEL 4
#define NE 16
#define HMAX 1280
#define NPAIR (N_TOK*KSEL)

typedef unsigned long long u64;
typedef unsigned int uint32;
typedef __nv_bfloat16 bf16;
typedef __nv_bfloat162 bf162;

#define MMA_BF16(d, a0,a1,a2,a3, b0,b1) \
  asm volatile("mma.sync.aligned.m16n8k16.row.col.f32.bf16.bf16.f32 " \
    "{%0,%1,%2,%3}, {%4,%5,%6,%7}, {%8,%9}, {%0,%1,%2,%3};" \
    : "+f"(d[0]),"+f"(d[1]),"+f"(d[2]),"+f"(d[3]) \
    : "r"(a0),"r"(a1),"r"(a2),"r"(a3),"r"(b0),"r"(b1))

#define LDSM_X4(r0,r1,r2,r3,addr) \
  asm volatile("ldmatrix.sync.aligned.m8n8.x4.shared.b16 {%0,%1,%2,%3}, [%4];" \
    : "=r"(r0),"=r"(r1),"=r"(r2),"=r"(r3) : "r"(addr))
#define LDSM_X2(r0,r1,addr) \
  asm volatile("ldmatrix.sync.aligned.m8n8.x2.shared.b16 {%0,%1}, [%2];" \
    : "=r"(r0),"=r"(r1) : "r"(addr))

#define CP16(dst, src) \
  asm volatile("cp.async.ca.shared.global [%0], [%1], 16;" :: "r"(dst), "l"(src))
#define CP16_Z(dst, src) \
  asm volatile("cp.async.ca.shared.global [%0], [%1], 16, 0;" :: "r"(dst), "l"(src))
#define CP_COMMIT() asm volatile("cp.async.commit_group;" ::: "memory")
#define CP_WAIT1()  asm volatile("cp.async.wait_group 1;" ::: "memory")
#define CP_WAIT0()  asm volatile("cp.async.wait_group 0;" ::: "memory")

__device__ __forceinline__ uint32 smem_u32(const void* p){
    uint32 a;
    asm("{ .reg .u64 t; cvta.to.shared.u64 t, %1; cvt.u32.u64 %0, t; }" : "=r"(a) : "l"(p));
    return a;
}

// ---------------- device scratch (static, no allocation) ----------------
__device__ float g_scores[N_TOK*PWY];
__device__ float g_freq[PWY];
__device__ int   g_topidx[NPAIR];
__device__ float g_topval[NPAIR];
__device__ int   g_cnt[3*NE];
__device__ int   g_list[3*NE*NPAIR];
__device__ float g_pre0[NPAIR*DM];
__device__ float g_post0[NPAIR*DM];
// split bf16 activations
__device__ bf16 g_xh[N_TOK*DM],    g_xl[N_TOK*DM];
__device__ bf16 g_h1h[N_TOK*256],  g_h1l[N_TOK*256];
__device__ bf16 g_h2h[N_TOK*128],  g_h2l[N_TOK*128];
__device__ bf16 g_xpreh[NPAIR*DM], g_xprel[NPAIR*DM];
__device__ bf16 g_xmidh[(size_t)NPAIR*HMAX], g_xmidl[(size_t)NPAIR*HMAX];
__device__ bf16 g_xmlph[NPAIR*DM], g_xmlpl[NPAIR*DM];
// split bf16 transposed weights: WT[n][k]
__device__ bf16 g_rw1h[256*256],  g_rw1l[256*256];
__device__ bf16 g_rw2h[128*256],  g_rw2l[128*256];
__device__ bf16 g_rw3h[PWY*128],  g_rw3l[PWY*128];
__device__ bf16 g_pwh[NE*DM*DM],  g_pwl[NE*DM*DM];
__device__ bf16 g_m1h[NE*HMAX*DM], g_m1l[NE*HMAX*DM];
__device__ bf16 g_m2h[NE*DM*HMAX], g_m2l[NE*DM*HMAX];
__device__ bf16 g_qwh[NE*DM*DM],  g_qwl[NE*DM*DM];

__device__ __forceinline__ float geluf(float v){
    return 0.5f*v*(1.0f+erff(v*0.70710678118654752f));
}

// ---------------- weight convert + transpose ----------------
__global__ __launch_bounds__(256) void convt(
    const float* __restrict__ W, bf16* __restrict__ Th,
    bf16* __restrict__ Tl, int R, int C,
    long long wstride, long long tstride)
{
    int e = blockIdx.z;
    __shared__ float tile[32][33];
    int c0 = blockIdx.x*32, r0 = blockIdx.y*32;
    const float* Win = W + (size_t)e*wstride;
    int tx = threadIdx.x & 31, ty = threadIdx.x >> 5;
    for (int i=0;i<32;i+=8)
        tile[ty+i][tx] = Win[(size_t)(r0+ty+i)*C + c0+tx];
    __syncthreads();
    bf16* oh = Th + (size_t)e*tstride;
    bf16* ol = Tl + (size_t)e*tstride;
    for (int i=0;i<32;i+=8){
        float v = tile[tx][ty+i];
        bf16 h = __float2bfloat16(v);
        oh[(size_t)(c0+ty+i)*R + r0+tx] = h;
        ol[(size_t)(c0+ty+i)*R + r0+tx] = __float2bfloat16(v - __bfloat162float(h));
    }
}

// ---------------- split x ----------------
__global__ __launch_bounds__(256) void split_x(const float* __restrict__ x)
{
    int idx = (blockIdx.x*256 + threadIdx.x)*8;
    float4 v0 = *(const float4*)&x[idx];
    float4 v1 = *(const float4*)&x[idx+4];
    float v[8] = {v0.x,v0.y,v0.z,v0.w,v1.x,v1.y,v1.z,v1.w};
    bf162* dh = (bf162*)&g_xh[idx];
    bf162* dl = (bf162*)&g_xl[idx];
#pragma unroll
    for (int j=0;j<4;j++){
        bf16 h0 = __float2bfloat16(v[2*j]);
        bf16 h1 = __float2bfloat16(v[2*j+1]);
        bf16 l0 = __float2bfloat16(v[2*j]   - __bfloat162float(h0));
        bf16 l1 = __float2bfloat16(v[2*j+1] - __bfloat162float(h1));
        dh[j] = __halves2bfloat162(h0,h1);
        dl[j] = __halves2bfloat162(l0,l1);
    }
}

// ---------------- split-bf16 mma.sync GEMM: 128x128 tile, 8 warps, cp.async 2-buf, ldmatrix --
#define SEG 10240
#define AHo 0
#define ALo SEG
#define BHo (2*SEG)
#define BLo (3*SEG)
#define BUF_E 5120
#define SMEM_GEMM_BYTES (4*SEG*2)

__global__ __launch_bounds__(256,2) void gemm_bf16(
    const bf16* __restrict__ Ahg, const bf16* __restrict__ Alg, int lda,
    const bf16* __restrict__ Wth, const bf16* __restrict__ Wtl,
    int Kw, long long wse,
    const float* __restrict__ bias, int bse,
    float* __restrict__ Cf, bf16* __restrict__ Chp, bf16* __restrict__ Clp,
    int ldc, int Kfix, int kvar, int nvar, int act, int listoff, int ashift, int osplit)
{
    extern __shared__ bf16 S[];
    int e = blockIdx.z;
    int hid = DM*(2 + (e>>2));
    int K = kvar ? hid : Kfix;
    int n0 = blockIdx.x*128;
    if (nvar && n0 >= hid) return;
    int m0 = blockIdx.y*128;
    const int* list = 0; int cnt = 0;
    if (listoff >= 0){
        cnt = g_cnt[listoff+e];
        if (m0 >= cnt) return;
        list = g_list + (size_t)(listoff+e)*NPAIR;
    }
    __shared__ int pairs[128];
    int tid = threadIdx.x;
    if (tid < 128)
        pairs[tid] = (listoff>=0) ? ((m0+tid < cnt) ? list[m0+tid] : -1) : (m0+tid);
    __syncthreads();

    int arow = tid >> 1;
    int half = (tid & 1) * 16;
    int prA = pairs[arow];
    bool avalid = (prA>=0);
    const bf16* Ahp = avalid ? (Ahg + (size_t)(prA>>ashift)*lda) : Ahg;
    const bf16* Alp = avalid ? (Alg + (size_t)(prA>>ashift)*lda) : Alg;
    const bf16* Bhp = Wth + (size_t)e*wse + (size_t)(n0+arow)*Kw;
    const bf16* Blp = Wtl + (size_t)e*wse + (size_t)(n0+arow)*Kw;

    uint32 Sb = smem_u32(S);
    uint32 dAh = Sb + 2*(AHo + arow*40 + half);
    uint32 dAl = Sb + 2*(ALo + arow*40 + half);
    uint32 dBh = Sb + 2*(BHo + arow*40 + half);
    uint32 dBl = Sb + 2*(BLo + arow*40 + half);
    const uint32 bufB = BUF_E*2;

    auto issue = [&](int c){
        uint32 bo = (c&1) ? bufB : 0;
#pragma unroll
        for (int j=0;j<2;j++){
            if (avalid){
                CP16(dAh + bo + j*16, Ahp + c*32 + half + j*8);
                CP16(dAl + bo + j*16, Alp + c*32 + half + j*8);
            } else {
                CP16_Z(dAh + bo + j*16, Ahp);
                CP16_Z(dAl + bo + j*16, Alp);
            }
            CP16(dBh + bo + j*16, Bhp + c*32 + half + j*8);
            CP16(dBl + bo + j*16, Blp + c*32 + half + j*8);
        }
    };

    int lane = tid & 31, wid = tid >> 5;
    int wm = wid >> 2, wn = wid & 3;
    int qr = lane >> 2, qc = lane & 3;
    int al_r = lane & 15, al_c = (lane >> 4) * 8;
    int bl_r = lane & 7,  bl_c = ((lane >> 3) & 1) * 8;

    float acc[4][4][4];
#pragma unroll
    for (int i=0;i<4;i++)
#pragma unroll
    for (int j=0;j<4;j++)
#pragma unroll
    for (int q=0;q<4;q++) acc[i][j][q]=0.f;

    int nchunks = K/32;
    issue(0); CP_COMMIT();
    for (int c=0;c<nchunks;c++){
        if (c+1 < nchunks){ issue(c+1); CP_COMMIT(); CP_WAIT1(); }
        else { CP_WAIT0(); }
        __syncthreads();
        int boE = (c&1) ? BUF_E : 0;
#pragma unroll
        for (int k16=0;k16<32;k16+=16){
            uint32 bh[4][2], bl4[4][2];
#pragma unroll
            for (int nf=0;nf<4;nf++){
                int brow = wn*32 + nf*8 + bl_r;
                uint32 abh = Sb + 2*(BHo + boE + brow*40 + k16 + bl_c);
                uint32 abl = Sb + 2*(BLo + boE + brow*40 + k16 + bl_c);
                LDSM_X2(bh[nf][0], bh[nf][1], abh);
                LDSM_X2(bl4[nf][0], bl4[nf][1], abl);
            }
#pragma unroll
            for (int mf=0;mf<4;mf++){
                int ar = wm*64 + mf*16 + al_r;
                uint32 aah = Sb + 2*(AHo + boE + ar*40 + k16 + al_c);
                uint32 aal = Sb + 2*(ALo + boE + ar*40 + k16 + al_c);
                uint32 ah0,ah1,ah2,ah3, al0,al1,al2,al3;
                LDSM_X4(ah0,ah1,ah2,ah3, aah);
                LDSM_X4(al0,al1,al2,al3, aal);
#pragma unroll
                for (int nf=0;nf<4;nf++){
                    MMA_BF16(acc[mf][nf], ah0,ah1,ah2,ah3, bh[nf][0],bh[nf][1]);
                    MMA_BF16(acc[mf][nf], ah0,ah1,ah2,ah3, bl4[nf][0],bl4[nf][1]);
                    MMA_BF16(acc[mf][nf], al0,al1,al2,al3, bh[nf][0],bh[nf][1]);
                }
            }
        }
        __syncthreads();
    }

    bool relu_e = (act==3) && (e&1);
#pragma unroll
    for (int mf=0;mf<4;mf++){
        int r0 = wm*64 + mf*16 + qr;
        int r1 = r0 + 8;
        int pr0 = pairs[r0], pr1 = pairs[r1];
#pragma unroll
        for (int nf=0;nf<4;nf++){
            int n = n0 + wn*32 + nf*8 + qc*2;
            float b0 = bias[(size_t)e*bse + n];
            float b1 = bias[(size_t)e*bse + n + 1];
            float v00 = acc[mf][nf][0] + b0, v01 = acc[mf][nf][1] + b1;
            float v10 = acc[mf][nf][2] + b0, v11 = acc[mf][nf][3] + b1;
            if (act==1){
                v00=geluf(v00); v01=geluf(v01); v10=geluf(v10); v11=geluf(v11);
            } else if (act==3){
                if (relu_e){
                    v00=fmaxf(v00,0.f); v01=fmaxf(v01,0.f);
                    v10=fmaxf(v10,0.f); v11=fmaxf(v11,0.f);
                } else {
                    v00=geluf(v00); v01=geluf(v01);
                    v10=geluf(v10); v11=geluf(v11);
                }
            }
            if (osplit){
                if (pr0>=0){
                    bf16 h0=__float2bfloat16(v00), h1=__float2bfloat16(v01);
                    bf16 l0=__float2bfloat16(v00-__bfloat162float(h0));
                    bf16 l1=__float2bfloat16(v01-__bfloat162float(h1));
                    *(bf162*)&Chp[(size_t)pr0*ldc + n] = __halves2bfloat162(h0,h1);
                    *(bf162*)&Clp[(size_t)pr0*ldc + n] = __halves2bfloat162(l0,l1);
                }
                if (pr1>=0){
                    bf16 h0=__float2bfloat16(v10), h1=__float2bfloat16(v11);
                    bf16 l0=__float2bfloat16(v10-__bfloat162float(h0));
                    bf16 l1=__float2bfloat16(v11-__bfloat162float(h1));
                    *(bf162*)&Chp[(size_t)pr1*ldc + n] = __halves2bfloat162(h0,h1);
                    *(bf162*)&Clp[(size_t)pr1*ldc + n] = __halves2bfloat162(l0,l1);
                }
            } else {
                if (pr0>=0) *(float2*)&Cf[(size_t)pr0*ldc + n] = make_float2(v00,v01);
                if (pr1>=0) *(float2*)&Cf[(size_t)pr1*ldc + n] = make_float2(v10,v11);
            }
        }
    }
}

// ---------------- pre epilogue: LN + act, writes split bf16 ----------------
__global__ __launch_bounds__(256) void epil_pre(
    const float* __restrict__ pg, const float* __restrict__ pbb)
{
    int i = blockIdx.x*8 + (threadIdx.x>>5);
    int lane = threadIdx.x & 31;
    int e = g_topidx[i] >> 8;
    const float* row = g_pre0 + (size_t)i*DM;
    float y[8];
    float4 v0 = *(const float4*)&row[lane*8];
    float4 v1 = *(const float4*)&row[lane*8+4];
    y[0]=v0.x;y[1]=v0.y;y[2]=v0.z;y[3]=v0.w;y[4]=v1.x;y[5]=v1.y;y[6]=v1.z;y[7]=v1.w;
    float s = y[0]+y[1]+y[2]+y[3]+y[4]+y[5]+y[6]+y[7];
#pragma unroll
    for (int m=16;m>0;m>>=1) s += __shfl_xor_sync(0xffffffffu, s, m, 32);
    float mu = s * (1.0f/DM);
    float ss = 0.f;
#pragma unroll
    for (int j=0;j<8;j++){ float d=y[j]-mu; ss += d*d; }
#pragma unroll
    for (int m=16;m>0;m>>=1) ss += __shfl_xor_sync(0xffffffffu, ss, m, 32);
    float rstd = rsqrtf(ss*(1.0f/DM) + 1e-5f);
    int actm = e % 3;
    bf162* dh = (bf162*)&g_xpreh[(size_t)i*DM + lane*8];
    bf162* dl = (bf162*)&g_xprel[(size_t)i*DM + lane*8];
#pragma unroll
    for (int j=0;j<4;j++){
        float o[2];
#pragma unroll
        for (int q=0;q<2;q++){
            int c = lane*8 + 2*j + q;
            float v = (y[2*j+q]-mu)*rstd*pg[e*DM+c] + pbb[e*DM+c];
            o[q] = (actm==0) ? geluf(v) : (actm==1) ? fmaxf(v,0.f) : tanhf(v);
        }
        bf16 h0=__float2bfloat16(o[0]), h1=__float2bfloat16(o[1]);
        bf16 l0=__float2bfloat16(o[0]-__bfloat162float(h0));
        bf16 l1=__float2bfloat16(o[1]-__bfloat162float(h1));
        dh[j] = __halves2bfloat162(h0,h1);
        dl[j] = __halves2bfloat162(l0,l1);
    }
}

// ---------------- post epilogue: warp-per-token, LN + weighted sum, no atomics -------------
__global__ __launch_bounds__(256) void epil_post(
    const float* __restrict__ qg, const float* __restrict__ qbb,
    float* __restrict__ out_y)
{
    int tok = blockIdx.x*8 + (threadIdx.x>>5);
    int lane = threadIdx.x & 31;
    float acc[8] = {0.f,0.f,0.f,0.f,0.f,0.f,0.f,0.f};
#pragma unroll
    for (int slot=0; slot<KSEL; slot++){
        int i = tok*KSEL + slot;
        int e = g_topidx[i] & 15;
        const float* row = g_post0 + (size_t)i*DM;
        float y[8];
        float4 v0 = *(const float4*)&row[lane*8];
        float4 v1 = *(const float4*)&row[lane*8+4];
        y[0]=v0.x;y[1]=v0.y;y[2]=v0.z;y[3]=v0.w;y[4]=v1.x;y[5]=v1.y;y[6]=v1.z;y[7]=v1.w;
        if ((e & 1) == 0){
            float s = y[0]+y[1]+y[2]+y[3]+y[4]+y[5]+y[6]+y[7];
#pragma unroll
            for (int m=16;m>0;m>>=1) s += __shfl_xor_sync(0xffffffffu, s, m, 32);
            float mu = s * (1.0f/DM);
            float ss = 0.f;
#pragma unroll
            for (int j=0;j<8;j++){ float d=y[j]-mu; ss += d*d; }
#pragma unroll
            for (int m=16;m>0;m>>=1) ss += __shfl_xor_sync(0xffffffffu, ss, m, 32);
            float rstd = rsqrtf(ss*(1.0f/DM) + 1e-5f);
#pragma unroll
            for (int j=0;j<8;j++){
                int c = lane*8 + j;
                y[j] = (y[j]-mu)*rstd*qg[e*DM+c] + qbb[e*DM+c];
            }
        }
        float w = g_topval[i];
#pragma unroll
        for (int j=0;j<8;j++) acc[j] += y[j]*w;
    }
    float* orow = out_y + (size_t)tok*DM + lane*8;
    *(float4*)&orow[0] = make_float4(acc[0],acc[1],acc[2],acc[3]);
    *(float4*)&orow[4] = make_float4(acc[4],acc[5],acc[6],acc[7]);
}

// ---------------- softmax + topk (R10-validated smem-tree version) ----------------
__global__ __launch_bounds__(256) void softmax_topk(
    const float* __restrict__ temp, float* __restrict__ pwout)
{
    __shared__ float s[PWY];
    __shared__ float rv[256*4];
    __shared__ int   ri[256*4];
    __shared__ float red1[256];
    __shared__ float red2[256];
    __shared__ float pv[KSEL];
    int n = blockIdx.x, tid = threadIdx.x;
    float* srow = g_scores + (size_t)n*PWY;
    for (int i=0;i<4;i++){
        int idx = i*1024 + tid*4;
        *(float4*)&s[idx] = *(const float4*)&srow[idx];
    }
    __syncthreads();
    float invt = 1.0f/temp[0];

    float tv[4] = {-INFINITY,-INFINITY,-INFINITY,-INFINITY};
    int tix[4] = {PWY,PWY,PWY,PWY};
    float lm = -INFINITY;
#pragma unroll
    for (int i=0;i<16;i++){
        int j = tid + i*256;
        float v = s[j];
        lm = fmaxf(lm, v);
        if (v > tv[3] || (v == tv[3] && j < tix[3])){
            tv[3]=v; tix[3]=j;
#pragma unroll
            for (int q=3;q>0;q--){
                if (tv[q] > tv[q-1] || (tv[q]==tv[q-1] && tix[q] < tix[q-1])){
                    float tmv=tv[q]; tv[q]=tv[q-1]; tv[q-1]=tmv;
                    int tmi=tix[q]; tix[q]=tix[q-1]; tix[q-1]=tmi;
                }
            }
        }
    }
    red1[tid]=lm; __syncthreads();
    for (int off=128;off>0;off>>=1){ if(tid<off) red1[tid]=fmaxf(red1[tid],red1[tid+off]); __syncthreads(); }
    float m0 = red1[0]; __syncthreads();

    float f[16]; float ls0=0.f, lst=0.f;
#pragma unroll
    for (int i=0;i<16;i++){
        int j = tid + i*256;
        float d = s[j]-m0;
        float e0 = __expf(d);
        f[i]=e0; ls0+=e0;
        lst += __expf(d*invt);
    }
    red1[tid]=ls0; red2[tid]=lst; __syncthreads();
    for (int off=128;off>0;off>>=1){
        if(tid<off){ red1[tid]+=red1[tid+off]; red2[tid]+=red2[tid+off]; }
        __syncthreads();
    }
    float inv0 = 1.0f/red1[0];
    float invsumt = 1.0f/red2[0];
    __syncthreads();

#pragma unroll
    for (int i=0;i<16;i++) srow[tid + i*256] = f[i]*inv0;

#pragma unroll
    for (int q=0;q<4;q++){ rv[tid*4+q]=tv[q]; ri[tid*4+q]=tix[q]; }
    __syncthreads();
    for (int off=128;off>0;off>>=1){
        if (tid < off){
            float a0[4], b0[4]; int ai[4], bi[4];
#pragma unroll
            for (int q=0;q<4;q++){
                a0[q]=rv[tid*4+q]; ai[q]=ri[tid*4+q];
                b0[q]=rv[(tid+off)*4+q]; bi[q]=ri[(tid+off)*4+q];
            }
            int ia=0, ib=0;
            float ov[4]; int oi[4];
#pragma unroll
            for (int q=0;q<4;q++){
                bool ta = (a0[ia] > b0[ib]) || (a0[ia]==b0[ib] && ai[ia] < bi[ib]);
                if (ta){ ov[q]=a0[ia]; oi[q]=ai[ia]; ia++; }
                else   { ov[q]=b0[ib]; oi[q]=bi[ib]; ib++; }
            }
#pragma unroll
            for (int q=0;q<4;q++){ rv[tid*4+q]=ov[q]; ri[tid*4+q]=oi[q]; }
        }
        __syncthreads();
    }

    if (tid < KSEL){
        int se = ri[tid];
        float p = __expf((s[se]-m0)*invt)*invsumt;
        pv[tid]=p;
        g_topidx[n*KSEL+tid]=se;
        g_topval[n*KSEL+tid]=p;
    }
    __syncthreads();
    float invps = 1.0f/(pv[0]+pv[1]+pv[2]+pv[3] + 1e-8f);
    int s0=ri[0], s1=ri[1], s2=ri[2], s3=ri[3];
    float w0=pv[0]*invps, w1=pv[1]*invps, w2=pv[2]*invps, w3=pv[3]*invps;
    float* prow = pwout + (size_t)n*PWY;
    for (int i=0;i<16;i++){
        int j = tid + i*256;
        float v = 0.f;
        if (j==s0) v=w0; else if (j==s1) v=w1; else if (j==s2) v=w2; else if (j==s3) v=w3;
        prow[j]=v;
    }
}

// ---------------- freq + loss + lists ----------------
__global__ __launch_bounds__(256) void freq_partial()
{
    int p = blockIdx.x*256 + threadIdx.x;
    int nbeg = blockIdx.y*256;
    float acc = 0.f;
    for (int n=nbeg; n<nbeg+256; n++)
        acc += g_scores[(size_t)n*PWY + p];
    atomicAdd(&g_freq[p], acc);
}

__global__ __launch_bounds__(256) void glbl_loss_kernel(float* __restrict__ out)
{
    __shared__ float red[256];
    int tid = threadIdx.x;
    const float invN = 1.0f/(float)N_TOK;
    float lsum = 0.f;
    for (int i=0;i<PWY/256;i++) lsum += g_freq[tid+i*256]*invN;
    red[tid]=lsum; __syncthreads();
    for (int off=128;off>0;off>>=1){ if(tid<off) red[tid]+=red[tid+off]; __syncthreads(); }
    float mean = red[0]/(float)PWY; __syncthreads();
    float lss = 0.f;
    for (int i=0;i<PWY/256;i++){
        float d = g_freq[tid+i*256]*invN - mean;
        lss += d*d;
    }
    red[tid]=lss; __syncthreads();
    for (int off=128;off>0;off>>=1){ if(tid<off) red[tid]+=red[tid+off]; __syncthreads(); }
    if (tid==0) out[0] = (float)PWY * (red[0]/(float)(PWY-1));
}

__global__ __launch_bounds__(256) void build_lists()
{
    int i = blockIdx.x*256 + threadIdx.x;
    if (i >= NPAIR) return;
    int idx = g_topidx[i];
    int pe = idx >> 8, rem = idx & 255;
    int me = rem >> 4, qe = rem & 15;
    int pos;
    pos = atomicAdd(&g_cnt[pe], 1);         g_list[pe*NPAIR + pos] = i;
    pos = atomicAdd(&g_cnt[NE+me], 1);      g_list[(NE+me)*NPAIR + pos] = i;
    pos = atomicAdd(&g_cnt[2*NE+qe], 1);    g_list[(2*NE+qe)*NPAIR + pos] = i;
}

// ---------------- host launch ----------------
extern "C" void kernel_launch(void* const* d_in, const int* in_sizes, int n_in,
                              void* d_out, int out_size)
{
    const float* x   = (const float*)d_in[0];
    const float* rw1 = (const float*)d_in[1];
    const float* rb1 = (const float*)d_in[2];
    const float* rw2 = (const float*)d_in[3];
    const float* rb2 = (const float*)d_in[4];
    const float* rw3 = (const float*)d_in[5];
    const float* rb3 = (const float*)d_in[6];
    const float* temp= (const float*)d_in[7];
    const float* pw  = (const float*)d_in[8];
    const float* pb  = (const float*)d_in[9];
    const float* pg  = (const float*)d_in[10];
    const float* pbb = (const float*)d_in[11];
    const float* mw1 = (const float*)d_in[12];
    const float* mb1 = (const float*)d_in[13];
    const float* mw2 = (const float*)d_in[14];
    const float* mb2 = (const float*)d_in[15];
    const float* qw  = (const float*)d_in[16];
    const float* qb  = (const float*)d_in[17];
    const float* qg  = (const float*)d_in[18];
    const float* qbb = (const float*)d_in[19];

    float* out      = (float*)d_out;
    float* out_y    = out;
    float* out_loss = out + N_TOK*DM;
    float* out_pw   = out + N_TOK*DM + 1;

    void* p;
    cudaGetSymbolAddress(&p, g_scores); float* scores = (float*)p;
    cudaGetSymbolAddress(&p, g_freq);   float* freqp = (float*)p;
    cudaGetSymbolAddress(&p, g_cnt);    int*   cntp = (int*)p;
    cudaGetSymbolAddress(&p, g_pre0);   float* pre0 = (float*)p;
    cudaGetSymbolAddress(&p, g_post0);  float* post0 = (float*)p;
    cudaGetSymbolAddress(&p, g_xh);     bf16* xh = (bf16*)p;
    cudaGetSymbolAddress(&p, g_xl);     bf16* xl = (bf16*)p;
    cudaGetSymbolAddress(&p, g_h1h);    bf16* h1h = (bf16*)p;
    cudaGetSymbolAddress(&p, g_h1l);    bf16* h1l = (bf16*)p;
    cudaGetSymbolAddress(&p, g_h2h);    bf16* h2h = (bf16*)p;
    cudaGetSymbolAddress(&p, g_h2l);    bf16* h2l = (bf16*)p;
    cudaGetSymbolAddress(&p, g_xpreh);  bf16* xpreh = (bf16*)p;
    cudaGetSymbolAddress(&p, g_xprel);  bf16* xprel = (bf16*)p;
    cudaGetSymbolAddress(&p, g_xmidh);  bf16* xmidh = (bf16*)p;
    cudaGetSymbolAddress(&p, g_xmidl);  bf16* xmidl = (bf16*)p;
    cudaGetSymbolAddress(&p, g_xmlph);  bf16* xmlph = (bf16*)p;
    cudaGetSymbolAddress(&p, g_xmlpl);  bf16* xmlpl = (bf16*)p;
    cudaGetSymbolAddress(&p, g_rw1h);   bf16* rw1h = (bf16*)p;
    cudaGetSymbolAddress(&p, g_rw1l);   bf16* rw1l = (bf16*)p;
    cudaGetSymbolAddress(&p, g_rw2h);   bf16* rw2h = (bf16*)p;
    cudaGetSymbolAddress(&p, g_rw2l);   bf16* rw2l = (bf16*)p;
    cudaGetSymbolAddress(&p, g_rw3h);   bf16* rw3h = (bf16*)p;
    cudaGetSymbolAddress(&p, g_rw3l);   bf16* rw3l = (bf16*)p;
    cudaGetSymbolAddress(&p, g_pwh);    bf16* pwh = (bf16*)p;
    cudaGetSymbolAddress(&p, g_pwl);    bf16* pwl = (bf16*)p;
    cudaGetSymbolAddress(&p, g_m1h);    bf16* m1h = (bf16*)p;
    cudaGetSymbolAddress(&p, g_m1l);    bf16* m1l = (bf16*)p;
    cudaGetSymbolAddress(&p, g_m2h);    bf16* m2h = (bf16*)p;
    cudaGetSymbolAddress(&p, g_m2l);    bf16* m2l = (bf16*)p;
    cudaGetSymbolAddress(&p, g_qwh);    bf16* qwh = (bf16*)p;
    cudaGetSymbolAddress(&p, g_qwl);    bf16* qwl = (bf16*)p;

    cudaFuncSetAttribute(gemm_bf16, cudaFuncAttributeMaxDynamicSharedMemorySize, SMEM_GEMM_BYTES);

    // router weight convert + split x + router chain first (ncu -s 5 lands on a gemm)
    convt<<<dim3(256/32, 256/32, 1), 256>>>(rw1, rw1h, rw1l, 256, 256, 0LL, 0LL);
    convt<<<dim3(128/32, 256/32, 1), 256>>>(rw2, rw2h, rw2l, 256, 128, 0LL, 0LL);
    convt<<<dim3(PWY/32, 128/32, 1), 256>>>(rw3, rw3h, rw3l, 128, PWY, 0LL, 0LL);
    split_x<<<N_TOK*DM/(256*8), 256>>>(x);

    gemm_bf16<<<dim3(2, N_TOK/128, 1), 256, SMEM_GEMM_BYTES>>>(
        xh, xl, DM, rw1h, rw1l, 256, 0LL, rb1, 0,
        0, h1h, h1l, 256, 256, 0, 0, 1, -1, 0, 1);
    gemm_bf16<<<dim3(1, N_TOK/128, 1), 256, SMEM_GEMM_BYTES>>>(
        h1h, h1l, 256, rw2h, rw2l, 256, 0LL, rb2, 0,
        0, h2h, h2l, 128, 256, 0, 0, 1, -1, 0, 1);
    gemm_bf16<<<dim3(PWY/128, N_TOK/128, 1), 256, SMEM_GEMM_BYTES>>>(
        h2h, h2l, 128, rw3h, rw3l, 128, 0LL, rb3, 0,
        scores, 0, 0, PWY, 128, 0, 0, 0, -1, 0, 0);

    softmax_topk<<<N_TOK, 256>>>(temp, out_pw);

    // memsets + expert weight conversion (after router; dependencies satisfied)
    cudaMemsetAsync(freqp, 0, PWY*sizeof(float), 0);
    cudaMemsetAsync(cntp,  0, 3*NE*sizeof(int), 0);
    convt<<<dim3(DM/32, DM/32, NE), 256>>>(pw, pwh, pwl, DM, DM,
        (long long)DM*DM, (long long)DM*DM);
    convt<<<dim3(HMAX/32, DM/32, NE), 256>>>(mw1, m1h, m1l, DM, HMAX,
        (long long)DM*HMAX, (long long)HMAX*DM);
    convt<<<dim3(DM/32, HMAX/32, NE), 256>>>(mw2, m2h, m2l, HMAX, DM,
        (long long)HMAX*DM, (long long)DM*HMAX);
    convt<<<dim3(DM/32, DM/32, NE), 256>>>(qw, qwh, qwl, DM, DM,
        (long long)DM*DM, (long long)DM*DM);

    // GLBL loss
    freq_partial<<<dim3(PWY/256, N_TOK/256), 256>>>();
    glbl_loss_kernel<<<1, 256>>>(out_loss);

    // routing
    build_lists<<<NPAIR/256, 256>>>();

    // pre experts: gemm -> LN epilogue
    gemm_bf16<<<dim3(DM/128, NPAIR/128, NE), 256, SMEM_GEMM_BYTES>>>(
        xh, xl, DM, pwh, pwl, DM, (long long)DM*DM, pb, DM,
        pre0, 0, 0, DM, DM, 0, 0, 0, 0, 2, 0);
    epil_pre<<<NPAIR/8, 256>>>(pg, pbb);

    // mlp experts
    gemm_bf16<<<dim3(HMAX/128, NPAIR/128, NE), 256, SMEM_GEMM_BYTES>>>(
        xpreh, xprel, DM, m1h, m1l, DM, (long long)HMAX*DM, mb1, HMAX,
        0, xmidh, xmidl, HMAX, DM, 0, 1, 3, NE, 0, 1);
    gemm_bf16<<<dim3(DM/128, NPAIR/128, NE), 256, SMEM_GEMM_BYTES>>>(
        xmidh, xmidl, HMAX, m2h, m2l, HMAX, (long long)DM*HMAX, mb2, DM,
        0, xmlph, xmlpl, DM, 0, 1, 0, 0, NE, 0, 1);

    // post experts: gemm -> warp-per-token LN + weighted sum (no atomics, no out_y memset)
    gemm_bf16<<<dim3(DM/128, NPAIR/128, NE), 256, SMEM_GEMM_BYTES>>>(
        xmlph, xmlpl, DM, qwh, qwl, DM, (long long)DM*DM, qb, DM,
        post0, 0, 0, DM, DM, 0, 0, 0, 2*NE, 0, 0);
    epil_post<<<N_TOK/8, 256>>>(qg, qbb, out_y);
}

// round 14
// speedup vs baseline: 1.4616x; 1.1150x over previous
#include <cuda_runtime.h>
#include <cuda_bf16.h>
#include <cuda_fp16.h>
#include <cstdint>
#include <math.h>

#define N_TOK 2048
#define DM 256
#define PWY 4096
#define KSEL 4
#define NE 16
#define HMAX 1280
#define NPAIR (N_TOK*KSEL)

typedef unsigned long long u64;
typedef unsigned int uint32;
typedef __nv_bfloat16 bf16;
typedef __nv_bfloat162 bf162;

#define MMA_BF16(d, a0,a1,a2,a3, b0,b1) \
  asm volatile("mma.sync.aligned.m16n8k16.row.col.f32.bf16.bf16.f32 " \
    "{%0,%1,%2,%3}, {%4,%5,%6,%7}, {%8,%9}, {%0,%1,%2,%3};" \
    : "+f"(d[0]),"+f"(d[1]),"+f"(d[2]),"+f"(d[3]) \
    : "r"(a0),"r"(a1),"r"(a2),"r"(a3),"r"(b0),"r"(b1))

#define MMA_F16(d, a0,a1,a2,a3, b0,b1) \
  asm volatile("mma.sync.aligned.m16n8k16.row.col.f32.f16.f16.f32 " \
    "{%0,%1,%2,%3}, {%4,%5,%6,%7}, {%8,%9}, {%0,%1,%2,%3};" \
    : "+f"(d[0]),"+f"(d[1]),"+f"(d[2]),"+f"(d[3]) \
    : "r"(a0),"r"(a1),"r"(a2),"r"(a3),"r"(b0),"r"(b1))

#define LDSM_X4(r0,r1,r2,r3,addr) \
  asm volatile("ldmatrix.sync.aligned.m8n8.x4.shared.b16 {%0,%1,%2,%3}, [%4];" \
    : "=r"(r0),"=r"(r1),"=r"(r2),"=r"(r3) : "r"(addr))
#define LDSM_X2(r0,r1,addr) \
  asm volatile("ldmatrix.sync.aligned.m8n8.x2.shared.b16 {%0,%1}, [%2];" \
    : "=r"(r0),"=r"(r1) : "r"(addr))

#define CP16(dst, src) \
  asm volatile("cp.async.ca.shared.global [%0], [%1], 16;" :: "r"(dst), "l"(src))
#define CP16_Z(dst, src) \
  asm volatile("cp.async.ca.shared.global [%0], [%1], 16, 0;" :: "r"(dst), "l"(src))
#define CP_COMMIT() asm volatile("cp.async.commit_group;" ::: "memory")
#define CP_WAIT1()  asm volatile("cp.async.wait_group 1;" ::: "memory")
#define CP_WAIT0()  asm volatile("cp.async.wait_group 0;" ::: "memory")

__device__ __forceinline__ uint32 smem_u32(const void* p){
    uint32 a;
    asm("{ .reg .u64 t; cvta.to.shared.u64 t, %1; cvt.u32.u64 %0, t; }" : "=r"(a) : "l"(p));
    return a;
}

// ---------------- device scratch (static, no allocation) ----------------
__device__ float g_scores[N_TOK*PWY];
__device__ float g_freq[PWY];
__device__ int   g_topidx[NPAIR];
__device__ float g_topval[NPAIR];
__device__ int   g_cnt[3*NE];
__device__ int   g_list[3*NE*NPAIR];
__device__ float g_pre0[NPAIR*DM];
__device__ float g_post0[NPAIR*DM];
// split 16-bit activations (bf16 or fp16 bits depending on stage)
__device__ bf16 g_xh[N_TOK*DM],    g_xl[N_TOK*DM];
__device__ bf16 g_h1h[N_TOK*256],  g_h1l[N_TOK*256];
__device__ bf16 g_h2h[N_TOK*128],  g_h2l[N_TOK*128];
__device__ bf16 g_xpreh[NPAIR*DM], g_xprel[NPAIR*DM];          // fp16 bits
__device__ bf16 g_xmidh[(size_t)NPAIR*HMAX], g_xmidl[(size_t)NPAIR*HMAX];  // fp16 bits
__device__ bf16 g_xmlph[NPAIR*DM], g_xmlpl[NPAIR*DM];          // bf16
// split 16-bit transposed weights: WT[n][k]
__device__ bf16 g_rw1h[256*256],  g_rw1l[256*256];
__device__ bf16 g_rw2h[128*256],  g_rw2l[128*256];
__device__ bf16 g_rw3h[PWY*128],  g_rw3l[PWY*128];
__device__ bf16 g_pwh[NE*DM*DM],  g_pwl[NE*DM*DM];
__device__ bf16 g_m1h[NE*HMAX*DM], g_m1l[NE*HMAX*DM];          // fp16 bits (high only)
__device__ bf16 g_m2h[NE*DM*HMAX], g_m2l[NE*DM*HMAX];          // fp16 bits (high only)
__device__ bf16 g_qwh[NE*DM*DM],  g_qwl[NE*DM*DM];

__device__ __forceinline__ float geluf(float v){
    return 0.5f*v*(1.0f+erff(v*0.70710678118654752f));
}

// ---------------- weight convert + transpose (fmt 0: bf16 hi/lo; 1: fp16 high only) --------
__global__ __launch_bounds__(256) void convt(
    const float* __restrict__ W, bf16* __restrict__ Th,
    bf16* __restrict__ Tl, int R, int C,
    long long wstride, long long tstride, int fmt)
{
    int e = blockIdx.z;
    __shared__ float tile[32][33];
    int c0 = blockIdx.x*32, r0 = blockIdx.y*32;
    const float* Win = W + (size_t)e*wstride;
    int tx = threadIdx.x & 31, ty = threadIdx.x >> 5;
    for (int i=0;i<32;i+=8)
        tile[ty+i][tx] = Win[(size_t)(r0+ty+i)*C + c0+tx];
    __syncthreads();
    bf16* oh = Th + (size_t)e*tstride;
    bf16* ol = Tl + (size_t)e*tstride;
    for (int i=0;i<32;i+=8){
        float v = tile[tx][ty+i];
        size_t o = (size_t)(c0+ty+i)*R + r0+tx;
        if (fmt==0){
            bf16 h = __float2bfloat16(v);
            oh[o] = h;
            ol[o] = __float2bfloat16(v - __bfloat162float(h));
        } else {
            ((__half*)oh)[o] = __float2half(v);
        }
    }
}

// ---------------- split x (bf16) ----------------
__global__ __launch_bounds__(256) void split_x(const float* __restrict__ x)
{
    int idx = (blockIdx.x*256 + threadIdx.x)*8;
    float4 v0 = *(const float4*)&x[idx];
    float4 v1 = *(const float4*)&x[idx+4];
    float v[8] = {v0.x,v0.y,v0.z,v0.w,v1.x,v1.y,v1.z,v1.w};
    bf162* dh = (bf162*)&g_xh[idx];
    bf162* dl = (bf162*)&g_xl[idx];
#pragma unroll
    for (int j=0;j<4;j++){
        bf16 h0 = __float2bfloat16(v[2*j]);
        bf16 h1 = __float2bfloat16(v[2*j+1]);
        bf16 l0 = __float2bfloat16(v[2*j]   - __bfloat162float(h0));
        bf16 l1 = __float2bfloat16(v[2*j+1] - __bfloat162float(h1));
        dh[j] = __halves2bfloat162(h0,h1);
        dl[j] = __halves2bfloat162(l0,l1);
    }
}

// ---------------- split 16-bit mma.sync GEMM: 128x128, 8 warps, cp.async 2-buf, ldmatrix ----
// F16=0: bf16, 3 MMAs (Ah·Bh + Ah·Bl + Al·Bh). F16=1: fp16, 2 MMAs (Ah·Bh + Al·Bh), no Bl.
// osplit: 0 = fp32 out, 1 = bf16 hi/lo out, 2 = fp16 hi/lo out.
#define SEG 10240
#define AHo 0
#define ALo SEG
#define BHo (2*SEG)
#define BLo (3*SEG)
#define BUF_E 5120
#define SMEM_GEMM_BYTES (4*SEG*2)

template<int F16>
__global__ __launch_bounds__(256,2) void gemm_t(
    const bf16* __restrict__ Ahg, const bf16* __restrict__ Alg, int lda,
    const bf16* __restrict__ Wth, const bf16* __restrict__ Wtl,
    int Kw, long long wse,
    const float* __restrict__ bias, int bse,
    float* __restrict__ Cf, bf16* __restrict__ Chp, bf16* __restrict__ Clp,
    int ldc, int Kfix, int kvar, int nvar, int act, int listoff, int ashift, int osplit)
{
    extern __shared__ bf16 S[];
    int e = blockIdx.z;
    int hid = DM*(2 + (e>>2));
    int K = kvar ? hid : Kfix;
    int n0 = blockIdx.x*128;
    if (nvar && n0 >= hid) return;
    int m0 = blockIdx.y*128;
    const int* list = 0; int cnt = 0;
    if (listoff >= 0){
        cnt = g_cnt[listoff+e];
        if (m0 >= cnt) return;
        list = g_list + (size_t)(listoff+e)*NPAIR;
    }
    __shared__ int pairs[128];
    int tid = threadIdx.x;
    if (tid < 128)
        pairs[tid] = (listoff>=0) ? ((m0+tid < cnt) ? list[m0+tid] : -1) : (m0+tid);
    __syncthreads();

    int arow = tid >> 1;
    int half = (tid & 1) * 16;
    int prA = pairs[arow];
    bool avalid = (prA>=0);
    const bf16* Ahp = avalid ? (Ahg + (size_t)(prA>>ashift)*lda) : Ahg;
    const bf16* Alp = avalid ? (Alg + (size_t)(prA>>ashift)*lda) : Alg;
    const bf16* Bhp = Wth + (size_t)e*wse + (size_t)(n0+arow)*Kw;
    const bf16* Blp = Wtl + (size_t)e*wse + (size_t)(n0+arow)*Kw;

    uint32 Sb = smem_u32(S);
    uint32 dAh = Sb + 2*(AHo + arow*40 + half);
    uint32 dAl = Sb + 2*(ALo + arow*40 + half);
    uint32 dBh = Sb + 2*(BHo + arow*40 + half);
    uint32 dBl = Sb + 2*(BLo + arow*40 + half);
    const uint32 bufB = BUF_E*2;

    auto issue = [&](int c){
        uint32 bo = (c&1) ? bufB : 0;
#pragma unroll
        for (int j=0;j<2;j++){
            if (avalid){
                CP16(dAh + bo + j*16, Ahp + c*32 + half + j*8);
                CP16(dAl + bo + j*16, Alp + c*32 + half + j*8);
            } else {
                CP16_Z(dAh + bo + j*16, Ahp);
                CP16_Z(dAl + bo + j*16, Alp);
            }
            CP16(dBh + bo + j*16, Bhp + c*32 + half + j*8);
            if (!F16) CP16(dBl + bo + j*16, Blp + c*32 + half + j*8);
        }
    };

    int lane = tid & 31, wid = tid >> 5;
    int wm = wid >> 2, wn = wid & 3;
    int qr = lane >> 2, qc = lane & 3;
    int al_r = lane & 15, al_c = (lane >> 4) * 8;
    int bl_r = lane & 7,  bl_c = ((lane >> 3) & 1) * 8;

    float acc[4][4][4];
#pragma unroll
    for (int i=0;i<4;i++)
#pragma unroll
    for (int j=0;j<4;j++)
#pragma unroll
    for (int q=0;q<4;q++) acc[i][j][q]=0.f;

    int nchunks = K/32;
    issue(0); CP_COMMIT();
    for (int c=0;c<nchunks;c++){
        if (c+1 < nchunks){ issue(c+1); CP_COMMIT(); CP_WAIT1(); }
        else { CP_WAIT0(); }
        __syncthreads();
        int boE = (c&1) ? BUF_E : 0;
#pragma unroll
        for (int k16=0;k16<32;k16+=16){
            uint32 bh[4][2], bl4[4][2];
#pragma unroll
            for (int nf=0;nf<4;nf++){
                int brow = wn*32 + nf*8 + bl_r;
                uint32 abh = Sb + 2*(BHo + boE + brow*40 + k16 + bl_c);
                LDSM_X2(bh[nf][0], bh[nf][1], abh);
                if (!F16){
                    uint32 abl = Sb + 2*(BLo + boE + brow*40 + k16 + bl_c);
                    LDSM_X2(bl4[nf][0], bl4[nf][1], abl);
                }
            }
#pragma unroll
            for (int mf=0;mf<4;mf++){
                int ar = wm*64 + mf*16 + al_r;
                uint32 aah = Sb + 2*(AHo + boE + ar*40 + k16 + al_c);
                uint32 aal = Sb + 2*(ALo + boE + ar*40 + k16 + al_c);
                uint32 ah0,ah1,ah2,ah3, al0,al1,al2,al3;
                LDSM_X4(ah0,ah1,ah2,ah3, aah);
                LDSM_X4(al0,al1,al2,al3, aal);
#pragma unroll
                for (int nf=0;nf<4;nf++){
                    if (F16){
                        MMA_F16(acc[mf][nf], ah0,ah1,ah2,ah3, bh[nf][0],bh[nf][1]);
                        MMA_F16(acc[mf][nf], al0,al1,al2,al3, bh[nf][0],bh[nf][1]);
                    } else {
                        MMA_BF16(acc[mf][nf], ah0,ah1,ah2,ah3, bh[nf][0],bh[nf][1]);
                        MMA_BF16(acc[mf][nf], ah0,ah1,ah2,ah3, bl4[nf][0],bl4[nf][1]);
                        MMA_BF16(acc[mf][nf], al0,al1,al2,al3, bh[nf][0],bh[nf][1]);
                    }
                }
            }
        }
        __syncthreads();
    }

    bool relu_e = (act==3) && (e&1);
#pragma unroll
    for (int mf=0;mf<4;mf++){
        int r0 = wm*64 + mf*16 + qr;
        int r1 = r0 + 8;
        int pr0 = pairs[r0], pr1 = pairs[r1];
#pragma unroll
        for (int nf=0;nf<4;nf++){
            int n = n0 + wn*32 + nf*8 + qc*2;
            float b0 = bias[(size_t)e*bse + n];
            float b1 = bias[(size_t)e*bse + n + 1];
            float v00 = acc[mf][nf][0] + b0, v01 = acc[mf][nf][1] + b1;
            float v10 = acc[mf][nf][2] + b0, v11 = acc[mf][nf][3] + b1;
            if (act==1){
                v00=geluf(v00); v01=geluf(v01); v10=geluf(v10); v11=geluf(v11);
            } else if (act==3){
                if (relu_e){
                    v00=fmaxf(v00,0.f); v01=fmaxf(v01,0.f);
                    v10=fmaxf(v10,0.f); v11=fmaxf(v11,0.f);
                } else {
                    v00=geluf(v00); v01=geluf(v01);
                    v10=geluf(v10); v11=geluf(v11);
                }
            }
            if (osplit==1){
                if (pr0>=0){
                    bf16 h0=__float2bfloat16(v00), h1=__float2bfloat16(v01);
                    bf16 l0=__float2bfloat16(v00-__bfloat162float(h0));
                    bf16 l1=__float2bfloat16(v01-__bfloat162float(h1));
                    *(bf162*)&Chp[(size_t)pr0*ldc + n] = __halves2bfloat162(h0,h1);
                    *(bf162*)&Clp[(size_t)pr0*ldc + n] = __halves2bfloat162(l0,l1);
                }
                if (pr1>=0){
                    bf16 h0=__float2bfloat16(v10), h1=__float2bfloat16(v11);
                    bf16 l0=__float2bfloat16(v10-__bfloat162float(h0));
                    bf16 l1=__float2bfloat16(v11-__bfloat162float(h1));
                    *(bf162*)&Chp[(size_t)pr1*ldc + n] = __halves2bfloat162(h0,h1);
                    *(bf162*)&Clp[(size_t)pr1*ldc + n] = __halves2bfloat162(l0,l1);
                }
            } else if (osplit==2){
                if (pr0>=0){
                    __half h0=__float2half(v00), h1=__float2half(v01);
                    __half l0=__float2half(v00-__half2float(h0));
                    __half l1=__float2half(v01-__half2float(h1));
                    *(__half2*)&Chp[(size_t)pr0*ldc + n] = __halves2half2(h0,h1);
                    *(__half2*)&Clp[(size_t)pr0*ldc + n] = __halves2half2(l0,l1);
                }
                if (pr1>=0){
                    __half h0=__float2half(v10), h1=__float2half(v11);
                    __half l0=__float2half(v10-__half2float(h0));
                    __half l1=__float2half(v11-__half2float(h1));
                    *(__half2*)&Chp[(size_t)pr1*ldc + n] = __halves2half2(h0,h1);
                    *(__half2*)&Clp[(size_t)pr1*ldc + n] = __halves2half2(l0,l1);
                }
            } else {
                if (pr0>=0) *(float2*)&Cf[(size_t)pr0*ldc + n] = make_float2(v00,v01);
                if (pr1>=0) *(float2*)&Cf[(size_t)pr1*ldc + n] = make_float2(v10,v11);
            }
        }
    }
}

// ---------------- pre epilogue: LN + act, writes split fp16 (mlp1 is fp16) ----------------
__global__ __launch_bounds__(256) void epil_pre(
    const float* __restrict__ pg, const float* __restrict__ pbb)
{
    int i = blockIdx.x*8 + (threadIdx.x>>5);
    int lane = threadIdx.x & 31;
    int e = g_topidx[i] >> 8;
    const float* row = g_pre0 + (size_t)i*DM;
    float y[8];
    float4 v0 = *(const float4*)&row[lane*8];
    float4 v1 = *(const float4*)&row[lane*8+4];
    y[0]=v0.x;y[1]=v0.y;y[2]=v0.z;y[3]=v0.w;y[4]=v1.x;y[5]=v1.y;y[6]=v1.z;y[7]=v1.w;
    float s = y[0]+y[1]+y[2]+y[3]+y[4]+y[5]+y[6]+y[7];
#pragma unroll
    for (int m=16;m>0;m>>=1) s += __shfl_xor_sync(0xffffffffu, s, m, 32);
    float mu = s * (1.0f/DM);
    float ss = 0.f;
#pragma unroll
    for (int j=0;j<8;j++){ float d=y[j]-mu; ss += d*d; }
#pragma unroll
    for (int m=16;m>0;m>>=1) ss += __shfl_xor_sync(0xffffffffu, ss, m, 32);
    float rstd = rsqrtf(ss*(1.0f/DM) + 1e-5f);
    int actm = e % 3;
    __half2* dh = (__half2*)&g_xpreh[(size_t)i*DM + lane*8];
    __half2* dl = (__half2*)&g_xprel[(size_t)i*DM + lane*8];
#pragma unroll
    for (int j=0;j<4;j++){
        float o[2];
#pragma unroll
        for (int q=0;q<2;q++){
            int c = lane*8 + 2*j + q;
            float v = (y[2*j+q]-mu)*rstd*pg[e*DM+c] + pbb[e*DM+c];
            o[q] = (actm==0) ? geluf(v) : (actm==1) ? fmaxf(v,0.f) : tanhf(v);
        }
        __half h0=__float2half(o[0]), h1=__float2half(o[1]);
        __half l0=__float2half(o[0]-__half2float(h0));
        __half l1=__float2half(o[1]-__half2float(h1));
        dh[j] = __halves2half2(h0,h1);
        dl[j] = __halves2half2(l0,l1);
    }
}

// ---------------- post epilogue: warp-per-token, LN + weighted sum, no atomics -------------
__global__ __launch_bounds__(256) void epil_post(
    const float* __restrict__ qg, const float* __restrict__ qbb,
    float* __restrict__ out_y)
{
    int tok = blockIdx.x*8 + (threadIdx.x>>5);
    int lane = threadIdx.x & 31;
    float acc[8] = {0.f,0.f,0.f,0.f,0.f,0.f,0.f,0.f};
#pragma unroll
    for (int slot=0; slot<KSEL; slot++){
        int i = tok*KSEL + slot;
        int e = g_topidx[i] & 15;
        const float* row = g_post0 + (size_t)i*DM;
        float y[8];
        float4 v0 = *(const float4*)&row[lane*8];
        float4 v1 = *(const float4*)&row[lane*8+4];
        y[0]=v0.x;y[1]=v0.y;y[2]=v0.z;y[3]=v0.w;y[4]=v1.x;y[5]=v1.y;y[6]=v1.z;y[7]=v1.w;
        if ((e & 1) == 0){
            float s = y[0]+y[1]+y[2]+y[3]+y[4]+y[5]+y[6]+y[7];
#pragma unroll
            for (int m=16;m>0;m>>=1) s += __shfl_xor_sync(0xffffffffu, s, m, 32);
            float mu = s * (1.0f/DM);
            float ss = 0.f;
#pragma unroll
            for (int j=0;j<8;j++){ float d=y[j]-mu; ss += d*d; }
#pragma unroll
            for (int m=16;m>0;m>>=1) ss += __shfl_xor_sync(0xffffffffu, ss, m, 32);
            float rstd = rsqrtf(ss*(1.0f/DM) + 1e-5f);
#pragma unroll
            for (int j=0;j<8;j++){
                int c = lane*8 + j;
                y[j] = (y[j]-mu)*rstd*qg[e*DM+c] + qbb[e*DM+c];
            }
        }
        float w = g_topval[i];
#pragma unroll
        for (int j=0;j<8;j++) acc[j] += y[j]*w;
    }
    float* orow = out_y + (size_t)tok*DM + lane*8;
    *(float4*)&orow[0] = make_float4(acc[0],acc[1],acc[2],acc[3]);
    *(float4*)&orow[4] = make_float4(acc[4],acc[5],acc[6],acc[7]);
}

// ---------------- softmax + topk (validated smem-tree version) ----------------
__global__ __launch_bounds__(256) void softmax_topk(
    const float* __restrict__ temp, float* __restrict__ pwout)
{
    __shared__ float s[PWY];
    __shared__ float rv[256*4];
    __shared__ int   ri[256*4];
    __shared__ float red1[256];
    __shared__ float red2[256];
    __shared__ float pv[KSEL];
    int n = blockIdx.x, tid = threadIdx.x;
    float* srow = g_scores + (size_t)n*PWY;
    for (int i=0;i<4;i++){
        int idx = i*1024 + tid*4;
        *(float4*)&s[idx] = *(const float4*)&srow[idx];
    }
    __syncthreads();
    float invt = 1.0f/temp[0];

    float tv[4] = {-INFINITY,-INFINITY,-INFINITY,-INFINITY};
    int tix[4] = {PWY,PWY,PWY,PWY};
    float lm = -INFINITY;
#pragma unroll
    for (int i=0;i<16;i++){
        int j = tid + i*256;
        float v = s[j];
        lm = fmaxf(lm, v);
        if (v > tv[3] || (v == tv[3] && j < tix[3])){
            tv[3]=v; tix[3]=j;
#pragma unroll
            for (int q=3;q>0;q--){
                if (tv[q] > tv[q-1] || (tv[q]==tv[q-1] && tix[q] < tix[q-1])){
                    float tmv=tv[q]; tv[q]=tv[q-1]; tv[q-1]=tmv;
                    int tmi=tix[q]; tix[q]=tix[q-1]; tix[q-1]=tmi;
                }
            }
        }
    }
    red1[tid]=lm; __syncthreads();
    for (int off=128;off>0;off>>=1){ if(tid<off) red1[tid]=fmaxf(red1[tid],red1[tid+off]); __syncthreads(); }
    float m0 = red1[0]; __syncthreads();

    float f[16]; float ls0=0.f, lst=0.f;
#pragma unroll
    for (int i=0;i<16;i++){
        int j = tid + i*256;
        float d = s[j]-m0;
        float e0 = __expf(d);
        f[i]=e0; ls0+=e0;
        lst += __expf(d*invt);
    }
    red1[tid]=ls0; red2[tid]=lst; __syncthreads();
    for (int off=128;off>0;off>>=1){
        if(tid<off){ red1[tid]+=red1[tid+off]; red2[tid]+=red2[tid+off]; }
        __syncthreads();
    }
    float inv0 = 1.0f/red1[0];
    float invsumt = 1.0f/red2[0];
    __syncthreads();

#pragma unroll
    for (int i=0;i<16;i++) srow[tid + i*256] = f[i]*inv0;

#pragma unroll
    for (int q=0;q<4;q++){ rv[tid*4+q]=tv[q]; ri[tid*4+q]=tix[q]; }
    __syncthreads();
    for (int off=128;off>0;off>>=1){
        if (tid < off){
            float a0[4], b0[4]; int ai[4], bi[4];
#pragma unroll
            for (int q=0;q<4;q++){
                a0[q]=rv[tid*4+q]; ai[q]=ri[tid*4+q];
                b0[q]=rv[(tid+off)*4+q]; bi[q]=ri[(tid+off)*4+q];
            }
            int ia=0, ib=0;
            float ov[4]; int oi[4];
#pragma unroll
            for (int q=0;q<4;q++){
                bool ta = (a0[ia] > b0[ib]) || (a0[ia]==b0[ib] && ai[ia] < bi[ib]);
                if (ta){ ov[q]=a0[ia]; oi[q]=ai[ia]; ia++; }
                else   { ov[q]=b0[ib]; oi[q]=bi[ib]; ib++; }
            }
#pragma unroll
            for (int q=0;q<4;q++){ rv[tid*4+q]=ov[q]; ri[tid*4+q]=oi[q]; }
        }
        __syncthreads();
    }

    if (tid < KSEL){
        int se = ri[tid];
        float p = __expf((s[se]-m0)*invt)*invsumt;
        pv[tid]=p;
        g_topidx[n*KSEL+tid]=se;
        g_topval[n*KSEL+tid]=p;
    }
    __syncthreads();
    float invps = 1.0f/(pv[0]+pv[1]+pv[2]+pv[3] + 1e-8f);
    int s0=ri[0], s1=ri[1], s2=ri[2], s3=ri[3];
    float w0=pv[0]*invps, w1=pv[1]*invps, w2=pv[2]*invps, w3=pv[3]*invps;
    float* prow = pwout + (size_t)n*PWY;
    for (int i=0;i<16;i++){
        int j = tid + i*256;
        float v = 0.f;
        if (j==s0) v=w0; else if (j==s1) v=w1; else if (j==s2) v=w2; else if (j==s3) v=w3;
        prow[j]=v;
    }
}

// ---------------- freq + loss + lists ----------------
__global__ __launch_bounds__(256) void freq_partial()
{
    int p = blockIdx.x*256 + threadIdx.x;
    int nbeg = blockIdx.y*256;
    float acc = 0.f;
    for (int n=nbeg; n<nbeg+256; n++)
        acc += g_scores[(size_t)n*PWY + p];
    atomicAdd(&g_freq[p], acc);
}

__global__ __launch_bounds__(256) void glbl_loss_kernel(float* __restrict__ out)
{
    __shared__ float red[256];
    int tid = threadIdx.x;
    const float invN = 1.0f/(float)N_TOK;
    float lsum = 0.f;
    for (int i=0;i<PWY/256;i++) lsum += g_freq[tid+i*256]*invN;
    red[tid]=lsum; __syncthreads();
    for (int off=128;off>0;off>>=1){ if(tid<off) red[tid]+=red[tid+off]; __syncthreads(); }
    float mean = red[0]/(float)PWY; __syncthreads();
    float lss = 0.f;
    for (int i=0;i<PWY/256;i++){
        float d = g_freq[tid+i*256]*invN - mean;
        lss += d*d;
    }
    red[tid]=lss; __syncthreads();
    for (int off=128;off>0;off>>=1){ if(tid<off) red[tid]+=red[tid+off]; __syncthreads(); }
    if (tid==0) out[0] = (float)PWY * (red[0]/(float)(PWY-1));
}

__global__ __launch_bounds__(256) void build_lists()
{
    int i = blockIdx.x*256 + threadIdx.x;
    if (i >= NPAIR) return;
    int idx = g_topidx[i];
    int pe = idx >> 8, rem = idx & 255;
    int me = rem >> 4, qe = rem & 15;
    int pos;
    pos = atomicAdd(&g_cnt[pe], 1);         g_list[pe*NPAIR + pos] = i;
    pos = atomicAdd(&g_cnt[NE+me], 1);      g_list[(NE+me)*NPAIR + pos] = i;
    pos = atomicAdd(&g_cnt[2*NE+qe], 1);    g_list[(2*NE+qe)*NPAIR + pos] = i;
}

// ---------------- host launch ----------------
extern "C" void kernel_launch(void* const* d_in, const int* in_sizes, int n_in,
                              void* d_out, int out_size)
{
    const float* x   = (const float*)d_in[0];
    const float* rw1 = (const float*)d_in[1];
    const float* rb1 = (const float*)d_in[2];
    const float* rw2 = (const float*)d_in[3];
    const float* rb2 = (const float*)d_in[4];
    const float* rw3 = (const float*)d_in[5];
    const float* rb3 = (const float*)d_in[6];
    const float* temp= (const float*)d_in[7];
    const float* pw  = (const float*)d_in[8];
    const float* pb  = (const float*)d_in[9];
    const float* pg  = (const float*)d_in[10];
    const float* pbb = (const float*)d_in[11];
    const float* mw1 = (const float*)d_in[12];
    const float* mb1 = (const float*)d_in[13];
    const float* mw2 = (const float*)d_in[14];
    const float* mb2 = (const float*)d_in[15];
    const float* qw  = (const float*)d_in[16];
    const float* qb  = (const float*)d_in[17];
    const float* qg  = (const float*)d_in[18];
    const float* qbb = (const float*)d_in[19];

    float* out      = (float*)d_out;
    float* out_y    = out;
    float* out_loss = out + N_TOK*DM;
    float* out_pw   = out + N_TOK*DM + 1;

    void* p;
    cudaGetSymbolAddress(&p, g_scores); float* scores = (float*)p;
    cudaGetSymbolAddress(&p, g_freq);   float* freqp = (float*)p;
    cudaGetSymbolAddress(&p, g_cnt);    int*   cntp = (int*)p;
    cudaGetSymbolAddress(&p, g_pre0);   float* pre0 = (float*)p;
    cudaGetSymbolAddress(&p, g_post0);  float* post0 = (float*)p;
    cudaGetSymbolAddress(&p, g_xh);     bf16* xh = (bf16*)p;
    cudaGetSymbolAddress(&p, g_xl);     bf16* xl = (bf16*)p;
    cudaGetSymbolAddress(&p, g_h1h);    bf16* h1h = (bf16*)p;
    cudaGetSymbolAddress(&p, g_h1l);    bf16* h1l = (bf16*)p;
    cudaGetSymbolAddress(&p, g_h2h);    bf16* h2h = (bf16*)p;
    cudaGetSymbolAddress(&p, g_h2l);    bf16* h2l = (bf16*)p;
    cudaGetSymbolAddress(&p, g_xpreh);  bf16* xpreh = (bf16*)p;
    cudaGetSymbolAddress(&p, g_xprel);  bf16* xprel = (bf16*)p;
    cudaGetSymbolAddress(&p, g_xmidh);  bf16* xmidh = (bf16*)p;
    cudaGetSymbolAddress(&p, g_xmidl);  bf16* xmidl = (bf16*)p;
    cudaGetSymbolAddress(&p, g_xmlph);  bf16* xmlph = (bf16*)p;
    cudaGetSymbolAddress(&p, g_xmlpl);  bf16* xmlpl = (bf16*)p;
    cudaGetSymbolAddress(&p, g_rw1h);   bf16* rw1h = (bf16*)p;
    cudaGetSymbolAddress(&p, g_rw1l);   bf16* rw1l = (bf16*)p;
    cudaGetSymbolAddress(&p, g_rw2h);   bf16* rw2h = (bf16*)p;
    cudaGetSymbolAddress(&p, g_rw2l);   bf16* rw2l = (bf16*)p;
    cudaGetSymbolAddress(&p, g_rw3h);   bf16* rw3h = (bf16*)p;
    cudaGetSymbolAddress(&p, g_rw3l);   bf16* rw3l = (bf16*)p;
    cudaGetSymbolAddress(&p, g_pwh);    bf16* pwh = (bf16*)p;
    cudaGetSymbolAddress(&p, g_pwl);    bf16* pwl = (bf16*)p;
    cudaGetSymbolAddress(&p, g_m1h);    bf16* m1h = (bf16*)p;
    cudaGetSymbolAddress(&p, g_m1l);    bf16* m1l = (bf16*)p;
    cudaGetSymbolAddress(&p, g_m2h);    bf16* m2h = (bf16*)p;
    cudaGetSymbolAddress(&p, g_m2l);    bf16* m2l = (bf16*)p;
    cudaGetSymbolAddress(&p, g_qwh);    bf16* qwh = (bf16*)p;
    cudaGetSymbolAddress(&p, g_qwl);    bf16* qwl = (bf16*)p;

    cudaFuncSetAttribute(gemm_t<0>, cudaFuncAttributeMaxDynamicSharedMemorySize, SMEM_GEMM_BYTES);
    cudaFuncSetAttribute(gemm_t<1>, cudaFuncAttributeMaxDynamicSharedMemorySize, SMEM_GEMM_BYTES);

    // router weight convert + split x + router chain
    convt<<<dim3(256/32, 256/32, 1), 256>>>(rw1, rw1h, rw1l, 256, 256, 0LL, 0LL, 0);
    convt<<<dim3(128/32, 256/32, 1), 256>>>(rw2, rw2h, rw2l, 256, 128, 0LL, 0LL, 0);
    convt<<<dim3(PWY/32, 128/32, 1), 256>>>(rw3, rw3h, rw3l, 128, PWY, 0LL, 0LL, 0);
    split_x<<<N_TOK*DM/(256*8), 256>>>(x);

    gemm_t<0><<<dim3(2, N_TOK/128, 1), 256, SMEM_GEMM_BYTES>>>(
        xh, xl, DM, rw1h, rw1l, 256, 0LL, rb1, 0,
        0, h1h, h1l, 256, 256, 0, 0, 1, -1, 0, 1);
    gemm_t<0><<<dim3(1, N_TOK/128, 1), 256, SMEM_GEMM_BYTES>>>(
        h1h, h1l, 256, rw2h, rw2l, 256, 0LL, rb2, 0,
        0, h2h, h2l, 128, 256, 0, 0, 1, -1, 0, 1);
    gemm_t<0><<<dim3(PWY/128, N_TOK/128, 1), 256, SMEM_GEMM_BYTES>>>(
        h2h, h2l, 128, rw3h, rw3l, 128, 0LL, rb3, 0,
        scores, 0, 0, PWY, 128, 0, 0, 0, -1, 0, 0);

    softmax_topk<<<N_TOK, 256>>>(temp, out_pw);

    // memsets + expert weight conversion
    cudaMemsetAsync(freqp, 0, PWY*sizeof(float), 0);
    cudaMemsetAsync(cntp,  0, 3*NE*sizeof(int), 0);
    convt<<<dim3(DM/32, DM/32, NE), 256>>>(pw, pwh, pwl, DM, DM,
        (long long)DM*DM, (long long)DM*DM, 0);
    convt<<<dim3(HMAX/32, DM/32, NE), 256>>>(mw1, m1h, m1l, DM, HMAX,
        (long long)DM*HMAX, (long long)HMAX*DM, 1);
    convt<<<dim3(DM/32, HMAX/32, NE), 256>>>(mw2, m2h, m2l, HMAX, DM,
        (long long)HMAX*DM, (long long)DM*HMAX, 1);
    convt<<<dim3(DM/32, DM/32, NE), 256>>>(qw, qwh, qwl, DM, DM,
        (long long)DM*DM, (long long)DM*DM, 0);

    // GLBL loss
    freq_partial<<<dim3(PWY/256, N_TOK/256), 256>>>();
    glbl_loss_kernel<<<1, 256>>>(out_loss);

    // routing
    build_lists<<<NPAIR/256, 256>>>();

    // pre experts: bf16 gemm -> LN epilogue (writes fp16 split)
    gemm_t<0><<<dim3(DM/128, NPAIR/128, NE), 256, SMEM_GEMM_BYTES>>>(
        xh, xl, DM, pwh, pwl, DM, (long long)DM*DM, pb, DM,
        pre0, 0, 0, DM, DM, 0, 0, 0, 0, 2, 0);
    epil_pre<<<NPAIR/8, 256>>>(pg, pbb);

    // mlp experts: fp16 2-MMA path
    gemm_t<1><<<dim3(HMAX/128, NPAIR/128, NE), 256, SMEM_GEMM_BYTES>>>(
        xpreh, xprel, DM, m1h, m1l, DM, (long long)HMAX*DM, mb1, HMAX,
        0, xmidh, xmidl, HMAX, DM, 0, 1, 3, NE, 0, 2);
    gemm_t<1><<<dim3(DM/128, NPAIR/128, NE), 256, SMEM_GEMM_BYTES>>>(
        xmidh, xmidl, HMAX, m2h, m2l, HMAX, (long long)DM*HMAX, mb2, DM,
        0, xmlph, xmlpl, DM, 0, 1, 0, 0, NE, 0, 1);

    // post experts: bf16 gemm -> warp-per-token LN + weighted sum
    gemm_t<0><<<dim3(DM/128, NPAIR/128, NE), 256, SMEM_GEMM_BYTES>>>(
        xmlph, xmlpl, DM, qwh, qwl, DM, (long long)DM*DM, qb, DM,
        post0, 0, 0, DM, DM, 0, 0, 0, 2*NE, 0, 0);
    epil_post<<<N_TOK/8, 256>>>(qg, qbb, out_y);
}

// round 15
// speedup vs baseline: 1.4975x; 1.0246x over previous
#include <cuda_runtime.h>
#include <cuda_bf16.h>
#include <cuda_fp16.h>
#include <cstdint>
#include <math.h>

#define N_TOK 2048
#define DM 256
#define PWY 4096
#define KSEL 4
#define NE 16
#define HMAX 1280
#define NPAIR (N_TOK*KSEL)

typedef unsigned long long u64;
typedef unsigned int uint32;
typedef __nv_bfloat16 bf16;
typedef __nv_bfloat162 bf162;

#define MMA_BF16(d, a0,a1,a2,a3, b0,b1) \
  asm volatile("mma.sync.aligned.m16n8k16.row.col.f32.bf16.bf16.f32 " \
    "{%0,%1,%2,%3}, {%4,%5,%6,%7}, {%8,%9}, {%0,%1,%2,%3};" \
    : "+f"(d[0]),"+f"(d[1]),"+f"(d[2]),"+f"(d[3]) \
    : "r"(a0),"r"(a1),"r"(a2),"r"(a3),"r"(b0),"r"(b1))

#define MMA_F16(d, a0,a1,a2,a3, b0,b1) \
  asm volatile("mma.sync.aligned.m16n8k16.row.col.f32.f16.f16.f32 " \
    "{%0,%1,%2,%3}, {%4,%5,%6,%7}, {%8,%9}, {%0,%1,%2,%3};" \
    : "+f"(d[0]),"+f"(d[1]),"+f"(d[2]),"+f"(d[3]) \
    : "r"(a0),"r"(a1),"r"(a2),"r"(a3),"r"(b0),"r"(b1))

#define LDSM_X4(r0,r1,r2,r3,addr) \
  asm volatile("ldmatrix.sync.aligned.m8n8.x4.shared.b16 {%0,%1,%2,%3}, [%4];" \
    : "=r"(r0),"=r"(r1),"=r"(r2),"=r"(r3) : "r"(addr))
#define LDSM_X2(r0,r1,addr) \
  asm volatile("ldmatrix.sync.aligned.m8n8.x2.shared.b16 {%0,%1}, [%2];" \
    : "=r"(r0),"=r"(r1) : "r"(addr))

#define CP16(dst, src) \
  asm volatile("cp.async.ca.shared.global [%0], [%1], 16;" :: "r"(dst), "l"(src))
#define CP16_Z(dst, src) \
  asm volatile("cp.async.ca.shared.global [%0], [%1], 16, 0;" :: "r"(dst), "l"(src))
#define CP_COMMIT() asm volatile("cp.async.commit_group;" ::: "memory")
#define CP_WAIT1()  asm volatile("cp.async.wait_group 1;" ::: "memory")
#define CP_WAIT0()  asm volatile("cp.async.wait_group 0;" ::: "memory")

__device__ __forceinline__ uint32 smem_u32(const void* p){
    uint32 a;
    asm("{ .reg .u64 t; cvta.to.shared.u64 t, %1; cvt.u32.u64 %0, t; }" : "=r"(a) : "l"(p));
    return a;
}

// ---------------- device scratch (static, no allocation) ----------------
__device__ float g_scores[N_TOK*PWY];
__device__ float g_freq[PWY];
__device__ int   g_topidx[NPAIR];
__device__ float g_topval[NPAIR];
__device__ int   g_cnt[3*NE];
__device__ int   g_list[3*NE*NPAIR];
__device__ float g_pre0[NPAIR*DM];
__device__ float g_post0[NPAIR*DM];
// split 16-bit activations
__device__ bf16 g_xh[N_TOK*DM],    g_xl[N_TOK*DM];      // bf16 (router)
__device__ bf16 g_xfh[N_TOK*DM],   g_xfl[N_TOK*DM];     // fp16 bits (pre)
__device__ bf16 g_h1h[N_TOK*256],  g_h1l[N_TOK*256];    // bf16
__device__ bf16 g_h2h[N_TOK*128],  g_h2l[N_TOK*128];    // bf16
__device__ bf16 g_xpreh[NPAIR*DM], g_xprel[NPAIR*DM];   // fp16 bits
__device__ bf16 g_xmidh[(size_t)NPAIR*HMAX], g_xmidl[(size_t)NPAIR*HMAX];  // fp16 bits
__device__ bf16 g_xmlph[NPAIR*DM], g_xmlpl[NPAIR*DM];   // fp16 bits
// split 16-bit transposed weights: WT[n][k]
__device__ bf16 g_rw1h[256*256],  g_rw1l[256*256];
__device__ bf16 g_rw2h[128*256],  g_rw2l[128*256];
__device__ bf16 g_rw3h[PWY*128],  g_rw3l[PWY*128];
__device__ bf16 g_pwh[NE*DM*DM],  g_pwl[NE*DM*DM];      // fp16 high only
__device__ bf16 g_m1h[NE*HMAX*DM], g_m1l[NE*HMAX*DM];   // fp16 high only
__device__ bf16 g_m2h[NE*DM*HMAX], g_m2l[NE*DM*HMAX];   // fp16 high only
__device__ bf16 g_qwh[NE*DM*DM],  g_qwl[NE*DM*DM];      // fp16 high only

__device__ __forceinline__ float geluf(float v){
    return 0.5f*v*(1.0f+erff(v*0.70710678118654752f));
}

// ---------------- weight convert + transpose (fmt 0: bf16 hi/lo; 1: fp16 high only) --------
__global__ __launch_bounds__(256) void convt(
    const float* __restrict__ W, bf16* __restrict__ Th,
    bf16* __restrict__ Tl, int R, int C,
    long long wstride, long long tstride, int fmt)
{
    int e = blockIdx.z;
    __shared__ float tile[32][33];
    int c0 = blockIdx.x*32, r0 = blockIdx.y*32;
    const float* Win = W + (size_t)e*wstride;
    int tx = threadIdx.x & 31, ty = threadIdx.x >> 5;
    for (int i=0;i<32;i+=8)
        tile[ty+i][tx] = Win[(size_t)(r0+ty+i)*C + c0+tx];
    __syncthreads();
    bf16* oh = Th + (size_t)e*tstride;
    bf16* ol = Tl + (size_t)e*tstride;
    for (int i=0;i<32;i+=8){
        float v = tile[tx][ty+i];
        size_t o = (size_t)(c0+ty+i)*R + r0+tx;
        if (fmt==0){
            bf16 h = __float2bfloat16(v);
            oh[o] = h;
            ol[o] = __float2bfloat16(v - __bfloat162float(h));
        } else {
            ((__half*)oh)[o] = __float2half(v);
        }
    }
}

// ---------------- split x: bf16 pair (router) + fp16 pair (pre) ----------------
__global__ __launch_bounds__(256) void split_x(const float* __restrict__ x)
{
    int idx = (blockIdx.x*256 + threadIdx.x)*8;
    float4 v0 = *(const float4*)&x[idx];
    float4 v1 = *(const float4*)&x[idx+4];
    float v[8] = {v0.x,v0.y,v0.z,v0.w,v1.x,v1.y,v1.z,v1.w};
    bf162* dh = (bf162*)&g_xh[idx];
    bf162* dl = (bf162*)&g_xl[idx];
    __half2* fh = (__half2*)&g_xfh[idx];
    __half2* fl = (__half2*)&g_xfl[idx];
#pragma unroll
    for (int j=0;j<4;j++){
        bf16 h0 = __float2bfloat16(v[2*j]);
        bf16 h1 = __float2bfloat16(v[2*j+1]);
        bf16 l0 = __float2bfloat16(v[2*j]   - __bfloat162float(h0));
        bf16 l1 = __float2bfloat16(v[2*j+1] - __bfloat162float(h1));
        dh[j] = __halves2bfloat162(h0,h1);
        dl[j] = __halves2bfloat162(l0,l1);
        __half p0 = __float2half(v[2*j]);
        __half p1 = __float2half(v[2*j+1]);
        __half q0 = __float2half(v[2*j]   - __half2float(p0));
        __half q1 = __float2half(v[2*j+1] - __half2float(p1));
        fh[j] = __halves2half2(p0,p1);
        fl[j] = __halves2half2(q0,q1);
    }
}

// ---------------- split 16-bit mma.sync GEMM: 128x128, 8 warps, cp.async 2-buf, ldmatrix ----
// F16=0: bf16, 3 MMAs. F16=1: fp16, 2 MMAs (A split, B high only).
// osplit: 0 = fp32 out, 1 = bf16 hi/lo out, 2 = fp16 hi/lo out.
#define SEG 10240
#define AHo 0
#define ALo SEG
#define BHo (2*SEG)
#define BLo (3*SEG)
#define BUF_E 5120
#define SMEM_GEMM_BYTES (4*SEG*2)

template<int F16>
__global__ __launch_bounds__(256,2) void gemm_t(
    const bf16* __restrict__ Ahg, const bf16* __restrict__ Alg, int lda,
    const bf16* __restrict__ Wth, const bf16* __restrict__ Wtl,
    int Kw, long long wse,
    const float* __restrict__ bias, int bse,
    float* __restrict__ Cf, bf16* __restrict__ Chp, bf16* __restrict__ Clp,
    int ldc, int Kfix, int kvar, int nvar, int act, int listoff, int ashift, int osplit)
{
    extern __shared__ bf16 S[];
    int e = blockIdx.z;
    int hid = DM*(2 + (e>>2));
    int K = kvar ? hid : Kfix;
    int n0 = blockIdx.x*128;
    if (nvar && n0 >= hid) return;
    int m0 = blockIdx.y*128;
    const int* list = 0; int cnt = 0;
    if (listoff >= 0){
        cnt = g_cnt[listoff+e];
        if (m0 >= cnt) return;
        list = g_list + (size_t)(listoff+e)*NPAIR;
    }
    __shared__ int pairs[128];
    int tid = threadIdx.x;
    if (tid < 128)
        pairs[tid] = (listoff>=0) ? ((m0+tid < cnt) ? list[m0+tid] : -1) : (m0+tid);
    __syncthreads();

    int arow = tid >> 1;
    int half = (tid & 1) * 16;
    int prA = pairs[arow];
    bool avalid = (prA>=0);
    const bf16* Ahp = avalid ? (Ahg + (size_t)(prA>>ashift)*lda) : Ahg;
    const bf16* Alp = avalid ? (Alg + (size_t)(prA>>ashift)*lda) : Alg;
    const bf16* Bhp = Wth + (size_t)e*wse + (size_t)(n0+arow)*Kw;
    const bf16* Blp = Wtl + (size_t)e*wse + (size_t)(n0+arow)*Kw;

    uint32 Sb = smem_u32(S);
    uint32 dAh = Sb + 2*(AHo + arow*40 + half);
    uint32 dAl = Sb + 2*(ALo + arow*40 + half);
    uint32 dBh = Sb + 2*(BHo + arow*40 + half);
    uint32 dBl = Sb + 2*(BLo + arow*40 + half);
    const uint32 bufB = BUF_E*2;

    auto issue = [&](int c){
        uint32 bo = (c&1) ? bufB : 0;
#pragma unroll
        for (int j=0;j<2;j++){
            if (avalid){
                CP16(dAh + bo + j*16, Ahp + c*32 + half + j*8);
                CP16(dAl + bo + j*16, Alp + c*32 + half + j*8);
            } else {
                CP16_Z(dAh + bo + j*16, Ahp);
                CP16_Z(dAl + bo + j*16, Alp);
            }
            CP16(dBh + bo + j*16, Bhp + c*32 + half + j*8);
            if (!F16) CP16(dBl + bo + j*16, Blp + c*32 + half + j*8);
        }
    };

    int lane = tid & 31, wid = tid >> 5;
    int wm = wid >> 2, wn = wid & 3;
    int qr = lane >> 2, qc = lane & 3;
    int al_r = lane & 15, al_c = (lane >> 4) * 8;
    int bl_r = lane & 7,  bl_c = ((lane >> 3) & 1) * 8;

    float acc[4][4][4];
#pragma unroll
    for (int i=0;i<4;i++)
#pragma unroll
    for (int j=0;j<4;j++)
#pragma unroll
    for (int q=0;q<4;q++) acc[i][j][q]=0.f;

    int nchunks = K/32;
    issue(0); CP_COMMIT();
    for (int c=0;c<nchunks;c++){
        if (c+1 < nchunks){ issue(c+1); CP_COMMIT(); CP_WAIT1(); }
        else { CP_WAIT0(); }
        __syncthreads();
        int boE = (c&1) ? BUF_E : 0;
#pragma unroll
        for (int k16=0;k16<32;k16+=16){
            uint32 bh[4][2], bl4[4][2];
#pragma unroll
            for (int nf=0;nf<4;nf++){
                int brow = wn*32 + nf*8 + bl_r;
                uint32 abh = Sb + 2*(BHo + boE + brow*40 + k16 + bl_c);
                LDSM_X2(bh[nf][0], bh[nf][1], abh);
                if (!F16){
                    uint32 abl = Sb + 2*(BLo + boE + brow*40 + k16 + bl_c);
                    LDSM_X2(bl4[nf][0], bl4[nf][1], abl);
                }
            }
#pragma unroll
            for (int mf=0;mf<4;mf++){
                int ar = wm*64 + mf*16 + al_r;
                uint32 aah = Sb + 2*(AHo + boE + ar*40 + k16 + al_c);
                uint32 aal = Sb + 2*(ALo + boE + ar*40 + k16 + al_c);
                uint32 ah0,ah1,ah2,ah3, al0,al1,al2,al3;
                LDSM_X4(ah0,ah1,ah2,ah3, aah);
                LDSM_X4(al0,al1,al2,al3, aal);
#pragma unroll
                for (int nf=0;nf<4;nf++){
                    if (F16){
                        MMA_F16(acc[mf][nf], ah0,ah1,ah2,ah3, bh[nf][0],bh[nf][1]);
                        MMA_F16(acc[mf][nf], al0,al1,al2,al3, bh[nf][0],bh[nf][1]);
                    } else {
                        MMA_BF16(acc[mf][nf], ah0,ah1,ah2,ah3, bh[nf][0],bh[nf][1]);
                        MMA_BF16(acc[mf][nf], ah0,ah1,ah2,ah3, bl4[nf][0],bl4[nf][1]);
                        MMA_BF16(acc[mf][nf], al0,al1,al2,al3, bh[nf][0],bh[nf][1]);
                    }
                }
            }
        }
        __syncthreads();
    }

    bool relu_e = (act==3) && (e&1);
#pragma unroll
    for (int mf=0;mf<4;mf++){
        int r0 = wm*64 + mf*16 + qr;
        int r1 = r0 + 8;
        int pr0 = pairs[r0], pr1 = pairs[r1];
#pragma unroll
        for (int nf=0;nf<4;nf++){
            int n = n0 + wn*32 + nf*8 + qc*2;
            float b0 = bias[(size_t)e*bse + n];
            float b1 = bias[(size_t)e*bse + n + 1];
            float v00 = acc[mf][nf][0] + b0, v01 = acc[mf][nf][1] + b1;
            float v10 = acc[mf][nf][2] + b0, v11 = acc[mf][nf][3] + b1;
            if (act==1){
                v00=geluf(v00); v01=geluf(v01); v10=geluf(v10); v11=geluf(v11);
            } else if (act==3){
                if (relu_e){
                    v00=fmaxf(v00,0.f); v01=fmaxf(v01,0.f);
                    v10=fmaxf(v10,0.f); v11=fmaxf(v11,0.f);
                } else {
                    v00=geluf(v00); v01=geluf(v01);
                    v10=geluf(v10); v11=geluf(v11);
                }
            }
            if (osplit==1){
                if (pr0>=0){
                    bf16 h0=__float2bfloat16(v00), h1=__float2bfloat16(v01);
                    bf16 l0=__float2bfloat16(v00-__bfloat162float(h0));
                    bf16 l1=__float2bfloat16(v01-__bfloat162float(h1));
                    *(bf162*)&Chp[(size_t)pr0*ldc + n] = __halves2bfloat162(h0,h1);
                    *(bf162*)&Clp[(size_t)pr0*ldc + n] = __halves2bfloat162(l0,l1);
                }
                if (pr1>=0){
                    bf16 h0=__float2bfloat16(v10), h1=__float2bfloat16(v11);
                    bf16 l0=__float2bfloat16(v10-__bfloat162float(h0));
                    bf16 l1=__float2bfloat16(v11-__bfloat162float(h1));
                    *(bf162*)&Chp[(size_t)pr1*ldc + n] = __halves2bfloat162(h0,h1);
                    *(bf162*)&Clp[(size_t)pr1*ldc + n] = __halves2bfloat162(l0,l1);
                }
            } else if (osplit==2){
                if (pr0>=0){
                    __half h0=__float2half(v00), h1=__float2half(v01);
                    __half l0=__float2half(v00-__half2float(h0));
                    __half l1=__float2half(v01-__half2float(h1));
                    *(__half2*)&Chp[(size_t)pr0*ldc + n] = __halves2half2(h0,h1);
                    *(__half2*)&Clp[(size_t)pr0*ldc + n] = __halves2half2(l0,l1);
                }
                if (pr1>=0){
                    __half h0=__float2half(v10), h1=__float2half(v11);
                    __half l0=__float2half(v10-__half2float(h0));
                    __half l1=__float2half(v11-__half2float(h1));
                    *(__half2*)&Chp[(size_t)pr1*ldc + n] = __halves2half2(h0,h1);
                    *(__half2*)&Clp[(size_t)pr1*ldc + n] = __halves2half2(l0,l1);
                }
            } else {
                if (pr0>=0) *(float2*)&Cf[(size_t)pr0*ldc + n] = make_float2(v00,v01);
                if (pr1>=0) *(float2*)&Cf[(size_t)pr1*ldc + n] = make_float2(v10,v11);
            }
        }
    }
}

// ---------------- pre epilogue: LN + act, writes split fp16 ----------------
__global__ __launch_bounds__(256) void epil_pre(
    const float* __restrict__ pg, const float* __restrict__ pbb)
{
    int i = blockIdx.x*8 + (threadIdx.x>>5);
    int lane = threadIdx.x & 31;
    int e = g_topidx[i] >> 8;
    const float* row = g_pre0 + (size_t)i*DM;
    float y[8];
    float4 v0 = *(const float4*)&row[lane*8];
    float4 v1 = *(const float4*)&row[lane*8+4];
    y[0]=v0.x;y[1]=v0.y;y[2]=v0.z;y[3]=v0.w;y[4]=v1.x;y[5]=v1.y;y[6]=v1.z;y[7]=v1.w;
    float s = y[0]+y[1]+y[2]+y[3]+y[4]+y[5]+y[6]+y[7];
#pragma unroll
    for (int m=16;m>0;m>>=1) s += __shfl_xor_sync(0xffffffffu, s, m, 32);
    float mu = s * (1.0f/DM);
    float ss = 0.f;
#pragma unroll
    for (int j=0;j<8;j++){ float d=y[j]-mu; ss += d*d; }
#pragma unroll
    for (int m=16;m>0;m>>=1) ss += __shfl_xor_sync(0xffffffffu, ss, m, 32);
    float rstd = rsqrtf(ss*(1.0f/DM) + 1e-5f);
    int actm = e % 3;
    __half2* dh = (__half2*)&g_xpreh[(size_t)i*DM + lane*8];
    __half2* dl = (__half2*)&g_xprel[(size_t)i*DM + lane*8];
#pragma unroll
    for (int j=0;j<4;j++){
        float o[2];
#pragma unroll
        for (int q=0;q<2;q++){
            int c = lane*8 + 2*j + q;
            float v = (y[2*j+q]-mu)*rstd*pg[e*DM+c] + pbb[e*DM+c];
            o[q] = (actm==0) ? geluf(v) : (actm==1) ? fmaxf(v,0.f) : tanhf(v);
        }
        __half h0=__float2half(o[0]), h1=__float2half(o[1]);
        __half l0=__float2half(o[0]-__half2float(h0));
        __half l1=__float2half(o[1]-__half2float(h1));
        dh[j] = __halves2half2(h0,h1);
        dl[j] = __halves2half2(l0,l1);
    }
}

// ---------------- post epilogue: warp-per-token, LN + weighted sum, no atomics -------------
__global__ __launch_bounds__(256) void epil_post(
    const float* __restrict__ qg, const float* __restrict__ qbb,
    float* __restrict__ out_y)
{
    int tok = blockIdx.x*8 + (threadIdx.x>>5);
    int lane = threadIdx.x & 31;
    float acc[8] = {0.f,0.f,0.f,0.f,0.f,0.f,0.f,0.f};
#pragma unroll
    for (int slot=0; slot<KSEL; slot++){
        int i = tok*KSEL + slot;
        int e = g_topidx[i] & 15;
        const float* row = g_post0 + (size_t)i*DM;
        float y[8];
        float4 v0 = *(const float4*)&row[lane*8];
        float4 v1 = *(const float4*)&row[lane*8+4];
        y[0]=v0.x;y[1]=v0.y;y[2]=v0.z;y[3]=v0.w;y[4]=v1.x;y[5]=v1.y;y[6]=v1.z;y[7]=v1.w;
        if ((e & 1) == 0){
            float s = y[0]+y[1]+y[2]+y[3]+y[4]+y[5]+y[6]+y[7];
#pragma unroll
            for (int m=16;m>0;m>>=1) s += __shfl_xor_sync(0xffffffffu, s, m, 32);
            float mu = s * (1.0f/DM);
            float ss = 0.f;
#pragma unroll
            for (int j=0;j<8;j++){ float d=y[j]-mu; ss += d*d; }
#pragma unroll
            for (int m=16;m>0;m>>=1) ss += __shfl_xor_sync(0xffffffffu, ss, m, 32);
            float rstd = rsqrtf(ss*(1.0f/DM) + 1e-5f);
#pragma unroll
            for (int j=0;j<8;j++){
                int c = lane*8 + j;
                y[j] = (y[j]-mu)*rstd*qg[e*DM+c] + qbb[e*DM+c];
            }
        }
        float w = g_topval[i];
#pragma unroll
        for (int j=0;j<8;j++) acc[j] += y[j]*w;
    }
    float* orow = out_y + (size_t)tok*DM + lane*8;
    *(float4*)&orow[0] = make_float4(acc[0],acc[1],acc[2],acc[3]);
    *(float4*)&orow[4] = make_float4(acc[4],acc[5],acc[6],acc[7]);
}

// ---------------- softmax + topk (validated smem-tree version) ----------------
__global__ __launch_bounds__(256) void softmax_topk(
    const float* __restrict__ temp, float* __restrict__ pwout)
{
    __shared__ float s[PWY];
    __shared__ float rv[256*4];
    __shared__ int   ri[256*4];
    __shared__ float red1[256];
    __shared__ float red2[256];
    __shared__ float pv[KSEL];
    int n = blockIdx.x, tid = threadIdx.x;
    float* srow = g_scores + (size_t)n*PWY;
    for (int i=0;i<4;i++){
        int idx = i*1024 + tid*4;
        *(float4*)&s[idx] = *(const float4*)&srow[idx];
    }
    __syncthreads();
    float invt = 1.0f/temp[0];

    float tv[4] = {-INFINITY,-INFINITY,-INFINITY,-INFINITY};
    int tix[4] = {PWY,PWY,PWY,PWY};
    float lm = -INFINITY;
#pragma unroll
    for (int i=0;i<16;i++){
        int j = tid + i*256;
        float v = s[j];
        lm = fmaxf(lm, v);
        if (v > tv[3] || (v == tv[3] && j < tix[3])){
            tv[3]=v; tix[3]=j;
#pragma unroll
            for (int q=3;q>0;q--){
                if (tv[q] > tv[q-1] || (tv[q]==tv[q-1] && tix[q] < tix[q-1])){
                    float tmv=tv[q]; tv[q]=tv[q-1]; tv[q-1]=tmv;
                    int tmi=tix[q]; tix[q]=tix[q-1]; tix[q-1]=tmi;
                }
            }
        }
    }
    red1[tid]=lm; __syncthreads();
    for (int off=128;off>0;off>>=1){ if(tid<off) red1[tid]=fmaxf(red1[tid],red1[tid+off]); __syncthreads(); }
    float m0 = red1[0]; __syncthreads();

    float f[16]; float ls0=0.f, lst=0.f;
#pragma unroll
    for (int i=0;i<16;i++){
        int j = tid + i*256;
        float d = s[j]-m0;
        float e0 = __expf(d);
        f[i]=e0; ls0+=e0;
        lst += __expf(d*invt);
    }
    red1[tid]=ls0; red2[tid]=lst; __syncthreads();
    for (int off=128;off>0;off>>=1){
        if(tid<off){ red1[tid]+=red1[tid+off]; red2[tid]+=red2[tid+off]; }
        __syncthreads();
    }
    float inv0 = 1.0f/red1[0];
    float invsumt = 1.0f/red2[0];
    __syncthreads();

#pragma unroll
    for (int i=0;i<16;i++) srow[tid + i*256] = f[i]*inv0;

#pragma unroll
    for (int q=0;q<4;q++){ rv[tid*4+q]=tv[q]; ri[tid*4+q]=tix[q]; }
    __syncthreads();
    for (int off=128;off>0;off>>=1){
        if (tid < off){
            float a0[4], b0[4]; int ai[4], bi[4];
#pragma unroll
            for (int q=0;q<4;q++){
                a0[q]=rv[tid*4+q]; ai[q]=ri[tid*4+q];
                b0[q]=rv[(tid+off)*4+q]; bi[q]=ri[(tid+off)*4+q];
            }
            int ia=0, ib=0;
            float ov[4]; int oi[4];
#pragma unroll
            for (int q=0;q<4;q++){
                bool ta = (a0[ia] > b0[ib]) || (a0[ia]==b0[ib] && ai[ia] < bi[ib]);
                if (ta){ ov[q]=a0[ia]; oi[q]=ai[ia]; ia++; }
                else   { ov[q]=b0[ib]; oi[q]=bi[ib]; ib++; }
            }
#pragma unroll
            for (int q=0;q<4;q++){ rv[tid*4+q]=ov[q]; ri[tid*4+q]=oi[q]; }
        }
        __syncthreads();
    }

    if (tid < KSEL){
        int se = ri[tid];
        float p = __expf((s[se]-m0)*invt)*invsumt;
        pv[tid]=p;
        g_topidx[n*KSEL+tid]=se;
        g_topval[n*KSEL+tid]=p;
    }
    __syncthreads();
    float invps = 1.0f/(pv[0]+pv[1]+pv[2]+pv[3] + 1e-8f);
    int s0=ri[0], s1=ri[1], s2=ri[2], s3=ri[3];
    float w0=pv[0]*invps, w1=pv[1]*invps, w2=pv[2]*invps, w3=pv[3]*invps;
    float* prow = pwout + (size_t)n*PWY;
    for (int i=0;i<16;i++){
        int j = tid + i*256;
        float v = 0.f;
        if (j==s0) v=w0; else if (j==s1) v=w1; else if (j==s2) v=w2; else if (j==s3) v=w3;
        prow[j]=v;
    }
}

// ---------------- freq + loss + lists ----------------
__global__ __launch_bounds__(256) void freq_partial()
{
    int p = blockIdx.x*256 + threadIdx.x;
    int nbeg = blockIdx.y*256;
    float acc = 0.f;
    for (int n=nbeg; n<nbeg+256; n++)
        acc += g_scores[(size_t)n*PWY + p];
    atomicAdd(&g_freq[p], acc);
}

__global__ __launch_bounds__(256) void glbl_loss_kernel(float* __restrict__ out)
{
    __shared__ float red[256];
    int tid = threadIdx.x;
    const float invN = 1.0f/(float)N_TOK;
    float lsum = 0.f;
    for (int i=0;i<PWY/256;i++) lsum += g_freq[tid+i*256]*invN;
    red[tid]=lsum; __syncthreads();
    for (int off=128;off>0;off>>=1){ if(tid<off) red[tid]+=red[tid+off]; __syncthreads(); }
    float mean = red[0]/(float)PWY; __syncthreads();
    float lss = 0.f;
    for (int i=0;i<PWY/256;i++){
        float d = g_freq[tid+i*256]*invN - mean;
        lss += d*d;
    }
    red[tid]=lss; __syncthreads();
    for (int off=128;off>0;off>>=1){ if(tid<off) red[tid]+=red[tid+off]; __syncthreads(); }
    if (tid==0) out[0] = (float)PWY * (red[0]/(float)(PWY-1));
}

__global__ __launch_bounds__(256) void build_lists()
{
    int i = blockIdx.x*256 + threadIdx.x;
    if (i >= NPAIR) return;
    int idx = g_topidx[i];
    int pe = idx >> 8, rem = idx & 255;
    int me = rem >> 4, qe = rem & 15;
    int pos;
    pos = atomicAdd(&g_cnt[pe], 1);         g_list[pe*NPAIR + pos] = i;
    pos = atomicAdd(&g_cnt[NE+me], 1);      g_list[(NE+me)*NPAIR + pos] = i;
    pos = atomicAdd(&g_cnt[2*NE+qe], 1);    g_list[(2*NE+qe)*NPAIR + pos] = i;
}

// ---------------- host launch ----------------
extern "C" void kernel_launch(void* const* d_in, const int* in_sizes, int n_in,
                              void* d_out, int out_size)
{
    const float* x   = (const float*)d_in[0];
    const float* rw1 = (const float*)d_in[1];
    const float* rb1 = (const float*)d_in[2];
    const float* rw2 = (const float*)d_in[3];
    const float* rb2 = (const float*)d_in[4];
    const float* rw3 = (const float*)d_in[5];
    const float* rb3 = (const float*)d_in[6];
    const float* temp= (const float*)d_in[7];
    const float* pw  = (const float*)d_in[8];
    const float* pb  = (const float*)d_in[9];
    const float* pg  = (const float*)d_in[10];
    const float* pbb = (const float*)d_in[11];
    const float* mw1 = (const float*)d_in[12];
    const float* mb1 = (const float*)d_in[13];
    const float* mw2 = (const float*)d_in[14];
    const float* mb2 = (const float*)d_in[15];
    const float* qw  = (const float*)d_in[16];
    const float* qb  = (const float*)d_in[17];
    const float* qg  = (const float*)d_in[18];
    const float* qbb = (const float*)d_in[19];

    float* out      = (float*)d_out;
    float* out_y    = out;
    float* out_loss = out + N_TOK*DM;
    float* out_pw   = out + N_TOK*DM + 1;

    void* p;
    cudaGetSymbolAddress(&p, g_scores); float* scores = (float*)p;
    cudaGetSymbolAddress(&p, g_freq);   float* freqp = (float*)p;
    cudaGetSymbolAddress(&p, g_cnt);    int*   cntp = (int*)p;
    cudaGetSymbolAddress(&p, g_pre0);   float* pre0 = (float*)p;
    cudaGetSymbolAddress(&p, g_post0);  float* post0 = (float*)p;
    cudaGetSymbolAddress(&p, g_xh);     bf16* xh = (bf16*)p;
    cudaGetSymbolAddress(&p, g_xl);     bf16* xl = (bf16*)p;
    cudaGetSymbolAddress(&p, g_xfh);    bf16* xfh = (bf16*)p;
    cudaGetSymbolAddress(&p, g_xfl);    bf16* xfl = (bf16*)p;
    cudaGetSymbolAddress(&p, g_h1h);    bf16* h1h = (bf16*)p;
    cudaGetSymbolAddress(&p, g_h1l);    bf16* h1l = (bf16*)p;
    cudaGetSymbolAddress(&p, g_h2h);    bf16* h2h = (bf16*)p;
    cudaGetSymbolAddress(&p, g_h2l);    bf16* h2l = (bf16*)p;
    cudaGetSymbolAddress(&p, g_xpreh);  bf16* xpreh = (bf16*)p;
    cudaGetSymbolAddress(&p, g_xprel);  bf16* xprel = (bf16*)p;
    cudaGetSymbolAddress(&p, g_xmidh);  bf16* xmidh = (bf16*)p;
    cudaGetSymbolAddress(&p, g_xmidl);  bf16* xmidl = (bf16*)p;
    cudaGetSymbolAddress(&p, g_xmlph);  bf16* xmlph = (bf16*)p;
    cudaGetSymbolAddress(&p, g_xmlpl);  bf16* xmlpl = (bf16*)p;
    cudaGetSymbolAddress(&p, g_rw1h);   bf16* rw1h = (bf16*)p;
    cudaGetSymbolAddress(&p, g_rw1l);   bf16* rw1l = (bf16*)p;
    cudaGetSymbolAddress(&p, g_rw2h);   bf16* rw2h = (bf16*)p;
    cudaGetSymbolAddress(&p, g_rw2l);   bf16* rw2l = (bf16*)p;
    cudaGetSymbolAddress(&p, g_rw3h);   bf16* rw3h = (bf16*)p;
    cudaGetSymbolAddress(&p, g_rw3l);   bf16* rw3l = (bf16*)p;
    cudaGetSymbolAddress(&p, g_pwh);    bf16* pwh = (bf16*)p;
    cudaGetSymbolAddress(&p, g_pwl);    bf16* pwl = (bf16*)p;
    cudaGetSymbolAddress(&p, g_m1h);    bf16* m1h = (bf16*)p;
    cudaGetSymbolAddress(&p, g_m1l);    bf16* m1l = (bf16*)p;
    cudaGetSymbolAddress(&p, g_m2h);    bf16* m2h = (bf16*)p;
    cudaGetSymbolAddress(&p, g_m2l);    bf16* m2l = (bf16*)p;
    cudaGetSymbolAddress(&p, g_qwh);    bf16* qwh = (bf16*)p;
    cudaGetSymbolAddress(&p, g_qwl);    bf16* qwl = (bf16*)p;

    cudaFuncSetAttribute(gemm_t<0>, cudaFuncAttributeMaxDynamicSharedMemorySize, SMEM_GEMM_BYTES);
    cudaFuncSetAttribute(gemm_t<1>, cudaFuncAttributeMaxDynamicSharedMemorySize, SMEM_GEMM_BYTES);

    // router weight convert + split x + router chain
    convt<<<dim3(256/32, 256/32, 1), 256>>>(rw1, rw1h, rw1l, 256, 256, 0LL, 0LL, 0);
    convt<<<dim3(128/32, 256/32, 1), 256>>>(rw2, rw2h, rw2l, 256, 128, 0LL, 0LL, 0);
    convt<<<dim3(PWY/32, 128/32, 1), 256>>>(rw3, rw3h, rw3l, 128, PWY, 0LL, 0LL, 0);
    split_x<<<N_TOK*DM/(256*8), 256>>>(x);

    gemm_t<0><<<dim3(2, N_TOK/128, 1), 256, SMEM_GEMM_BYTES>>>(
        xh, xl, DM, rw1h, rw1l, 256, 0LL, rb1, 0,
        0, h1h, h1l, 256, 256, 0, 0, 1, -1, 0, 1);
    gemm_t<0><<<dim3(1, N_TOK/128, 1), 256, SMEM_GEMM_BYTES>>>(
        h1h, h1l, 256, rw2h, rw2l, 256, 0LL, rb2, 0,
        0, h2h, h2l, 128, 256, 0, 0, 1, -1, 0, 1);
    gemm_t<0><<<dim3(PWY/128, N_TOK/128, 1), 256, SMEM_GEMM_BYTES>>>(
        h2h, h2l, 128, rw3h, rw3l, 128, 0LL, rb3, 0,
        scores, 0, 0, PWY, 128, 0, 0, 0, -1, 0, 0);

    softmax_topk<<<N_TOK, 256>>>(temp, out_pw);

    // memsets + expert weight conversion (pw/qw now fp16 high only)
    cudaMemsetAsync(freqp, 0, PWY*sizeof(float), 0);
    cudaMemsetAsync(cntp,  0, 3*NE*sizeof(int), 0);
    convt<<<dim3(DM/32, DM/32, NE), 256>>>(pw, pwh, pwl, DM, DM,
        (long long)DM*DM, (long long)DM*DM, 1);
    convt<<<dim3(HMAX/32, DM/32, NE), 256>>>(mw1, m1h, m1l, DM, HMAX,
        (long long)DM*HMAX, (long long)HMAX*DM, 1);
    convt<<<dim3(DM/32, HMAX/32, NE), 256>>>(mw2, m2h, m2l, HMAX, DM,
        (long long)HMAX*DM, (long long)DM*HMAX, 1);
    convt<<<dim3(DM/32, DM/32, NE), 256>>>(qw, qwh, qwl, DM, DM,
        (long long)DM*DM, (long long)DM*DM, 1);

    // GLBL loss
    freq_partial<<<dim3(PWY/256, N_TOK/256), 256>>>();
    glbl_loss_kernel<<<1, 256>>>(out_loss);

    // routing
    build_lists<<<NPAIR/256, 256>>>();

    // pre experts: fp16 2-MMA gemm -> LN epilogue (writes fp16 split)
    gemm_t<1><<<dim3(DM/128, NPAIR/128, NE), 256, SMEM_GEMM_BYTES>>>(
        xfh, xfl, DM, pwh, pwl, DM, (long long)DM*DM, pb, DM,
        pre0, 0, 0, DM, DM, 0, 0, 0, 0, 2, 0);
    epil_pre<<<NPAIR/8, 256>>>(pg, pbb);

    // mlp experts: fp16 2-MMA
    gemm_t<1><<<dim3(HMAX/128, NPAIR/128, NE), 256, SMEM_GEMM_BYTES>>>(
        xpreh, xprel, DM, m1h, m1l, DM, (long long)HMAX*DM, mb1, HMAX,
        0, xmidh, xmidl, HMAX, DM, 0, 1, 3, NE, 0, 2);
    gemm_t<1><<<dim3(DM/128, NPAIR/128, NE), 256, SMEM_GEMM_BYTES>>>(
        xmidh, xmidl, HMAX, m2h, m2l, HMAX, (long long)DM*HMAX, mb2, DM,
        0, xmlph, xmlpl, DM, 0, 1, 0, 0, NE, 0, 2);

    // post experts: fp16 2-MMA gemm -> warp-per-token LN + weighted sum
    gemm_t<1><<<dim3(DM/128, NPAIR/128, NE), 256, SMEM_GEMM_BYTES>>>(
        xmlph, xmlpl, DM, qwh, qwl, DM, (long long)DM*DM, qb, DM,
        post0, 0, 0, DM, DM, 0, 0, 0, 2*NE, 0, 0);
    epil_post<<<N_TOK/8, 256>>>(qg, qbb, out_y);
}

// round 16
// speedup vs baseline: 1.7033x; 1.1374x over previous
#include <cuda_runtime.h>
#include <cuda_bf16.h>
#include <cuda_fp16.h>
#include <cstdint>
#include <math.h>

#define N_TOK 2048
#define DM 256
#define PWY 4096
#define KSEL 4
#define NE 16
#define HMAX 1280
#define NPAIR (N_TOK*KSEL)

typedef unsigned long long u64;
typedef unsigned int uint32;
typedef __nv_bfloat16 bf16;
typedef __nv_bfloat162 bf162;

#define MMA_BF16(d, a0,a1,a2,a3, b0,b1) \
  asm volatile("mma.sync.aligned.m16n8k16.row.col.f32.bf16.bf16.f32 " \
    "{%0,%1,%2,%3}, {%4,%5,%6,%7}, {%8,%9}, {%0,%1,%2,%3};" \
    : "+f"(d[0]),"+f"(d[1]),"+f"(d[2]),"+f"(d[3]) \
    : "r"(a0),"r"(a1),"r"(a2),"r"(a3),"r"(b0),"r"(b1))

#define MMA_F16(d, a0,a1,a2,a3, b0,b1) \
  asm volatile("mma.sync.aligned.m16n8k16.row.col.f32.f16.f16.f32 " \
    "{%0,%1,%2,%3}, {%4,%5,%6,%7}, {%8,%9}, {%0,%1,%2,%3};" \
    : "+f"(d[0]),"+f"(d[1]),"+f"(d[2]),"+f"(d[3]) \
    : "r"(a0),"r"(a1),"r"(a2),"r"(a3),"r"(b0),"r"(b1))

#define LDSM_X4(r0,r1,r2,r3,addr) \
  asm volatile("ldmatrix.sync.aligned.m8n8.x4.shared.b16 {%0,%1,%2,%3}, [%4];" \
    : "=r"(r0),"=r"(r1),"=r"(r2),"=r"(r3) : "r"(addr))
#define LDSM_X2(r0,r1,addr) \
  asm volatile("ldmatrix.sync.aligned.m8n8.x2.shared.b16 {%0,%1}, [%2];" \
    : "=r"(r0),"=r"(r1) : "r"(addr))

#define CP16(dst, src) \
  asm volatile("cp.async.ca.shared.global [%0], [%1], 16;" :: "r"(dst), "l"(src))
#define CP16_Z(dst, src) \
  asm volatile("cp.async.ca.shared.global [%0], [%1], 16, 0;" :: "r"(dst), "l"(src))
#define CP_COMMIT() asm volatile("cp.async.commit_group;" ::: "memory")
#define CP_WAIT1()  asm volatile("cp.async.wait_group 1;" ::: "memory")
#define CP_WAIT0()  asm volatile("cp.async.wait_group 0;" ::: "memory")

__device__ __forceinline__ uint32 smem_u32(const void* p){
    uint32 a;
    asm("{ .reg .u64 t; cvta.to.shared.u64 t, %1; cvt.u32.u64 %0, t; }" : "=r"(a) : "l"(p));
    return a;
}

// ---------------- device scratch (static, no allocation) ----------------
__device__ float g_scores[N_TOK*PWY];
__device__ float g_freq[PWY];
__device__ int   g_topidx[NPAIR];
__device__ float g_topval[NPAIR];
__device__ int   g_cnt[3*NE];
__device__ int   g_list[3*NE*NPAIR];
__device__ float g_pre0[NPAIR*DM];
__device__ float g_post0[NPAIR*DM];
// split 16-bit activations
__device__ bf16 g_xh[N_TOK*DM],    g_xl[N_TOK*DM];      // bf16 (router)
__device__ bf16 g_xfh[N_TOK*DM],   g_xfl[N_TOK*DM];     // fp16 bits (pre)
__device__ bf16 g_h1h[N_TOK*256],  g_h1l[N_TOK*256];    // bf16
__device__ bf16 g_h2h[N_TOK*128],  g_h2l[N_TOK*128];    // bf16
__device__ bf16 g_xpreh[NPAIR*DM], g_xprel[NPAIR*DM];   // fp16 (high only used)
__device__ bf16 g_xmidh[(size_t)NPAIR*HMAX], g_xmidl[(size_t)NPAIR*HMAX];  // fp16 (high only used)
__device__ bf16 g_xmlph[NPAIR*DM], g_xmlpl[NPAIR*DM];   // fp16 split
// split 16-bit transposed weights: WT[n][k]
__device__ bf16 g_rw1h[256*256],  g_rw1l[256*256];
__device__ bf16 g_rw2h[128*256],  g_rw2l[128*256];
__device__ bf16 g_rw3h[PWY*128],  g_rw3l[PWY*128];
__device__ bf16 g_pwh[NE*DM*DM],  g_pwl[NE*DM*DM];      // fp16 high only
__device__ bf16 g_m1h[NE*HMAX*DM], g_m1l[NE*HMAX*DM];   // fp16 high only
__device__ bf16 g_m2h[NE*DM*HMAX], g_m2l[NE*DM*HMAX];   // fp16 high only
__device__ bf16 g_qwh[NE*DM*DM],  g_qwl[NE*DM*DM];      // fp16 high only

__device__ __forceinline__ float geluf(float v){
    return 0.5f*v*(1.0f+erff(v*0.70710678118654752f));
}

// ---------------- weight convert + transpose (fmt 0: bf16 hi/lo; 1: fp16 high only) --------
__global__ __launch_bounds__(256) void convt(
    const float* __restrict__ W, bf16* __restrict__ Th,
    bf16* __restrict__ Tl, int R, int C,
    long long wstride, long long tstride, int fmt)
{
    int e = blockIdx.z;
    __shared__ float tile[32][33];
    int c0 = blockIdx.x*32, r0 = blockIdx.y*32;
    const float* Win = W + (size_t)e*wstride;
    int tx = threadIdx.x & 31, ty = threadIdx.x >> 5;
    for (int i=0;i<32;i+=8)
        tile[ty+i][tx] = Win[(size_t)(r0+ty+i)*C + c0+tx];
    __syncthreads();
    bf16* oh = Th + (size_t)e*tstride;
    bf16* ol = Tl + (size_t)e*tstride;
    for (int i=0;i<32;i+=8){
        float v = tile[tx][ty+i];
        size_t o = (size_t)(c0+ty+i)*R + r0+tx;
        if (fmt==0){
            bf16 h = __float2bfloat16(v);
            oh[o] = h;
            ol[o] = __float2bfloat16(v - __bfloat162float(h));
        } else {
            ((__half*)oh)[o] = __float2half(v);
        }
    }
}

// ---------------- split x: bf16 pair (router) + fp16 pair (pre) ----------------
__global__ __launch_bounds__(256) void split_x(const float* __restrict__ x)
{
    int idx = (blockIdx.x*256 + threadIdx.x)*8;
    float4 v0 = *(const float4*)&x[idx];
    float4 v1 = *(const float4*)&x[idx+4];
    float v[8] = {v0.x,v0.y,v0.z,v0.w,v1.x,v1.y,v1.z,v1.w};
    bf162* dh = (bf162*)&g_xh[idx];
    bf162* dl = (bf162*)&g_xl[idx];
    __half2* fh = (__half2*)&g_xfh[idx];
    __half2* fl = (__half2*)&g_xfl[idx];
#pragma unroll
    for (int j=0;j<4;j++){
        bf16 h0 = __float2bfloat16(v[2*j]);
        bf16 h1 = __float2bfloat16(v[2*j+1]);
        bf16 l0 = __float2bfloat16(v[2*j]   - __bfloat162float(h0));
        bf16 l1 = __float2bfloat16(v[2*j+1] - __bfloat162float(h1));
        dh[j] = __halves2bfloat162(h0,h1);
        dl[j] = __halves2bfloat162(l0,l1);
        __half p0 = __float2half(v[2*j]);
        __half p1 = __float2half(v[2*j+1]);
        __half q0 = __float2half(v[2*j]   - __half2float(p0));
        __half q1 = __float2half(v[2*j+1] - __half2float(p1));
        fh[j] = __halves2half2(p0,p1);
        fl[j] = __halves2half2(q0,q1);
    }
}

// ---------------- split 16-bit mma.sync GEMM: 128x128, 8 warps, cp.async 2-buf, ldmatrix ----
// MODE 0: bf16 3 MMAs. MODE 1: fp16 2 MMAs (A split). MODE 2: fp16 1 MMA (A high only).
// osplit: 0 = fp32 out, 1 = bf16 hi/lo, 2 = fp16 hi/lo, 3 = fp16 high only.
#define SEG 10240
#define AHo 0
#define ALo SEG
#define BHo (2*SEG)
#define BLo (3*SEG)
#define BUF_E 5120
#define SMEM_GEMM_BYTES (4*SEG*2)

template<int MODE>
__global__ __launch_bounds__(256,2) void gemm_t(
    const bf16* __restrict__ Ahg, const bf16* __restrict__ Alg, int lda,
    const bf16* __restrict__ Wth, const bf16* __restrict__ Wtl,
    int Kw, long long wse,
    const float* __restrict__ bias, int bse,
    float* __restrict__ Cf, bf16* __restrict__ Chp, bf16* __restrict__ Clp,
    int ldc, int Kfix, int kvar, int nvar, int act, int listoff, int ashift, int osplit)
{
    extern __shared__ bf16 S[];
    int e = blockIdx.z;
    int hid = DM*(2 + (e>>2));
    int K = kvar ? hid : Kfix;
    int n0 = blockIdx.x*128;
    if (nvar && n0 >= hid) return;
    int m0 = blockIdx.y*128;
    const int* list = 0; int cnt = 0;
    if (listoff >= 0){
        cnt = g_cnt[listoff+e];
        if (m0 >= cnt) return;
        list = g_list + (size_t)(listoff+e)*NPAIR;
    }
    __shared__ int pairs[128];
    int tid = threadIdx.x;
    if (tid < 128)
        pairs[tid] = (listoff>=0) ? ((m0+tid < cnt) ? list[m0+tid] : -1) : (m0+tid);
    __syncthreads();

    int arow = tid >> 1;
    int half = (tid & 1) * 16;
    int prA = pairs[arow];
    bool avalid = (prA>=0);
    const bf16* Ahp = avalid ? (Ahg + (size_t)(prA>>ashift)*lda) : Ahg;
    const bf16* Alp = avalid ? (Alg + (size_t)(prA>>ashift)*lda) : Alg;
    const bf16* Bhp = Wth + (size_t)e*wse + (size_t)(n0+arow)*Kw;
    const bf16* Blp = Wtl + (size_t)e*wse + (size_t)(n0+arow)*Kw;

    uint32 Sb = smem_u32(S);
    uint32 dAh = Sb + 2*(AHo + arow*40 + half);
    uint32 dAl = Sb + 2*(ALo + arow*40 + half);
    uint32 dBh = Sb + 2*(BHo + arow*40 + half);
    uint32 dBl = Sb + 2*(BLo + arow*40 + half);
    const uint32 bufB = BUF_E*2;

    auto issue = [&](int c){
        uint32 bo = (c&1) ? bufB : 0;
#pragma unroll
        for (int j=0;j<2;j++){
            if (avalid){
                CP16(dAh + bo + j*16, Ahp + c*32 + half + j*8);
                if (MODE != 2) CP16(dAl + bo + j*16, Alp + c*32 + half + j*8);
            } else {
                CP16_Z(dAh + bo + j*16, Ahp);
                if (MODE != 2) CP16_Z(dAl + bo + j*16, Alp);
            }
            CP16(dBh + bo + j*16, Bhp + c*32 + half + j*8);
            if (MODE == 0) CP16(dBl + bo + j*16, Blp + c*32 + half + j*8);
        }
    };

    int lane = tid & 31, wid = tid >> 5;
    int wm = wid >> 2, wn = wid & 3;
    int qr = lane >> 2, qc = lane & 3;
    int al_r = lane & 15, al_c = (lane >> 4) * 8;
    int bl_r = lane & 7,  bl_c = ((lane >> 3) & 1) * 8;

    float acc[4][4][4];
#pragma unroll
    for (int i=0;i<4;i++)
#pragma unroll
    for (int j=0;j<4;j++)
#pragma unroll
    for (int q=0;q<4;q++) acc[i][j][q]=0.f;

    int nchunks = K/32;
    issue(0); CP_COMMIT();
    for (int c=0;c<nchunks;c++){
        if (c+1 < nchunks){ issue(c+1); CP_COMMIT(); CP_WAIT1(); }
        else { CP_WAIT0(); }
        __syncthreads();
        int boE = (c&1) ? BUF_E : 0;
#pragma unroll
        for (int k16=0;k16<32;k16+=16){
            uint32 bh[4][2], bl4[4][2];
#pragma unroll
            for (int nf=0;nf<4;nf++){
                int brow = wn*32 + nf*8 + bl_r;
                uint32 abh = Sb + 2*(BHo + boE + brow*40 + k16 + bl_c);
                LDSM_X2(bh[nf][0], bh[nf][1], abh);
                if (MODE == 0){
                    uint32 abl = Sb + 2*(BLo + boE + brow*40 + k16 + bl_c);
                    LDSM_X2(bl4[nf][0], bl4[nf][1], abl);
                }
            }
#pragma unroll
            for (int mf=0;mf<4;mf++){
                int ar = wm*64 + mf*16 + al_r;
                uint32 aah = Sb + 2*(AHo + boE + ar*40 + k16 + al_c);
                uint32 ah0,ah1,ah2,ah3;
                LDSM_X4(ah0,ah1,ah2,ah3, aah);
                uint32 al0=0,al1=0,al2=0,al3=0;
                if (MODE != 2){
                    uint32 aal = Sb + 2*(ALo + boE + ar*40 + k16 + al_c);
                    LDSM_X4(al0,al1,al2,al3, aal);
                }
#pragma unroll
                for (int nf=0;nf<4;nf++){
                    if (MODE == 2){
                        MMA_F16(acc[mf][nf], ah0,ah1,ah2,ah3, bh[nf][0],bh[nf][1]);
                    } else if (MODE == 1){
                        MMA_F16(acc[mf][nf], ah0,ah1,ah2,ah3, bh[nf][0],bh[nf][1]);
                        MMA_F16(acc[mf][nf], al0,al1,al2,al3, bh[nf][0],bh[nf][1]);
                    } else {
                        MMA_BF16(acc[mf][nf], ah0,ah1,ah2,ah3, bh[nf][0],bh[nf][1]);
                        MMA_BF16(acc[mf][nf], ah0,ah1,ah2,ah3, bl4[nf][0],bl4[nf][1]);
                        MMA_BF16(acc[mf][nf], al0,al1,al2,al3, bh[nf][0],bh[nf][1]);
                    }
                }
            }
        }
        __syncthreads();
    }

    bool relu_e = (act==3) && (e&1);
#pragma unroll
    for (int mf=0;mf<4;mf++){
        int r0 = wm*64 + mf*16 + qr;
        int r1 = r0 + 8;
        int pr0 = pairs[r0], pr1 = pairs[r1];
#pragma unroll
        for (int nf=0;nf<4;nf++){
            int n = n0 + wn*32 + nf*8 + qc*2;
            float b0 = bias[(size_t)e*bse + n];
            float b1 = bias[(size_t)e*bse + n + 1];
            float v00 = acc[mf][nf][0] + b0, v01 = acc[mf][nf][1] + b1;
            float v10 = acc[mf][nf][2] + b0, v11 = acc[mf][nf][3] + b1;
            if (act==1){
                v00=geluf(v00); v01=geluf(v01); v10=geluf(v10); v11=geluf(v11);
            } else if (act==3){
                if (relu_e){
                    v00=fmaxf(v00,0.f); v01=fmaxf(v01,0.f);
                    v10=fmaxf(v10,0.f); v11=fmaxf(v11,0.f);
                } else {
                    v00=geluf(v00); v01=geluf(v01);
                    v10=geluf(v10); v11=geluf(v11);
                }
            }
            if (osplit==1){
                if (pr0>=0){
                    bf16 h0=__float2bfloat16(v00), h1=__float2bfloat16(v01);
                    bf16 l0=__float2bfloat16(v00-__bfloat162float(h0));
                    bf16 l1=__float2bfloat16(v01-__bfloat162float(h1));
                    *(bf162*)&Chp[(size_t)pr0*ldc + n] = __halves2bfloat162(h0,h1);
                    *(bf162*)&Clp[(size_t)pr0*ldc + n] = __halves2bfloat162(l0,l1);
                }
                if (pr1>=0){
                    bf16 h0=__float2bfloat16(v10), h1=__float2bfloat16(v11);
                    bf16 l0=__float2bfloat16(v10-__bfloat162float(h0));
                    bf16 l1=__float2bfloat16(v11-__bfloat162float(h1));
                    *(bf162*)&Chp[(size_t)pr1*ldc + n] = __halves2bfloat162(h0,h1);
                    *(bf162*)&Clp[(size_t)pr1*ldc + n] = __halves2bfloat162(l0,l1);
                }
            } else if (osplit==2){
                if (pr0>=0){
                    __half h0=__float2half(v00), h1=__float2half(v01);
                    __half l0=__float2half(v00-__half2float(h0));
                    __half l1=__float2half(v01-__half2float(h1));
                    *(__half2*)&Chp[(size_t)pr0*ldc + n] = __halves2half2(h0,h1);
                    *(__half2*)&Clp[(size_t)pr0*ldc + n] = __halves2half2(l0,l1);
                }
                if (pr1>=0){
                    __half h0=__float2half(v10), h1=__float2half(v11);
                    __half l0=__float2half(v10-__half2float(h0));
                    __half l1=__float2half(v11-__half2float(h1));
                    *(__half2*)&Chp[(size_t)pr1*ldc + n] = __halves2half2(h0,h1);
                    *(__half2*)&Clp[(size_t)pr1*ldc + n] = __halves2half2(l0,l1);
                }
            } else if (osplit==3){
                if (pr0>=0)
                    *(__half2*)&Chp[(size_t)pr0*ldc + n] =
                        __halves2half2(__float2half(v00), __float2half(v01));
                if (pr1>=0)
                    *(__half2*)&Chp[(size_t)pr1*ldc + n] =
                        __halves2half2(__float2half(v10), __float2half(v11));
            } else {
                if (pr0>=0) *(float2*)&Cf[(size_t)pr0*ldc + n] = make_float2(v00,v01);
                if (pr1>=0) *(float2*)&Cf[(size_t)pr1*ldc + n] = make_float2(v10,v11);
            }
        }
    }
}

// ---------------- pre epilogue: LN + act, writes fp16 high only (mlp1 is 1-MMA) ------------
__global__ __launch_bounds__(256) void epil_pre(
    const float* __restrict__ pg, const float* __restrict__ pbb)
{
    int i = blockIdx.x*8 + (threadIdx.x>>5);
    int lane = threadIdx.x & 31;
    int e = g_topidx[i] >> 8;
    const float* row = g_pre0 + (size_t)i*DM;
    float y[8];
    float4 v0 = *(const float4*)&row[lane*8];
    float4 v1 = *(const float4*)&row[lane*8+4];
    y[0]=v0.x;y[1]=v0.y;y[2]=v0.z;y[3]=v0.w;y[4]=v1.x;y[5]=v1.y;y[6]=v1.z;y[7]=v1.w;
    float s = y[0]+y[1]+y[2]+y[3]+y[4]+y[5]+y[6]+y[7];
#pragma unroll
    for (int m=16;m>0;m>>=1) s += __shfl_xor_sync(0xffffffffu, s, m, 32);
    float mu = s * (1.0f/DM);
    float ss = 0.f;
#pragma unroll
    for (int j=0;j<8;j++){ float d=y[j]-mu; ss += d*d; }
#pragma unroll
    for (int m=16;m>0;m>>=1) ss += __shfl_xor_sync(0xffffffffu, ss, m, 32);
    float rstd = rsqrtf(ss*(1.0f/DM) + 1e-5f);
    int actm = e % 3;
    __half2* dh = (__half2*)&g_xpreh[(size_t)i*DM + lane*8];
#pragma unroll
    for (int j=0;j<4;j++){
        float o[2];
#pragma unroll
        for (int q=0;q<2;q++){
            int c = lane*8 + 2*j + q;
            float v = (y[2*j+q]-mu)*rstd*pg[e*DM+c] + pbb[e*DM+c];
            o[q] = (actm==0) ? geluf(v) : (actm==1) ? fmaxf(v,0.f) : tanhf(v);
        }
        dh[j] = __halves2half2(__float2half(o[0]), __float2half(o[1]));
    }
}

// ---------------- post epilogue: warp-per-token, LN + weighted sum, no atomics -------------
__global__ __launch_bounds__(256) void epil_post(
    const float* __restrict__ qg, const float* __restrict__ qbb,
    float* __restrict__ out_y)
{
    int tok = blockIdx.x*8 + (threadIdx.x>>5);
    int lane = threadIdx.x & 31;
    float acc[8] = {0.f,0.f,0.f,0.f,0.f,0.f,0.f,0.f};
#pragma unroll
    for (int slot=0; slot<KSEL; slot++){
        int i = tok*KSEL + slot;
        int e = g_topidx[i] & 15;
        const float* row = g_post0 + (size_t)i*DM;
        float y[8];
        float4 v0 = *(const float4*)&row[lane*8];
        float4 v1 = *(const float4*)&row[lane*8+4];
        y[0]=v0.x;y[1]=v0.y;y[2]=v0.z;y[3]=v0.w;y[4]=v1.x;y[5]=v1.y;y[6]=v1.z;y[7]=v1.w;
        if ((e & 1) == 0){
            float s = y[0]+y[1]+y[2]+y[3]+y[4]+y[5]+y[6]+y[7];
#pragma unroll
            for (int m=16;m>0;m>>=1) s += __shfl_xor_sync(0xffffffffu, s, m, 32);
            float mu = s * (1.0f/DM);
            float ss = 0.f;
#pragma unroll
            for (int j=0;j<8;j++){ float d=y[j]-mu; ss += d*d; }
#pragma unroll
            for (int m=16;m>0;m>>=1) ss += __shfl_xor_sync(0xffffffffu, ss, m, 32);
            float rstd = rsqrtf(ss*(1.0f/DM) + 1e-5f);
#pragma unroll
            for (int j=0;j<8;j++){
                int c = lane*8 + j;
                y[j] = (y[j]-mu)*rstd*qg[e*DM+c] + qbb[e*DM+c];
            }
        }
        float w = g_topval[i];
#pragma unroll
        for (int j=0;j<8;j++) acc[j] += y[j]*w;
    }
    float* orow = out_y + (size_t)tok*DM + lane*8;
    *(float4*)&orow[0] = make_float4(acc[0],acc[1],acc[2],acc[3]);
    *(float4*)&orow[4] = make_float4(acc[4],acc[5],acc[6],acc[7]);
}

// ---------------- softmax + topk (validated smem-tree version) ----------------
__global__ __launch_bounds__(256) void softmax_topk(
    const float* __restrict__ temp, float* __restrict__ pwout)
{
    __shared__ float s[PWY];
    __shared__ float rv[256*4];
    __shared__ int   ri[256*4];
    __shared__ float red1[256];
    __shared__ float red2[256];
    __shared__ float pv[KSEL];
    int n = blockIdx.x, tid = threadIdx.x;
    float* srow = g_scores + (size_t)n*PWY;
    for (int i=0;i<4;i++){
        int idx = i*1024 + tid*4;
        *(float4*)&s[idx] = *(const float4*)&srow[idx];
    }
    __syncthreads();
    float invt = 1.0f/temp[0];

    float tv[4] = {-INFINITY,-INFINITY,-INFINITY,-INFINITY};
    int tix[4] = {PWY,PWY,PWY,PWY};
    float lm = -INFINITY;
#pragma unroll
    for (int i=0;i<16;i++){
        int j = tid + i*256;
        float v = s[j];
        lm = fmaxf(lm, v);
        if (v > tv[3] || (v == tv[3] && j < tix[3])){
            tv[3]=v; tix[3]=j;
#pragma unroll
            for (int q=3;q>0;q--){
                if (tv[q] > tv[q-1] || (tv[q]==tv[q-1] && tix[q] < tix[q-1])){
                    float tmv=tv[q]; tv[q]=tv[q-1]; tv[q-1]=tmv;
                    int tmi=tix[q]; tix[q]=tix[q-1]; tix[q-1]=tmi;
                }
            }
        }
    }
    red1[tid]=lm; __syncthreads();
    for (int off=128;off>0;off>>=1){ if(tid<off) red1[tid]=fmaxf(red1[tid],red1[tid+off]); __syncthreads(); }
    float m0 = red1[0]; __syncthreads();

    float f[16]; float ls0=0.f, lst=0.f;
#pragma unroll
    for (int i=0;i<16;i++){
        int j = tid + i*256;
        float d = s[j]-m0;
        float e0 = __expf(d);
        f[i]=e0; ls0+=e0;
        lst += __expf(d*invt);
    }
    red1[tid]=ls0; red2[tid]=lst; __syncthreads();
    for (int off=128;off>0;off>>=1){
        if(tid<off){ red1[tid]+=red1[tid+off]; red2[tid]+=red2[tid+off]; }
        __syncthreads();
    }
    float inv0 = 1.0f/red1[0];
    float invsumt = 1.0f/red2[0];
    __syncthreads();

#pragma unroll
    for (int i=0;i<16;i++) srow[tid + i*256] = f[i]*inv0;

#pragma unroll
    for (int q=0;q<4;q++){ rv[tid*4+q]=tv[q]; ri[tid*4+q]=tix[q]; }
    __syncthreads();
    for (int off=128;off>0;off>>=1){
        if (tid < off){
            float a0[4], b0[4]; int ai[4], bi[4];
#pragma unroll
            for (int q=0;q<4;q++){
                a0[q]=rv[tid*4+q]; ai[q]=ri[tid*4+q];
                b0[q]=rv[(tid+off)*4+q]; bi[q]=ri[(tid+off)*4+q];
            }
            int ia=0, ib=0;
            float ov[4]; int oi[4];
#pragma unroll
            for (int q=0;q<4;q++){
                bool ta = (a0[ia] > b0[ib]) || (a0[ia]==b0[ib] && ai[ia] < bi[ib]);
                if (ta){ ov[q]=a0[ia]; oi[q]=ai[ia]; ia++; }
                else   { ov[q]=b0[ib]; oi[q]=bi[ib]; ib++; }
            }
#pragma unroll
            for (int q=0;q<4;q++){ rv[tid*4+q]=ov[q]; ri[tid*4+q]=oi[q]; }
        }
        __syncthreads();
    }

    if (tid < KSEL){
        int se = ri[tid];
        float p = __expf((s[se]-m0)*invt)*invsumt;
        pv[tid]=p;
        g_topidx[n*KSEL+tid]=se;
        g_topval[n*KSEL+tid]=p;
    }
    __syncthreads();
    float invps = 1.0f/(pv[0]+pv[1]+pv[2]+pv[3] + 1e-8f);
    int s0=ri[0], s1=ri[1], s2=ri[2], s3=ri[3];
    float w0=pv[0]*invps, w1=pv[1]*invps, w2=pv[2]*invps, w3=pv[3]*invps;
    float* prow = pwout + (size_t)n*PWY;
    for (int i=0;i<16;i++){
        int j = tid + i*256;
        float v = 0.f;
        if (j==s0) v=w0; else if (j==s1) v=w1; else if (j==s2) v=w2; else if (j==s3) v=w3;
        prow[j]=v;
    }
}

// ---------------- freq + loss + lists ----------------
__global__ __launch_bounds__(256) void freq_partial()
{
    int p = blockIdx.x*256 + threadIdx.x;
    int nbeg = blockIdx.y*256;
    float acc = 0.f;
    for (int n=nbeg; n<nbeg+256; n++)
        acc += g_scores[(size_t)n*PWY + p];
    atomicAdd(&g_freq[p], acc);
}

__global__ __launch_bounds__(256) void glbl_loss_kernel(float* __restrict__ out)
{
    __shared__ float red[256];
    int tid = threadIdx.x;
    const float invN = 1.0f/(float)N_TOK;
    float lsum = 0.f;
    for (int i=0;i<PWY/256;i++) lsum += g_freq[tid+i*256]*invN;
    red[tid]=lsum; __syncthreads();
    for (int off=128;off>0;off>>=1){ if(tid<off) red[tid]+=red[tid+off]; __syncthreads(); }
    float mean = red[0]/(float)PWY; __syncthreads();
    float lss = 0.f;
    for (int i=0;i<PWY/256;i++){
        float d = g_freq[tid+i*256]*invN - mean;
        lss += d*d;
    }
    red[tid]=lss; __syncthreads();
    for (int off=128;off>0;off>>=1){ if(tid<off) red[tid]+=red[tid+off]; __syncthreads(); }
    if (tid==0) out[0] = (float)PWY * (red[0]/(float)(PWY-1));
}

__global__ __launch_bounds__(256) void build_lists()
{
    int i = blockIdx.x*256 + threadIdx.x;
    if (i >= NPAIR) return;
    int idx = g_topidx[i];
    int pe = idx >> 8, rem = idx & 255;
    int me = rem >> 4, qe = rem & 15;
    int pos;
    pos = atomicAdd(&g_cnt[pe], 1);         g_list[pe*NPAIR + pos] = i;
    pos = atomicAdd(&g_cnt[NE+me], 1);      g_list[(NE+me)*NPAIR + pos] = i;
    pos = atomicAdd(&g_cnt[2*NE+qe], 1);    g_list[(2*NE+qe)*NPAIR + pos] = i;
}

// ---------------- host launch ----------------
extern "C" void kernel_launch(void* const* d_in, const int* in_sizes, int n_in,
                              void* d_out, int out_size)
{
    const float* x   = (const float*)d_in[0];
    const float* rw1 = (const float*)d_in[1];
    const float* rb1 = (const float*)d_in[2];
    const float* rw2 = (const float*)d_in[3];
    const float* rb2 = (const float*)d_in[4];
    const float* rw3 = (const float*)d_in[5];
    const float* rb3 = (const float*)d_in[6];
    const float* temp= (const float*)d_in[7];
    const float* pw  = (const float*)d_in[8];
    const float* pb  = (const float*)d_in[9];
    const float* pg  = (const float*)d_in[10];
    const float* pbb = (const float*)d_in[11];
    const float* mw1 = (const float*)d_in[12];
    const float* mb1 = (const float*)d_in[13];
    const float* mw2 = (const float*)d_in[14];
    const float* mb2 = (const float*)d_in[15];
    const float* qw  = (const float*)d_in[16];
    const float* qb  = (const float*)d_in[17];
    const float* qg  = (const float*)d_in[18];
    const float* qbb = (const float*)d_in[19];

    float* out      = (float*)d_out;
    float* out_y    = out;
    float* out_loss = out + N_TOK*DM;
    float* out_pw   = out + N_TOK*DM + 1;

    void* p;
    cudaGetSymbolAddress(&p, g_scores); float* scores = (float*)p;
    cudaGetSymbolAddress(&p, g_freq);   float* freqp = (float*)p;
    cudaGetSymbolAddress(&p, g_cnt);    int*   cntp = (int*)p;
    cudaGetSymbolAddress(&p, g_pre0);   float* pre0 = (float*)p;
    cudaGetSymbolAddress(&p, g_post0);  float* post0 = (float*)p;
    cudaGetSymbolAddress(&p, g_xh);     bf16* xh = (bf16*)p;
    cudaGetSymbolAddress(&p, g_xl);     bf16* xl = (bf16*)p;
    cudaGetSymbolAddress(&p, g_xfh);    bf16* xfh = (bf16*)p;
    cudaGetSymbolAddress(&p, g_xfl);    bf16* xfl = (bf16*)p;
    cudaGetSymbolAddress(&p, g_h1h);    bf16* h1h = (bf16*)p;
    cudaGetSymbolAddress(&p, g_h1l);    bf16* h1l = (bf16*)p;
    cudaGetSymbolAddress(&p, g_h2h);    bf16* h2h = (bf16*)p;
    cudaGetSymbolAddress(&p, g_h2l);    bf16* h2l = (bf16*)p;
    cudaGetSymbolAddress(&p, g_xpreh);  bf16* xpreh = (bf16*)p;
    cudaGetSymbolAddress(&p, g_xprel);  bf16* xprel = (bf16*)p;
    cudaGetSymbolAddress(&p, g_xmidh);  bf16* xmidh = (bf16*)p;
    cudaGetSymbolAddress(&p, g_xmidl);  bf16* xmidl = (bf16*)p;
    cudaGetSymbolAddress(&p, g_xmlph);  bf16* xmlph = (bf16*)p;
    cudaGetSymbolAddress(&p, g_xmlpl);  bf16* xmlpl = (bf16*)p;
    cudaGetSymbolAddress(&p, g_rw1h);   bf16* rw1h = (bf16*)p;
    cudaGetSymbolAddress(&p, g_rw1l);   bf16* rw1l = (bf16*)p;
    cudaGetSymbolAddress(&p, g_rw2h);   bf16* rw2h = (bf16*)p;
    cudaGetSymbolAddress(&p, g_rw2l);   bf16* rw2l = (bf16*)p;
    cudaGetSymbolAddress(&p, g_rw3h);   bf16* rw3h = (bf16*)p;
    cudaGetSymbolAddress(&p, g_rw3l);   bf16* rw3l = (bf16*)p;
    cudaGetSymbolAddress(&p, g_pwh);    bf16* pwh = (bf16*)p;
    cudaGetSymbolAddress(&p, g_pwl);    bf16* pwl = (bf16*)p;
    cudaGetSymbolAddress(&p, g_m1h);    bf16* m1h = (bf16*)p;
    cudaGetSymbolAddress(&p, g_m1l);    bf16* m1l = (bf16*)p;
    cudaGetSymbolAddress(&p, g_m2h);    bf16* m2h = (bf16*)p;
    cudaGetSymbolAddress(&p, g_m2l);    bf16* m2l = (bf16*)p;
    cudaGetSymbolAddress(&p, g_qwh);    bf16* qwh = (bf16*)p;
    cudaGetSymbolAddress(&p, g_qwl);    bf16* qwl = (bf16*)p;

    cudaFuncSetAttribute(gemm_t<0>, cudaFuncAttributeMaxDynamicSharedMemorySize, SMEM_GEMM_BYTES);
    cudaFuncSetAttribute(gemm_t<1>, cudaFuncAttributeMaxDynamicSharedMemorySize, SMEM_GEMM_BYTES);
    cudaFuncSetAttribute(gemm_t<2>, cudaFuncAttributeMaxDynamicSharedMemorySize, SMEM_GEMM_BYTES);

    // router weight convert + split x + router chain
    convt<<<dim3(256/32, 256/32, 1), 256>>>(rw1, rw1h, rw1l, 256, 256, 0LL, 0LL, 0);
    convt<<<dim3(128/32, 256/32, 1), 256>>>(rw2, rw2h, rw2l, 256, 128, 0LL, 0LL, 0);
    convt<<<dim3(PWY/32, 128/32, 1), 256>>>(rw3, rw3h, rw3l, 128, PWY, 0LL, 0LL, 0);
    split_x<<<N_TOK*DM/(256*8), 256>>>(x);

    gemm_t<0><<<dim3(2, N_TOK/128, 1), 256, SMEM_GEMM_BYTES>>>(
        xh, xl, DM, rw1h, rw1l, 256, 0LL, rb1, 0,
        0, h1h, h1l, 256, 256, 0, 0, 1, -1, 0, 1);
    gemm_t<0><<<dim3(1, N_TOK/128, 1), 256, SMEM_GEMM_BYTES>>>(
        h1h, h1l, 256, rw2h, rw2l, 256, 0LL, rb2, 0,
        0, h2h, h2l, 128, 256, 0, 0, 1, -1, 0, 1);
    gemm_t<0><<<dim3(PWY/128, N_TOK/128, 1), 256, SMEM_GEMM_BYTES>>>(
        h2h, h2l, 128, rw3h, rw3l, 128, 0LL, rb3, 0,
        scores, 0, 0, PWY, 128, 0, 0, 0, -1, 0, 0);

    softmax_topk<<<N_TOK, 256>>>(temp, out_pw);

    // memsets + expert weight conversion (all fp16 high only)
    cudaMemsetAsync(freqp, 0, PWY*sizeof(float), 0);
    cudaMemsetAsync(cntp,  0, 3*NE*sizeof(int), 0);
    convt<<<dim3(DM/32, DM/32, NE), 256>>>(pw, pwh, pwl, DM, DM,
        (long long)DM*DM, (long long)DM*DM, 1);
    convt<<<dim3(HMAX/32, DM/32, NE), 256>>>(mw1, m1h, m1l, DM, HMAX,
        (long long)DM*HMAX, (long long)HMAX*DM, 1);
    convt<<<dim3(DM/32, HMAX/32, NE), 256>>>(mw2, m2h, m2l, HMAX, DM,
        (long long)HMAX*DM, (long long)DM*HMAX, 1);
    convt<<<dim3(DM/32, DM/32, NE), 256>>>(qw, qwh, qwl, DM, DM,
        (long long)DM*DM, (long long)DM*DM, 1);

    // GLBL loss
    freq_partial<<<dim3(PWY/256, N_TOK/256), 256>>>();
    glbl_loss_kernel<<<1, 256>>>(out_loss);

    // routing
    build_lists<<<NPAIR/256, 256>>>();

    // pre experts: fp16 2-MMA gemm -> LN epilogue (writes fp16 high only)
    gemm_t<1><<<dim3(DM/128, NPAIR/128, NE), 256, SMEM_GEMM_BYTES>>>(
        xfh, xfl, DM, pwh, pwl, DM, (long long)DM*DM, pb, DM,
        pre0, 0, 0, DM, DM, 0, 0, 0, 0, 2, 0);
    epil_pre<<<NPAIR/8, 256>>>(pg, pbb);

    // mlp experts: fp16 1-MMA (A high only)
    gemm_t<2><<<dim3(HMAX/128, NPAIR/128, NE), 256, SMEM_GEMM_BYTES>>>(
        xpreh, xprel, DM, m1h, m1l, DM, (long long)HMAX*DM, mb1, HMAX,
        0, xmidh, xmidl, HMAX, DM, 0, 1, 3, NE, 0, 3);
    gemm_t<2><<<dim3(DM/128, NPAIR/128, NE), 256, SMEM_GEMM_BYTES>>>(
        xmidh, xmidl, HMAX, m2h, m2l, HMAX, (long long)DM*HMAX, mb2, DM,
        0, xmlph, xmlpl, DM, 0, 1, 0, 0, NE, 0, 2);

    // post experts: fp16 2-MMA gemm -> warp-per-token LN + weighted sum
    gemm_t<1><<<dim3(DM/128, NPAIR/128, NE), 256, SMEM_GEMM_BYTES>>>(
        xmlph, xmlpl, DM, qwh, qwl, DM, (long long)DM*DM, qb, DM,
        post0, 0, 0, DM, DM, 0, 0, 0, 2*NE, 0, 0);
    epil_post<<<N_TOK/8, 256>>>(qg, qbb, out_y);
}

// round 17
// speedup vs baseline: 1.7983x; 1.0558x over previous
#include <cuda_runtime.h>
#include <cuda_bf16.h>
#include <cuda_fp16.h>
#include <cstdint>
#include <math.h>

#define N_TOK 2048
#define DM 256
#define PWY 4096
#define KSEL 4
#define NE 16
#define HMAX 1280
#define NPAIR (N_TOK*KSEL)

typedef unsigned long long u64;
typedef unsigned int uint32;
typedef __nv_bfloat16 bf16;
typedef __nv_bfloat162 bf162;

#define MMA_BF16(d, a0,a1,a2,a3, b0,b1) \
  asm volatile("mma.sync.aligned.m16n8k16.row.col.f32.bf16.bf16.f32 " \
    "{%0,%1,%2,%3}, {%4,%5,%6,%7}, {%8,%9}, {%0,%1,%2,%3};" \
    : "+f"(d[0]),"+f"(d[1]),"+f"(d[2]),"+f"(d[3]) \
    : "r"(a0),"r"(a1),"r"(a2),"r"(a3),"r"(b0),"r"(b1))

#define MMA_F16(d, a0,a1,a2,a3, b0,b1) \
  asm volatile("mma.sync.aligned.m16n8k16.row.col.f32.f16.f16.f32 " \
    "{%0,%1,%2,%3}, {%4,%5,%6,%7}, {%8,%9}, {%0,%1,%2,%3};" \
    : "+f"(d[0]),"+f"(d[1]),"+f"(d[2]),"+f"(d[3]) \
    : "r"(a0),"r"(a1),"r"(a2),"r"(a3),"r"(b0),"r"(b1))

#define LDSM_X4(r0,r1,r2,r3,addr) \
  asm volatile("ldmatrix.sync.aligned.m8n8.x4.shared.b16 {%0,%1,%2,%3}, [%4];" \
    : "=r"(r0),"=r"(r1),"=r"(r2),"=r"(r3) : "r"(addr))
#define LDSM_X2(r0,r1,addr) \
  asm volatile("ldmatrix.sync.aligned.m8n8.x2.shared.b16 {%0,%1}, [%2];" \
    : "=r"(r0),"=r"(r1) : "r"(addr))

#define CP16(dst, src) \
  asm volatile("cp.async.ca.shared.global [%0], [%1], 16;" :: "r"(dst), "l"(src))
#define CP16_Z(dst, src) \
  asm volatile("cp.async.ca.shared.global [%0], [%1], 16, 0;" :: "r"(dst), "l"(src))
#define CP_COMMIT() asm volatile("cp.async.commit_group;" ::: "memory")
#define CP_WAIT1()  asm volatile("cp.async.wait_group 1;" ::: "memory")
#define CP_WAIT0()  asm volatile("cp.async.wait_group 0;" ::: "memory")

__device__ __forceinline__ uint32 smem_u32(const void* p){
    uint32 a;
    asm("{ .reg .u64 t; cvta.to.shared.u64 t, %1; cvt.u32.u64 %0, t; }" : "=r"(a) : "l"(p));
    return a;
}

// ---------------- device scratch (static, no allocation) ----------------
__device__ float g_scores[N_TOK*PWY];
__device__ float g_freq[PWY];
__device__ int   g_topidx[NPAIR];
__device__ float g_topval[NPAIR];
__device__ int   g_cnt[3*NE];
__device__ int   g_list[3*NE*NPAIR];
__device__ float g_pre0[NPAIR*DM];
__device__ float g_post0[NPAIR*DM];
// split 16-bit activations
__device__ bf16 g_xh[N_TOK*DM],    g_xl[N_TOK*DM];      // bf16 (router)
__device__ bf16 g_xfh[N_TOK*DM],   g_xfl[N_TOK*DM];     // fp16 bits (pre; high only used)
__device__ bf16 g_h1h[N_TOK*256],  g_h1l[N_TOK*256];    // bf16
__device__ bf16 g_h2h[N_TOK*128],  g_h2l[N_TOK*128];    // bf16
__device__ bf16 g_xpreh[NPAIR*DM], g_xprel[NPAIR*DM];   // fp16 (high only used)
__device__ bf16 g_xmidh[(size_t)NPAIR*HMAX], g_xmidl[(size_t)NPAIR*HMAX];  // fp16 (high only)
__device__ bf16 g_xmlph[NPAIR*DM], g_xmlpl[NPAIR*DM];   // fp16 (high only used)
// split 16-bit transposed weights: WT[n][k]
__device__ bf16 g_rw1h[256*256],  g_rw1l[256*256];
__device__ bf16 g_rw2h[128*256],  g_rw2l[128*256];
__device__ bf16 g_rw3h[PWY*128],  g_rw3l[PWY*128];
__device__ bf16 g_pwh[NE*DM*DM],  g_pwl[NE*DM*DM];      // fp16 high only
__device__ bf16 g_m1h[NE*HMAX*DM], g_m1l[NE*HMAX*DM];   // fp16 high only
__device__ bf16 g_m2h[NE*DM*HMAX], g_m2l[NE*DM*HMAX];   // fp16 high only
__device__ bf16 g_qwh[NE*DM*DM],  g_qwl[NE*DM*DM];      // fp16 high only

__device__ __forceinline__ float geluf(float v){
    return 0.5f*v*(1.0f+erff(v*0.70710678118654752f));
}

// ---------------- weight convert + transpose, vectorized paired stores ----------------
// fmt 0: bf16 hi/lo; 1: fp16 high only.
__global__ __launch_bounds__(256) void convt(
    const float* __restrict__ W, bf16* __restrict__ Th,
    bf16* __restrict__ Tl, int R, int C,
    long long wstride, long long tstride, int fmt)
{
    int e = blockIdx.z;
    __shared__ float tile[32][33];
    int c0 = blockIdx.x*32, r0 = blockIdx.y*32;
    const float* Win = W + (size_t)e*wstride;
    int tx = threadIdx.x & 31, ty = threadIdx.x >> 5;
    for (int i=0;i<32;i+=8)
        tile[ty+i][tx] = Win[(size_t)(r0+ty+i)*C + c0+tx];
    __syncthreads();
    bf16* oh = Th + (size_t)e*tstride;
    bf16* ol = Tl + (size_t)e*tstride;
    int rl = (threadIdx.x & 15)*2;   // output-column (r) pair
    int cl = threadIdx.x >> 4;       // output-row (c) 0..15
#pragma unroll
    for (int i=0;i<32;i+=16){
        int c = cl + i;
        float v0 = tile[rl][c], v1 = tile[rl+1][c];
        size_t o = (size_t)(c0+c)*R + r0+rl;
        if (fmt==0){
            bf16 h0=__float2bfloat16(v0), h1=__float2bfloat16(v1);
            *(bf162*)&oh[o] = __halves2bfloat162(h0,h1);
            *(bf162*)&ol[o] = __halves2bfloat162(
                __float2bfloat16(v0-__bfloat162float(h0)),
                __float2bfloat16(v1-__bfloat162float(h1)));
        } else {
            *(__half2*)&oh[o] = __halves2half2(__float2half(v0), __float2half(v1));
        }
    }
}

// ---------------- split x: bf16 pair (router) + fp16 high (pre, 1-MMA) ----------------
__global__ __launch_bounds__(256) void split_x(const float* __restrict__ x)
{
    int idx = (blockIdx.x*256 + threadIdx.x)*8;
    float4 v0 = *(const float4*)&x[idx];
    float4 v1 = *(const float4*)&x[idx+4];
    float v[8] = {v0.x,v0.y,v0.z,v0.w,v1.x,v1.y,v1.z,v1.w};
    bf162* dh = (bf162*)&g_xh[idx];
    bf162* dl = (bf162*)&g_xl[idx];
    __half2* fh = (__half2*)&g_xfh[idx];
#pragma unroll
    for (int j=0;j<4;j++){
        bf16 h0 = __float2bfloat16(v[2*j]);
        bf16 h1 = __float2bfloat16(v[2*j+1]);
        bf16 l0 = __float2bfloat16(v[2*j]   - __bfloat162float(h0));
        bf16 l1 = __float2bfloat16(v[2*j+1] - __bfloat162float(h1));
        dh[j] = __halves2bfloat162(h0,h1);
        dl[j] = __halves2bfloat162(l0,l1);
        fh[j] = __halves2half2(__float2half(v[2*j]), __float2half(v[2*j+1]));
    }
}

// ---------------- split 16-bit mma.sync GEMM: 128x128, 8 warps, cp.async 2-buf, ldmatrix ----
// MODE 0: bf16 3 MMAs. MODE 1: fp16 2 MMAs (A split). MODE 2: fp16 1 MMA (A high only).
// osplit: 0 = fp32 out, 1 = bf16 hi/lo, 2 = fp16 hi/lo, 3 = fp16 high only.
#define SEG 10240
#define AHo 0
#define ALo SEG
#define BHo (2*SEG)
#define BLo (3*SEG)
#define BUF_E 5120
#define SMEM_GEMM_BYTES (4*SEG*2)

template<int MODE>
__global__ __launch_bounds__(256,2) void gemm_t(
    const bf16* __restrict__ Ahg, const bf16* __restrict__ Alg, int lda,
    const bf16* __restrict__ Wth, const bf16* __restrict__ Wtl,
    int Kw, long long wse,
    const float* __restrict__ bias, int bse,
    float* __restrict__ Cf, bf16* __restrict__ Chp, bf16* __restrict__ Clp,
    int ldc, int Kfix, int kvar, int nvar, int act, int listoff, int ashift, int osplit)
{
    extern __shared__ bf16 S[];
    int e = blockIdx.z;
    int hid = DM*(2 + (e>>2));
    int K = kvar ? hid : Kfix;
    int n0 = blockIdx.x*128;
    if (nvar && n0 >= hid) return;
    int m0 = blockIdx.y*128;
    const int* list = 0; int cnt = 0;
    if (listoff >= 0){
        cnt = g_cnt[listoff+e];
        if (m0 >= cnt) return;
        list = g_list + (size_t)(listoff+e)*NPAIR;
    }
    __shared__ int pairs[128];
    int tid = threadIdx.x;
    if (tid < 128)
        pairs[tid] = (listoff>=0) ? ((m0+tid < cnt) ? list[m0+tid] : -1) : (m0+tid);
    __syncthreads();

    int arow = tid >> 1;
    int half = (tid & 1) * 16;
    int prA = pairs[arow];
    bool avalid = (prA>=0);
    const bf16* Ahp = avalid ? (Ahg + (size_t)(prA>>ashift)*lda) : Ahg;
    const bf16* Alp = avalid ? (Alg + (size_t)(prA>>ashift)*lda) : Alg;
    const bf16* Bhp = Wth + (size_t)e*wse + (size_t)(n0+arow)*Kw;
    const bf16* Blp = Wtl + (size_t)e*wse + (size_t)(n0+arow)*Kw;

    uint32 Sb = smem_u32(S);
    uint32 dAh = Sb + 2*(AHo + arow*40 + half);
    uint32 dAl = Sb + 2*(ALo + arow*40 + half);
    uint32 dBh = Sb + 2*(BHo + arow*40 + half);
    uint32 dBl = Sb + 2*(BLo + arow*40 + half);
    const uint32 bufB = BUF_E*2;

    auto issue = [&](int c){
        uint32 bo = (c&1) ? bufB : 0;
#pragma unroll
        for (int j=0;j<2;j++){
            if (avalid){
                CP16(dAh + bo + j*16, Ahp + c*32 + half + j*8);
                if (MODE != 2) CP16(dAl + bo + j*16, Alp + c*32 + half + j*8);
            } else {
                CP16_Z(dAh + bo + j*16, Ahp);
                if (MODE != 2) CP16_Z(dAl + bo + j*16, Alp);
            }
            CP16(dBh + bo + j*16, Bhp + c*32 + half + j*8);
            if (MODE == 0) CP16(dBl + bo + j*16, Blp + c*32 + half + j*8);
        }
    };

    int lane = tid & 31, wid = tid >> 5;
    int wm = wid >> 2, wn = wid & 3;
    int qr = lane >> 2, qc = lane & 3;
    int al_r = lane & 15, al_c = (lane >> 4) * 8;
    int bl_r = lane & 7,  bl_c = ((lane >> 3) & 1) * 8;

    float acc[4][4][4];
#pragma unroll
    for (int i=0;i<4;i++)
#pragma unroll
    for (int j=0;j<4;j++)
#pragma unroll
    for (int q=0;q<4;q++) acc[i][j][q]=0.f;

    int nchunks = K/32;
    issue(0); CP_COMMIT();
    for (int c=0;c<nchunks;c++){
        if (c+1 < nchunks){ issue(c+1); CP_COMMIT(); CP_WAIT1(); }
        else { CP_WAIT0(); }
        __syncthreads();
        int boE = (c&1) ? BUF_E : 0;
#pragma unroll
        for (int k16=0;k16<32;k16+=16){
            uint32 bh[4][2], bl4[4][2];
#pragma unroll
            for (int nf=0;nf<4;nf++){
                int brow = wn*32 + nf*8 + bl_r;
                uint32 abh = Sb + 2*(BHo + boE + brow*40 + k16 + bl_c);
                LDSM_X2(bh[nf][0], bh[nf][1], abh);
                if (MODE == 0){
                    uint32 abl = Sb + 2*(BLo + boE + brow*40 + k16 + bl_c);
                    LDSM_X2(bl4[nf][0], bl4[nf][1], abl);
                }
            }
#pragma unroll
            for (int mf=0;mf<4;mf++){
                int ar = wm*64 + mf*16 + al_r;
                uint32 aah = Sb + 2*(AHo + boE + ar*40 + k16 + al_c);
                uint32 ah0,ah1,ah2,ah3;
                LDSM_X4(ah0,ah1,ah2,ah3, aah);
                uint32 al0=0,al1=0,al2=0,al3=0;
                if (MODE != 2){
                    uint32 aal = Sb + 2*(ALo + boE + ar*40 + k16 + al_c);
                    LDSM_X4(al0,al1,al2,al3, aal);
                }
#pragma unroll
                for (int nf=0;nf<4;nf++){
                    if (MODE == 2){
                        MMA_F16(acc[mf][nf], ah0,ah1,ah2,ah3, bh[nf][0],bh[nf][1]);
                    } else if (MODE == 1){
                        MMA_F16(acc[mf][nf], ah0,ah1,ah2,ah3, bh[nf][0],bh[nf][1]);
                        MMA_F16(acc[mf][nf], al0,al1,al2,al3, bh[nf][0],bh[nf][1]);
                    } else {
                        MMA_BF16(acc[mf][nf], ah0,ah1,ah2,ah3, bh[nf][0],bh[nf][1]);
                        MMA_BF16(acc[mf][nf], ah0,ah1,ah2,ah3, bl4[nf][0],bl4[nf][1]);
                        MMA_BF16(acc[mf][nf], al0,al1,al2,al3, bh[nf][0],bh[nf][1]);
                    }
                }
            }
        }
        __syncthreads();
    }

    bool relu_e = (act==3) && (e&1);
#pragma unroll
    for (int mf=0;mf<4;mf++){
        int r0 = wm*64 + mf*16 + qr;
        int r1 = r0 + 8;
        int pr0 = pairs[r0], pr1 = pairs[r1];
#pragma unroll
        for (int nf=0;nf<4;nf++){
            int n = n0 + wn*32 + nf*8 + qc*2;
            float b0 = bias[(size_t)e*bse + n];
            float b1 = bias[(size_t)e*bse + n + 1];
            float v00 = acc[mf][nf][0] + b0, v01 = acc[mf][nf][1] + b1;
            float v10 = acc[mf][nf][2] + b0, v11 = acc[mf][nf][3] + b1;
            if (act==1){
                v00=geluf(v00); v01=geluf(v01); v10=geluf(v10); v11=geluf(v11);
            } else if (act==3){
                if (relu_e){
                    v00=fmaxf(v00,0.f); v01=fmaxf(v01,0.f);
                    v10=fmaxf(v10,0.f); v11=fmaxf(v11,0.f);
                } else {
                    v00=geluf(v00); v01=geluf(v01);
                    v10=geluf(v10); v11=geluf(v11);
                }
            }
            if (osplit==1){
                if (pr0>=0){
                    bf16 h0=__float2bfloat16(v00), h1=__float2bfloat16(v01);
                    bf16 l0=__float2bfloat16(v00-__bfloat162float(h0));
                    bf16 l1=__float2bfloat16(v01-__bfloat162float(h1));
                    *(bf162*)&Chp[(size_t)pr0*ldc + n] = __halves2bfloat162(h0,h1);
                    *(bf162*)&Clp[(size_t)pr0*ldc + n] = __halves2bfloat162(l0,l1);
                }
                if (pr1>=0){
                    bf16 h0=__float2bfloat16(v10), h1=__float2bfloat16(v11);
                    bf16 l0=__float2bfloat16(v10-__bfloat162float(h0));
                    bf16 l1=__float2bfloat16(v11-__bfloat162float(h1));
                    *(bf162*)&Chp[(size_t)pr1*ldc + n] = __halves2bfloat162(h0,h1);
                    *(bf162*)&Clp[(size_t)pr1*ldc + n] = __halves2bfloat162(l0,l1);
                }
            } else if (osplit==2){
                if (pr0>=0){
                    __half h0=__float2half(v00), h1=__float2half(v01);
                    __half l0=__float2half(v00-__half2float(h0));
                    __half l1=__float2half(v01-__half2float(h1));
                    *(__half2*)&Chp[(size_t)pr0*ldc + n] = __halves2half2(h0,h1);
                    *(__half2*)&Clp[(size_t)pr0*ldc + n] = __halves2half2(l0,l1);
                }
                if (pr1>=0){
                    __half h0=__float2half(v10), h1=__float2half(v11);
                    __half l0=__float2half(v10-__half2float(h0));
                    __half l1=__float2half(v11-__half2float(h1));
                    *(__half2*)&Chp[(size_t)pr1*ldc + n] = __halves2half2(h0,h1);
                    *(__half2*)&Clp[(size_t)pr1*ldc + n] = __halves2half2(l0,l1);
                }
            } else if (osplit==3){
                if (pr0>=0)
                    *(__half2*)&Chp[(size_t)pr0*ldc + n] =
                        __halves2half2(__float2half(v00), __float2half(v01));
                if (pr1>=0)
                    *(__half2*)&Chp[(size_t)pr1*ldc + n] =
                        __halves2half2(__float2half(v10), __float2half(v11));
            } else {
                if (pr0>=0) *(float2*)&Cf[(size_t)pr0*ldc + n] = make_float2(v00,v01);
                if (pr1>=0) *(float2*)&Cf[(size_t)pr1*ldc + n] = make_float2(v10,v11);
            }
        }
    }
}

// ---------------- pre epilogue: LN + act, writes fp16 high only ----------------
__global__ __launch_bounds__(256) void epil_pre(
    const float* __restrict__ pg, const float* __restrict__ pbb)
{
    int i = blockIdx.x*8 + (threadIdx.x>>5);
    int lane = threadIdx.x & 31;
    int e = g_topidx[i] >> 8;
    const float* row = g_pre0 + (size_t)i*DM;
    float y[8];
    float4 v0 = *(const float4*)&row[lane*8];
    float4 v1 = *(const float4*)&row[lane*8+4];
    y[0]=v0.x;y[1]=v0.y;y[2]=v0.z;y[3]=v0.w;y[4]=v1.x;y[5]=v1.y;y[6]=v1.z;y[7]=v1.w;
    float s = y[0]+y[1]+y[2]+y[3]+y[4]+y[5]+y[6]+y[7];
#pragma unroll
    for (int m=16;m>0;m>>=1) s += __shfl_xor_sync(0xffffffffu, s, m, 32);
    float mu = s * (1.0f/DM);
    float ss = 0.f;
#pragma unroll
    for (int j=0;j<8;j++){ float d=y[j]-mu; ss += d*d; }
#pragma unroll
    for (int m=16;m>0;m>>=1) ss += __shfl_xor_sync(0xffffffffu, ss, m, 32);
    float rstd = rsqrtf(ss*(1.0f/DM) + 1e-5f);
    int actm = e % 3;
    __half2* dh = (__half2*)&g_xpreh[(size_t)i*DM + lane*8];
#pragma unroll
    for (int j=0;j<4;j++){
        float o[2];
#pragma unroll
        for (int q=0;q<2;q++){
            int c = lane*8 + 2*j + q;
            float v = (y[2*j+q]-mu)*rstd*pg[e*DM+c] + pbb[e*DM+c];
            o[q] = (actm==0) ? geluf(v) : (actm==1) ? fmaxf(v,0.f) : tanhf(v);
        }
        dh[j] = __halves2half2(__float2half(o[0]), __float2half(o[1]));
    }
}

// ---------------- post epilogue: warp-per-token, LN + weighted sum, no atomics -------------
__global__ __launch_bounds__(256) void epil_post(
    const float* __restrict__ qg, const float* __restrict__ qbb,
    float* __restrict__ out_y)
{
    int tok = blockIdx.x*8 + (threadIdx.x>>5);
    int lane = threadIdx.x & 31;
    float acc[8] = {0.f,0.f,0.f,0.f,0.f,0.f,0.f,0.f};
#pragma unroll
    for (int slot=0; slot<KSEL; slot++){
        int i = tok*KSEL + slot;
        int e = g_topidx[i] & 15;
        const float* row = g_post0 + (size_t)i*DM;
        float y[8];
        float4 v0 = *(const float4*)&row[lane*8];
        float4 v1 = *(const float4*)&row[lane*8+4];
        y[0]=v0.x;y[1]=v0.y;y[2]=v0.z;y[3]=v0.w;y[4]=v1.x;y[5]=v1.y;y[6]=v1.z;y[7]=v1.w;
        if ((e & 1) == 0){
            float s = y[0]+y[1]+y[2]+y[3]+y[4]+y[5]+y[6]+y[7];
#pragma unroll
            for (int m=16;m>0;m>>=1) s += __shfl_xor_sync(0xffffffffu, s, m, 32);
            float mu = s * (1.0f/DM);
            float ss = 0.f;
#pragma unroll
            for (int j=0;j<8;j++){ float d=y[j]-mu; ss += d*d; }
#pragma unroll
            for (int m=16;m>0;m>>=1) ss += __shfl_xor_sync(0xffffffffu, ss, m, 32);
            float rstd = rsqrtf(ss*(1.0f/DM) + 1e-5f);
#pragma unroll
            for (int j=0;j<8;j++){
                int c = lane*8 + j;
                y[j] = (y[j]-mu)*rstd*qg[e*DM+c] + qbb[e*DM+c];
            }
        }
        float w = g_topval[i];
#pragma unroll
        for (int j=0;j<8;j++) acc[j] += y[j]*w;
    }
    float* orow = out_y + (size_t)tok*DM + lane*8;
    *(float4*)&orow[0] = make_float4(acc[0],acc[1],acc[2],acc[3]);
    *(float4*)&orow[4] = make_float4(acc[4],acc[5],acc[6],acc[7]);
}

// ---------------- softmax + topk (validated smem-tree version) ----------------
__global__ __launch_bounds__(256) void softmax_topk(
    const float* __restrict__ temp, float* __restrict__ pwout)
{
    __shared__ float s[PWY];
    __shared__ float rv[256*4];
    __shared__ int   ri[256*4];
    __shared__ float red1[256];
    __shared__ float red2[256];
    __shared__ float pv[KSEL];
    int n = blockIdx.x, tid = threadIdx.x;
    float* srow = g_scores + (size_t)n*PWY;
    for (int i=0;i<4;i++){
        int idx = i*1024 + tid*4;
        *(float4*)&s[idx] = *(const float4*)&srow[idx];
    }
    __syncthreads();
    float invt = 1.0f/temp[0];

    float tv[4] = {-INFINITY,-INFINITY,-INFINITY,-INFINITY};
    int tix[4] = {PWY,PWY,PWY,PWY};
    float lm = -INFINITY;
#pragma unroll
    for (int i=0;i<16;i++){
        int j = tid + i*256;
        float v = s[j];
        lm = fmaxf(lm, v);
        if (v > tv[3] || (v == tv[3] && j < tix[3])){
            tv[3]=v; tix[3]=j;
#pragma unroll
            for (int q=3;q>0;q--){
                if (tv[q] > tv[q-1] || (tv[q]==tv[q-1] && tix[q] < tix[q-1])){
                    float tmv=tv[q]; tv[q]=tv[q-1]; tv[q-1]=tmv;
                    int tmi=tix[q]; tix[q]=tix[q-1]; tix[q-1]=tmi;
                }
            }
        }
    }
    red1[tid]=lm; __syncthreads();
    for (int off=128;off>0;off>>=1){ if(tid<off) red1[tid]=fmaxf(red1[tid],red1[tid+off]); __syncthreads(); }
    float m0 = red1[0]; __syncthreads();

    float f[16]; float ls0=0.f, lst=0.f;
#pragma unroll
    for (int i=0;i<16;i++){
        int j = tid + i*256;
        float d = s[j]-m0;
        float e0 = __expf(d);
        f[i]=e0; ls0+=e0;
        lst += __expf(d*invt);
    }
    red1[tid]=ls0; red2[tid]=lst; __syncthreads();
    for (int off=128;off>0;off>>=1){
        if(tid<off){ red1[tid]+=red1[tid+off]; red2[tid]+=red2[tid+off]; }
        __syncthreads();
    }
    float inv0 = 1.0f/red1[0];
    float invsumt = 1.0f/red2[0];
    __syncthreads();

#pragma unroll
    for (int i=0;i<16;i++) srow[tid + i*256] = f[i]*inv0;

#pragma unroll
    for (int q=0;q<4;q++){ rv[tid*4+q]=tv[q]; ri[tid*4+q]=tix[q]; }
    __syncthreads();
    for (int off=128;off>0;off>>=1){
        if (tid < off){
            float a0[4], b0[4]; int ai[4], bi[4];
#pragma unroll
            for (int q=0;q<4;q++){
                a0[q]=rv[tid*4+q]; ai[q]=ri[tid*4+q];
                b0[q]=rv[(tid+off)*4+q]; bi[q]=ri[(tid+off)*4+q];
            }
            int ia=0, ib=0;
            float ov[4]; int oi[4];
#pragma unroll
            for (int q=0;q<4;q++){
                bool ta = (a0[ia] > b0[ib]) || (a0[ia]==b0[ib] && ai[ia] < bi[ib]);
                if (ta){ ov[q]=a0[ia]; oi[q]=ai[ia]; ia++; }
                else   { ov[q]=b0[ib]; oi[q]=bi[ib]; ib++; }
            }
#pragma unroll
            for (int q=0;q<4;q++){ rv[tid*4+q]=ov[q]; ri[tid*4+q]=oi[q]; }
        }
        __syncthreads();
    }

    if (tid < KSEL){
        int se = ri[tid];
        float p = __expf((s[se]-m0)*invt)*invsumt;
        pv[tid]=p;
        g_topidx[n*KSEL+tid]=se;
        g_topval[n*KSEL+tid]=p;
    }
    __syncthreads();
    float invps = 1.0f/(pv[0]+pv[1]+pv[2]+pv[3] + 1e-8f);
    int s0=ri[0], s1=ri[1], s2=ri[2], s3=ri[3];
    float w0=pv[0]*invps, w1=pv[1]*invps, w2=pv[2]*invps, w3=pv[3]*invps;
    float* prow = pwout + (size_t)n*PWY;
    for (int i=0;i<16;i++){
        int j = tid + i*256;
        float v = 0.f;
        if (j==s0) v=w0; else if (j==s1) v=w1; else if (j==s2) v=w2; else if (j==s3) v=w3;
        prow[j]=v;
    }
}

// ---------------- freq + loss + lists ----------------
__global__ __launch_bounds__(256) void freq_partial()
{
    int p = blockIdx.x*256 + threadIdx.x;
    int nbeg = blockIdx.y*256;
    float acc = 0.f;
    for (int n=nbeg; n<nbeg+256; n++)
        acc += g_scores[(size_t)n*PWY + p];
    atomicAdd(&g_freq[p], acc);
}

__global__ __launch_bounds__(256) void glbl_loss_kernel(float* __restrict__ out)
{
    __shared__ float red[256];
    int tid = threadIdx.x;
    const float invN = 1.0f/(float)N_TOK;
    float lsum = 0.f;
    for (int i=0;i<PWY/256;i++) lsum += g_freq[tid+i*256]*invN;
    red[tid]=lsum; __syncthreads();
    for (int off=128;off>0;off>>=1){ if(tid<off) red[tid]+=red[tid+off]; __syncthreads(); }
    float mean = red[0]/(float)PWY; __syncthreads();
    float lss = 0.f;
    for (int i=0;i<PWY/256;i++){
        float d = g_freq[tid+i*256]*invN - mean;
        lss += d*d;
    }
    red[tid]=lss; __syncthreads();
    for (int off=128;off>0;off>>=1){ if(tid<off) red[tid]+=red[tid+off]; __syncthreads(); }
    if (tid==0) out[0] = (float)PWY * (red[0]/(float)(PWY-1));
}

__global__ __launch_bounds__(256) void build_lists()
{
    int i = blockIdx.x*256 + threadIdx.x;
    if (i >= NPAIR) return;
    int idx = g_topidx[i];
    int pe = idx >> 8, rem = idx & 255;
    int me = rem >> 4, qe = rem & 15;
    int pos;
    pos = atomicAdd(&g_cnt[pe], 1);         g_list[pe*NPAIR + pos] = i;
    pos = atomicAdd(&g_cnt[NE+me], 1);      g_list[(NE+me)*NPAIR + pos] = i;
    pos = atomicAdd(&g_cnt[2*NE+qe], 1);    g_list[(2*NE+qe)*NPAIR + pos] = i;
}

// ---------------- host launch ----------------
extern "C" void kernel_launch(void* const* d_in, const int* in_sizes, int n_in,
                              void* d_out, int out_size)
{
    const float* x   = (const float*)d_in[0];
    const float* rw1 = (const float*)d_in[1];
    const float* rb1 = (const float*)d_in[2];
    const float* rw2 = (const float*)d_in[3];
    const float* rb2 = (const float*)d_in[4];
    const float* rw3 = (const float*)d_in[5];
    const float* rb3 = (const float*)d_in[6];
    const float* temp= (const float*)d_in[7];
    const float* pw  = (const float*)d_in[8];
    const float* pb  = (const float*)d_in[9];
    const float* pg  = (const float*)d_in[10];
    const float* pbb = (const float*)d_in[11];
    const float* mw1 = (const float*)d_in[12];
    const float* mb1 = (const float*)d_in[13];
    const float* mw2 = (const float*)d_in[14];
    const float* mb2 = (const float*)d_in[15];
    const float* qw  = (const float*)d_in[16];
    const float* qb  = (const float*)d_in[17];
    const float* qg  = (const float*)d_in[18];
    const float* qbb = (const float*)d_in[19];

    float* out      = (float*)d_out;
    float* out_y    = out;
    float* out_loss = out + N_TOK*DM;
    float* out_pw   = out + N_TOK*DM + 1;

    void* p;
    cudaGetSymbolAddress(&p, g_scores); float* scores = (float*)p;
    cudaGetSymbolAddress(&p, g_freq);   float* freqp = (float*)p;
    cudaGetSymbolAddress(&p, g_cnt);    int*   cntp = (int*)p;
    cudaGetSymbolAddress(&p, g_pre0);   float* pre0 = (float*)p;
    cudaGetSymbolAddress(&p, g_post0);  float* post0 = (float*)p;
    cudaGetSymbolAddress(&p, g_xh);     bf16* xh = (bf16*)p;
    cudaGetSymbolAddress(&p, g_xl);     bf16* xl = (bf16*)p;
    cudaGetSymbolAddress(&p, g_xfh);    bf16* xfh = (bf16*)p;
    cudaGetSymbolAddress(&p, g_xfl);    bf16* xfl = (bf16*)p;
    cudaGetSymbolAddress(&p, g_h1h);    bf16* h1h = (bf16*)p;
    cudaGetSymbolAddress(&p, g_h1l);    bf16* h1l = (bf16*)p;
    cudaGetSymbolAddress(&p, g_h2h);    bf16* h2h = (bf16*)p;
    cudaGetSymbolAddress(&p, g_h2l);    bf16* h2l = (bf16*)p;
    cudaGetSymbolAddress(&p, g_xpreh);  bf16* xpreh = (bf16*)p;
    cudaGetSymbolAddress(&p, g_xprel);  bf16* xprel = (bf16*)p;
    cudaGetSymbolAddress(&p, g_xmidh);  bf16* xmidh = (bf16*)p;
    cudaGetSymbolAddress(&p, g_xmidl);  bf16* xmidl = (bf16*)p;
    cudaGetSymbolAddress(&p, g_xmlph);  bf16* xmlph = (bf16*)p;
    cudaGetSymbolAddress(&p, g_xmlpl);  bf16* xmlpl = (bf16*)p;
    cudaGetSymbolAddress(&p, g_rw1h);   bf16* rw1h = (bf16*)p;
    cudaGetSymbolAddress(&p, g_rw1l);   bf16* rw1l = (bf16*)p;
    cudaGetSymbolAddress(&p, g_rw2h);   bf16* rw2h = (bf16*)p;
    cudaGetSymbolAddress(&p, g_rw2l);   bf16* rw2l = (bf16*)p;
    cudaGetSymbolAddress(&p, g_rw3h);   bf16* rw3h = (bf16*)p;
    cudaGetSymbolAddress(&p, g_rw3l);   bf16* rw3l = (bf16*)p;
    cudaGetSymbolAddress(&p, g_pwh);    bf16* pwh = (bf16*)p;
    cudaGetSymbolAddress(&p, g_pwl);    bf16* pwl = (bf16*)p;
    cudaGetSymbolAddress(&p, g_m1h);    bf16* m1h = (bf16*)p;
    cudaGetSymbolAddress(&p, g_m1l);    bf16* m1l = (bf16*)p;
    cudaGetSymbolAddress(&p, g_m2h);    bf16* m2h = (bf16*)p;
    cudaGetSymbolAddress(&p, g_m2l);    bf16* m2l = (bf16*)p;
    cudaGetSymbolAddress(&p, g_qwh);    bf16* qwh = (bf16*)p;
    cudaGetSymbolAddress(&p, g_qwl);    bf16* qwl = (bf16*)p;

    cudaFuncSetAttribute(gemm_t<0>, cudaFuncAttributeMaxDynamicSharedMemorySize, SMEM_GEMM_BYTES);
    cudaFuncSetAttribute(gemm_t<1>, cudaFuncAttributeMaxDynamicSharedMemorySize, SMEM_GEMM_BYTES);
    cudaFuncSetAttribute(gemm_t<2>, cudaFuncAttributeMaxDynamicSharedMemorySize, SMEM_GEMM_BYTES);

    // router weight convert + split x + router chain
    convt<<<dim3(256/32, 256/32, 1), 256>>>(rw1, rw1h, rw1l, 256, 256, 0LL, 0LL, 0);
    convt<<<dim3(128/32, 256/32, 1), 256>>>(rw2, rw2h, rw2l, 256, 128, 0LL, 0LL, 0);
    convt<<<dim3(PWY/32, 128/32, 1), 256>>>(rw3, rw3h, rw3l, 128, PWY, 0LL, 0LL, 0);
    split_x<<<N_TOK*DM/(256*8), 256>>>(x);

    gemm_t<0><<<dim3(2, N_TOK/128, 1), 256, SMEM_GEMM_BYTES>>>(
        xh, xl, DM, rw1h, rw1l, 256, 0LL, rb1, 0,
        0, h1h, h1l, 256, 256, 0, 0, 1, -1, 0, 1);
    gemm_t<0><<<dim3(1, N_TOK/128, 1), 256, SMEM_GEMM_BYTES>>>(
        h1h, h1l, 256, rw2h, rw2l, 256, 0LL, rb2, 0,
        0, h2h, h2l, 128, 256, 0, 0, 1, -1, 0, 1);
    gemm_t<0><<<dim3(PWY/128, N_TOK/128, 1), 256, SMEM_GEMM_BYTES>>>(
        h2h, h2l, 128, rw3h, rw3l, 128, 0LL, rb3, 0,
        scores, 0, 0, PWY, 128, 0, 0, 0, -1, 0, 0);

    softmax_topk<<<N_TOK, 256>>>(temp, out_pw);

    // memsets + expert weight conversion (all fp16 high only)
    cudaMemsetAsync(freqp, 0, PWY*sizeof(float), 0);
    cudaMemsetAsync(cntp,  0, 3*NE*sizeof(int), 0);
    convt<<<dim3(DM/32, DM/32, NE), 256>>>(pw, pwh, pwl, DM, DM,
        (long long)DM*DM, (long long)DM*DM, 1);
    convt<<<dim3(HMAX/32, DM/32, NE), 256>>>(mw1, m1h, m1l, DM, HMAX,
        (long long)DM*HMAX, (long long)HMAX*DM, 1);
    convt<<<dim3(DM/32, HMAX/32, NE), 256>>>(mw2, m2h, m2l, HMAX, DM,
        (long long)HMAX*DM, (long long)DM*HMAX, 1);
    convt<<<dim3(DM/32, DM/32, NE), 256>>>(qw, qwh, qwl, DM, DM,
        (long long)DM*DM, (long long)DM*DM, 1);

    // GLBL loss
    freq_partial<<<dim3(PWY/256, N_TOK/256), 256>>>();
    glbl_loss_kernel<<<1, 256>>>(out_loss);

    // routing
    build_lists<<<NPAIR/256, 256>>>();

    // pre experts: fp16 1-MMA gemm -> LN epilogue (writes fp16 high only)
    gemm_t<2><<<dim3(DM/128, NPAIR/128, NE), 256, SMEM_GEMM_BYTES>>>(
        xfh, xfl, DM, pwh, pwl, DM, (long long)DM*DM, pb, DM,
        pre0, 0, 0, DM, DM, 0, 0, 0, 0, 2, 0);
    epil_pre<<<NPAIR/8, 256>>>(pg, pbb);

    // mlp experts: fp16 1-MMA
    gemm_t<2><<<dim3(HMAX/128, NPAIR/128, NE), 256, SMEM_GEMM_BYTES>>>(
        xpreh, xprel, DM, m1h, m1l, DM, (long long)HMAX*DM, mb1, HMAX,
        0, xmidh, xmidl, HMAX, DM, 0, 1, 3, NE, 0, 3);
    gemm_t<2><<<dim3(DM/128, NPAIR/128, NE), 256, SMEM_GEMM_BYTES>>>(
        xmidh, xmidl, HMAX, m2h, m2l, HMAX, (long long)DM*HMAX, mb2, DM,
        0, xmlph, xmlpl, DM, 0, 1, 0, 0, NE, 0, 3);

    // post experts: fp16 1-MMA gemm -> warp-per-token LN + weighted sum
    gemm_t<2><<<dim3(DM/128, NPAIR/128, NE), 256, SMEM_GEMM_BYTES>>>(
        xmlph, xmlpl, DM, qwh, qwl, DM, (long long)DM*DM, qb, DM,
        post0, 0, 0, DM, DM, 0, 0, 0, 2*NE, 0, 0);
    epil_post<<<N_TOK/8, 256>>>(qg, qbb, out_y);
}